// round 4
// baseline (speedup 1.0000x reference)
#include <cuda_runtime.h>
#include <cuda_bf16.h>
#include <cstdint>

// ---------------------------------------------------------------------------
// B=4, L=2048, D=1024, fp32. Outputs: out(8.39M) | res(16.78M) | a2(16.78M).
// GEMMs via legacy mma.sync bf16 (sm_80 path, valid on compute_103) with
// 2-term bf16 split (3 products, product-major ILP ordering).
// ---------------------------------------------------------------------------

#define SZB 8388608ll      // 8192*1024 elements
#define SSB 16777216ll     // 4*2048*2048 elements
#define WSZ 1048576ll      // 1024*1024 elements

__device__ float g_buf[151000064ull];   // 604MB scratch pool

using bf16 = __nv_bfloat16;

__device__ __forceinline__ uint32_t smem_u32(const void* p){
    uint32_t a;
    asm("{ .reg .u64 t; cvta.to.shared.u64 t, %1; cvt.u32.u64 %0, t; }" : "=r"(a) : "l"(p));
    return a;
}
__device__ __forceinline__ uint32_t pack2(float x, float y){
    __nv_bfloat162 t = __floats2bfloat162_rn(x, y);
    return *(uint32_t*)&t;
}
__device__ __forceinline__ void split1(float x, float& h, float& l){
    h = __bfloat162float(__float2bfloat16(x));
    l = x - h;
}

#define LDSM4(R, addr) \
    asm volatile("ldmatrix.sync.aligned.m8n8.x4.shared.b16 {%0,%1,%2,%3}, [%4];" \
        : "=r"((R)[0]), "=r"((R)[1]), "=r"((R)[2]), "=r"((R)[3]) : "r"(addr))

#define MMA16816(d, a, b) \
    asm volatile("mma.sync.aligned.m16n8k16.row.col.f32.bf16.bf16.f32 " \
        "{%0,%1,%2,%3}, {%4,%5,%6,%7}, {%8,%9}, {%0,%1,%2,%3};" \
        : "+f"((d)[0]), "+f"((d)[1]), "+f"((d)[2]), "+f"((d)[3]) \
        : "r"((a)[0]), "r"((a)[1]), "r"((a)[2]), "r"((a)[3]), "r"((b)[0]), "r"((b)[1]))

#define CP_ASYNC16(dst, src) \
    asm volatile("cp.async.cg.shared.global [%0], [%1], 16;" :: "r"(dst), "l"(src))

// ---------------------------------------------------------------------------
// GEMM: C = scale*(A @ B^T) (+bias).  A=(Ah,Al)[M,K] bf16, B=(Bh,Bl)[N,K] bf16.
// Products: AhBh + AhBl + AlBh (product-major for ILP).
// OM bit0: fp32 C; bit1: bf16 split (Ch,Cl); bit2: fp32 res (row stride 2048).
// 128x128 tile, BK=32, 4-stage cp.async, 8 warps (2x4), warp tile 64x32.
// ---------------------------------------------------------------------------
constexpr int TPAD  = 80;                 // padded row stride bytes (32 bf16 = 64B data)
constexpr int TILEB = 128 * TPAD;         // 10240
constexpr int STGB  = 4 * TILEB;          // 40960
constexpr int SMEMB = 4 * STGB;           // 163840

template<int OM, bool BIAS>
__global__ void __launch_bounds__(256, 1) gemm_bf3(
    const bf16* __restrict__ Ah, const bf16* __restrict__ Al,
    const bf16* __restrict__ Bh, const bf16* __restrict__ Bl,
    const float* __restrict__ bias,
    float* __restrict__ Cf, bf16* __restrict__ Ch, bf16* __restrict__ Cl,
    float* __restrict__ Cres, int resOff,
    int M, int N, int K, float scale,
    long long sA, long long sB, long long sC)
{
    extern __shared__ char sm[];
    const uint32_t sb = smem_u32(sm);
    const int tid = threadIdx.x, lane = tid & 31, warp = tid >> 5;
    const int wm = warp >> 2, wn = warp & 3;
    const int bz = blockIdx.z;
    Ah += bz * sA;  Al += bz * sA;
    Bh += bz * sB;  Bl += bz * sB;
    const long long co = (long long)bz * sC;
    const int m0 = blockIdx.y * 128, n0 = blockIdx.x * 128;

    auto load_stage = [&](int slot, int k0){
        const uint32_t s = sb + slot * STGB;
        const bf16* srcs[4] = {Ah, Al, Bh, Bl};
#pragma unroll
        for (int t = 0; t < 4; t++) {
            const bf16* src = srcs[t];
            const int rbase = (t < 2) ? m0 : n0;
#pragma unroll
            for (int i = 0; i < 2; i++) {
                const int c = tid + i * 256;          // 0..511
                const int row = c >> 2, s4 = c & 3;
                const uint32_t dst = s + t * TILEB + row * TPAD + s4 * 16;
                const bf16* g = src + (long long)(rbase + row) * K + k0 + s4 * 8;
                CP_ASYNC16(dst, g);
            }
        }
    };

    const int NS = K / 32;
    for (int p = 0; p < 3; p++) {
        load_stage(p, p * 32);
        asm volatile("cp.async.commit_group;" ::: "memory");
    }

    float acc[4][4][4] = {};

    for (int s = 0; s < NS; s++) {
        asm volatile("cp.async.wait_group 2;" ::: "memory");
        __syncthreads();
        if (s + 3 < NS) load_stage((s + 3) & 3, (s + 3) * 32);
        asm volatile("cp.async.commit_group;" ::: "memory");

        const uint32_t st  = sb + (s & 3) * STGB;
        const uint32_t tAh = st, tAl = st + TILEB, tBh = st + 2*TILEB, tBl = st + 3*TILEB;

#pragma unroll
        for (int ks = 0; ks < 2; ks++) {
            const int kb = ks * 32;   // byte offset of 16-elem k slab
            uint32_t ah[4][4], al[4][4], bh[4][2], bl[4][2];
#pragma unroll
            for (int mi = 0; mi < 4; mi++) {
                const uint32_t r   = wm * 64 + mi * 16 + (lane & 15);
                const uint32_t byo = kb + ((lane >> 4) << 4);
                LDSM4(ah[mi], tAh + r * TPAD + byo);
                LDSM4(al[mi], tAl + r * TPAD + byo);
            }
#pragma unroll
            for (int pi = 0; pi < 2; pi++) {
                const uint32_t r   = wn * 32 + pi * 16 + (lane & 7) + ((lane >> 4) << 3);
                const uint32_t byo = kb + (((lane >> 3) & 1) << 4);
                uint32_t v[4];
                LDSM4(v, tBh + r * TPAD + byo);
                bh[2*pi][0] = v[0]; bh[2*pi][1] = v[1];
                bh[2*pi+1][0] = v[2]; bh[2*pi+1][1] = v[3];
                LDSM4(v, tBl + r * TPAD + byo);
                bl[2*pi][0] = v[0]; bl[2*pi][1] = v[1];
                bl[2*pi+1][0] = v[2]; bl[2*pi+1][1] = v[3];
            }
            // product-major: 16 independent MMAs between accumulator reuses
#pragma unroll
            for (int mi = 0; mi < 4; mi++)
#pragma unroll
                for (int ni = 0; ni < 4; ni++)
                    MMA16816(acc[mi][ni], ah[mi], bh[ni]);
#pragma unroll
            for (int mi = 0; mi < 4; mi++)
#pragma unroll
                for (int ni = 0; ni < 4; ni++)
                    MMA16816(acc[mi][ni], ah[mi], bl[ni]);
#pragma unroll
            for (int mi = 0; mi < 4; mi++)
#pragma unroll
                for (int ni = 0; ni < 4; ni++)
                    MMA16816(acc[mi][ni], al[mi], bh[ni]);
        }
    }

    // epilogue
#pragma unroll
    for (int mi = 0; mi < 4; mi++) {
        const int r0 = m0 + wm * 64 + mi * 16 + (lane >> 2);
#pragma unroll
        for (int ni = 0; ni < 4; ni++) {
            const int col = n0 + wn * 32 + ni * 8 + (lane & 3) * 2;
            float b0 = 0.f, b1 = 0.f;
            if (BIAS) { b0 = __ldg(bias + col); b1 = __ldg(bias + col + 1); }
            const float x0 = acc[mi][ni][0] * scale + b0;
            const float x1 = acc[mi][ni][1] * scale + b1;
            const float x2 = acc[mi][ni][2] * scale + b0;
            const float x3 = acc[mi][ni][3] * scale + b1;
            const long long g0 = co + (long long)r0 * N + col;
            const long long g1 = co + (long long)(r0 + 8) * N + col;
            if (OM & 1) {
                *(float2*)(Cf + g0) = make_float2(x0, x1);
                *(float2*)(Cf + g1) = make_float2(x2, x3);
            }
            if (OM & 2) {
                float h0, l0, h1, l1, h2, l2, h3, l3;
                split1(x0, h0, l0); split1(x1, h1, l1);
                split1(x2, h2, l2); split1(x3, h3, l3);
                *(uint32_t*)(Ch + g0) = pack2(h0, h1);
                *(uint32_t*)(Ch + g1) = pack2(h2, h3);
                *(uint32_t*)(Cl + g0) = pack2(l0, l1);
                *(uint32_t*)(Cl + g1) = pack2(l2, l3);
            }
            if (OM & 4) {     // residual copy, row stride 2048, col offset resOff
                const long long rg0 = (long long)r0 * 2048 + resOff + col;
                const long long rg1 = (long long)(r0 + 8) * 2048 + resOff + col;
                *(float2*)(Cres + rg0) = make_float2(x0, x1);
                *(float2*)(Cres + rg1) = make_float2(x2, x3);
            }
        }
    }
}

// ---------------------------------------------------------------------------
// batched fp32 -> bf16 hi/lo split (3 tensors)
// ---------------------------------------------------------------------------
struct Split3 { const float* x[3]; bf16* h[3]; bf16* l[3]; };

__global__ void __launch_bounds__(256) split3_k(Split3 j)
{
    const int z = blockIdx.y;
    const float* x = j.x[z];
    bf16* h = j.h[z]; bf16* l = j.l[z];
    const long long i = ((long long)blockIdx.x * 256 + threadIdx.x) * 4;
    const float4 v = *(const float4*)(x + i);
    float h0,l0,h1,l1,h2,l2,h3,l3;
    split1(v.x,h0,l0); split1(v.y,h1,l1); split1(v.z,h2,l2); split1(v.w,h3,l3);
    uint2 hp, lp;
    hp.x = pack2(h0,h1); hp.y = pack2(h2,h3);
    lp.x = pack2(l0,l1); lp.y = pack2(l2,l3);
    *(uint2*)(h + i) = hp;
    *(uint2*)(l + i) = lp;
}

// ---------------------------------------------------------------------------
// transpose + split: X[R,C] fp32 -> T[C,R] bf16 hi/lo  (z batches)
// ---------------------------------------------------------------------------
__global__ void __launch_bounds__(256) tspb_k(
    const float* __restrict__ X, bf16* __restrict__ Th, bf16* __restrict__ Tl,
    int R, int C, long long sIn, long long sOut)
{
    __shared__ float t[32][33];
    X  += (long long)blockIdx.z * sIn;
    Th += (long long)blockIdx.z * sOut;
    Tl += (long long)blockIdx.z * sOut;
    const int c0 = blockIdx.x * 32, r0 = blockIdx.y * 32;
    const int tx = threadIdx.x, ty = threadIdx.y;       // (32,8)
#pragma unroll
    for (int i = 0; i < 4; i++)
        t[ty + i * 8][tx] = X[(long long)(r0 + ty + i * 8) * C + c0 + tx];
    __syncthreads();
#pragma unroll
    for (int i = 0; i < 4; i++) {
        const float v = t[tx][ty + i * 8];
        float h, l; split1(v, h, l);
        const long long g = (long long)(c0 + ty + i * 8) * R + r0 + tx;
        Th[g] = __float2bfloat16(h);
        Tl[g] = __float2bfloat16(l);
    }
}

// batched weight transpose+split (8 weights, 1024x1024 each)
struct W8 { const float* w[8]; bf16* th[8]; bf16* tl[8]; };

__global__ void __launch_bounds__(256) tspw_k(W8 j)
{
    __shared__ float t[32][33];
    const int z = blockIdx.z;
    const float* X = j.w[z];
    bf16* Th = j.th[z]; bf16* Tl = j.tl[z];
    const int c0 = blockIdx.x * 32, r0 = blockIdx.y * 32;
    const int tx = threadIdx.x, ty = threadIdx.y;
#pragma unroll
    for (int i = 0; i < 4; i++)
        t[ty + i * 8][tx] = X[(long long)(r0 + ty + i * 8) * 1024 + c0 + tx];
    __syncthreads();
#pragma unroll
    for (int i = 0; i < 4; i++) {
        const float v = t[tx][ty + i * 8];
        float h, l; split1(v, h, l);
        const long long g = (long long)(c0 + ty + i * 8) * 1024 + r0 + tx;
        Th[g] = __float2bfloat16(h);
        Tl[g] = __float2bfloat16(l);
    }
}

// ---------------------------------------------------------------------------
// LayerNorm rows of 1024. SPLIT: bf16 hi/lo out; else fp32 out.
// ---------------------------------------------------------------------------
template<bool SPLIT>
__global__ void __launch_bounds__(256) ln_k(
    const float* __restrict__ x, const float* __restrict__ g,
    const float* __restrict__ b, void* __restrict__ y0, void* __restrict__ y1)
{
    const long long row = blockIdx.x;
    const float4 v = ((const float4*)(x + row * 1024))[threadIdx.x];

    float s  = v.x + v.y + v.z + v.w;
    float s2 = v.x*v.x + v.y*v.y + v.z*v.z + v.w*v.w;
    __shared__ float sh[8], sh2[8];
#pragma unroll
    for (int o = 16; o > 0; o >>= 1) {
        s  += __shfl_xor_sync(0xffffffffu, s, o);
        s2 += __shfl_xor_sync(0xffffffffu, s2, o);
    }
    const int lane = threadIdx.x & 31, warp = threadIdx.x >> 5;
    if (lane == 0) { sh[warp] = s; sh2[warp] = s2; }
    __syncthreads();
    float S = 0.f, S2 = 0.f;
#pragma unroll
    for (int i = 0; i < 8; i++) { S += sh[i]; S2 += sh2[i]; }
    const float mean = S * (1.0f / 1024.0f);
    const float var  = S2 * (1.0f / 1024.0f) - mean * mean;
    const float inv  = rsqrtf(var + 1e-6f);

    const float4 gg = ((const float4*)g)[threadIdx.x];
    const float4 bb = ((const float4*)b)[threadIdx.x];
    float4 o;
    o.x = (v.x - mean) * inv * gg.x + bb.x;
    o.y = (v.y - mean) * inv * gg.y + bb.y;
    o.z = (v.z - mean) * inv * gg.z + bb.z;
    o.w = (v.w - mean) * inv * gg.w + bb.w;
    if (SPLIT) {
        float h0,l0,h1,l1,h2,l2,h3,l3;
        split1(o.x,h0,l0); split1(o.y,h1,l1); split1(o.z,h2,l2); split1(o.w,h3,l3);
        uint2 hp, lp;
        hp.x = pack2(h0,h1); hp.y = pack2(h2,h3);
        lp.x = pack2(l0,l1); lp.y = pack2(l2,l3);
        ((uint2*)((bf16*)y0 + row * 1024))[threadIdx.x] = hp;
        ((uint2*)((bf16*)y1 + row * 1024))[threadIdx.x] = lp;
    } else {
        ((float4*)((float*)y0 + row * 1024))[threadIdx.x] = o;
    }
}

// ---------------------------------------------------------------------------
// row softmax (2048); writes bf16 split P; optionally fp32 back in place.
// ---------------------------------------------------------------------------
template<bool F32OUT>
__global__ void __launch_bounds__(256) softmax_k(
    float* __restrict__ S, bf16* __restrict__ Ph, bf16* __restrict__ Pl)
{
    const long long row = blockIdx.x;
    float* r = S + row * 2048;
    const int base = threadIdx.x * 8;

    float v[8];
    float4 a = *(const float4*)(r + base);
    float4 c = *(const float4*)(r + base + 4);
    v[0]=a.x; v[1]=a.y; v[2]=a.z; v[3]=a.w; v[4]=c.x; v[5]=c.y; v[6]=c.z; v[7]=c.w;

    float mx = v[0];
#pragma unroll
    for (int i = 1; i < 8; i++) mx = fmaxf(mx, v[i]);
    __shared__ float shm[8], shs[8];
#pragma unroll
    for (int o = 16; o > 0; o >>= 1) mx = fmaxf(mx, __shfl_xor_sync(0xffffffffu, mx, o));
    const int lane = threadIdx.x & 31, warp = threadIdx.x >> 5;
    if (lane == 0) shm[warp] = mx;
    __syncthreads();
    float M = shm[0];
#pragma unroll
    for (int i = 1; i < 8; i++) M = fmaxf(M, shm[i]);

    float sum = 0.f;
#pragma unroll
    for (int i = 0; i < 8; i++) { v[i] = __expf(v[i] - M); sum += v[i]; }
#pragma unroll
    for (int o = 16; o > 0; o >>= 1) sum += __shfl_xor_sync(0xffffffffu, sum, o);
    if (lane == 0) shs[warp] = sum;
    __syncthreads();
    float T = 0.f;
#pragma unroll
    for (int i = 0; i < 8; i++) T += shs[i];
    const float inv = 1.0f / T;

    uint4 hp, lp;
    float p0,p1,h0,l0,h1,l1;
    p0 = v[0]*inv; p1 = v[1]*inv; split1(p0,h0,l0); split1(p1,h1,l1);
    hp.x = pack2(h0,h1); lp.x = pack2(l0,l1); a.x = p0; a.y = p1;
    p0 = v[2]*inv; p1 = v[3]*inv; split1(p0,h0,l0); split1(p1,h1,l1);
    hp.y = pack2(h0,h1); lp.y = pack2(l0,l1); a.z = p0; a.w = p1;
    p0 = v[4]*inv; p1 = v[5]*inv; split1(p0,h0,l0); split1(p1,h1,l1);
    hp.z = pack2(h0,h1); lp.z = pack2(l0,l1); c.x = p0; c.y = p1;
    p0 = v[6]*inv; p1 = v[7]*inv; split1(p0,h0,l0); split1(p1,h1,l1);
    hp.w = pack2(h0,h1); lp.w = pack2(l0,l1); c.z = p0; c.w = p1;

    *(uint4*)(Ph + row * 2048 + base) = hp;
    *(uint4*)(Pl + row * 2048 + base) = lp;
    if (F32OUT) {
        *(float4*)(r + base)     = a;
        *(float4*)(r + base + 4) = c;
    }
}

// ---------------------------------------------------------------------------
extern "C" void kernel_launch(void* const* d_in, const int* in_sizes, int n_in,
                              void* d_out, int out_size)
{
    const float* q = (const float*)d_in[0];
    const float* k = (const float*)d_in[1];
    const float* v = (const float*)d_in[2];
    const float* W[8]  = {(const float*)d_in[3],  (const float*)d_in[5],
                          (const float*)d_in[7],  (const float*)d_in[9],
                          (const float*)d_in[11], (const float*)d_in[13],
                          (const float*)d_in[15], (const float*)d_in[17]};
    const float* bW[8] = {(const float*)d_in[4],  (const float*)d_in[6],
                          (const float*)d_in[8],  (const float*)d_in[10],
                          (const float*)d_in[12], (const float*)d_in[14],
                          (const float*)d_in[16], (const float*)d_in[18]};
    const float* gq1 = (const float*)d_in[19]; const float* Bq1 = (const float*)d_in[20];
    const float* gk1 = (const float*)d_in[21]; const float* Bk1 = (const float*)d_in[22];
    const float* gv1 = (const float*)d_in[23]; const float* Bv1 = (const float*)d_in[24];
    const float* gq2 = (const float*)d_in[25]; const float* Bq2 = (const float*)d_in[26];
    const float* gk2 = (const float*)d_in[27]; const float* Bk2 = (const float*)d_in[28];
    const float* gv2 = (const float*)d_in[29]; const float* Bv2 = (const float*)d_in[30];

    float* out = (float*)d_out;
    float* res = out + SZB;
    float* a2  = res + SSB;

    float* buf = nullptr;
    cudaGetSymbolAddress((void**)&buf, g_buf);
    char* P = (char*)buf;
    auto takeB = [&](long long bytes){ char* r = P; P += bytes; return r; };
    bf16* q_h  = (bf16*)takeB(SZB*2); bf16* q_l  = (bf16*)takeB(SZB*2);
    bf16* k_h  = (bf16*)takeB(SZB*2); bf16* k_l  = (bf16*)takeB(SZB*2);
    bf16* v_h  = (bf16*)takeB(SZB*2); bf16* v_l  = (bf16*)takeB(SZB*2);
    float* q1b = (float*)takeB(SZB*4);
    float* kb  = (float*)takeB(SZB*4);
    float* vb  = (float*)takeB(SZB*4);
    float* q2b = (float*)takeB(SZB*4);
    bf16* nq_h = (bf16*)takeB(SZB*2); bf16* nq_l = (bf16*)takeB(SZB*2);
    bf16* nk_h = (bf16*)takeB(SZB*2); bf16* nk_l = (bf16*)takeB(SZB*2);
    float* nv  = (float*)takeB(SZB*4);
    bf16* nvT_h= (bf16*)takeB(SZB*2); bf16* nvT_l= (bf16*)takeB(SZB*2);
    bf16* oa_h = (bf16*)takeB(SZB*2); bf16* oa_l = (bf16*)takeB(SZB*2);
    bf16* o1_h = (bf16*)takeB(SZB*2); bf16* o1_l = (bf16*)takeB(SZB*2);
    float* Sbuf= (float*)takeB(SSB*4);
    bf16* P_h  = (bf16*)takeB(SSB*2); bf16* P_l  = (bf16*)takeB(SSB*2);
    bf16* WTp  = (bf16*)takeB(8ll * 2 * WSZ * 2);
    auto WTh = [&](int i){ return WTp + (long long)i * 2 * WSZ; };
    auto WTl = [&](int i){ return WTp + (long long)i * 2 * WSZ + WSZ; };

    cudaFuncSetAttribute(gemm_bf3<1,true >, cudaFuncAttributeMaxDynamicSharedMemorySize, SMEMB);
    cudaFuncSetAttribute(gemm_bf3<1,false>, cudaFuncAttributeMaxDynamicSharedMemorySize, SMEMB);
    cudaFuncSetAttribute(gemm_bf3<2,true >, cudaFuncAttributeMaxDynamicSharedMemorySize, SMEMB);
    cudaFuncSetAttribute(gemm_bf3<2,false>, cudaFuncAttributeMaxDynamicSharedMemorySize, SMEMB);
    cudaFuncSetAttribute(gemm_bf3<5,true >, cudaFuncAttributeMaxDynamicSharedMemorySize, SMEMB);

    const dim3 tb(32, 8);
    const dim3 gproj(1024/128, 8192/128, 1);     // 8 x 64
    const dim3 gS(2048/128, 2048/128, 4);        // 16 x 16 x 4
    const dim3 gO(1024/128, 2048/128, 4);        // 8 x 16 x 4
    const float it = 1.0f / 32.0f;
    const long long sLD = 2048ll*1024, sLL = 2048ll*2048, sDL = 1024ll*2048;

    // operand prep (batched)
    Split3 s3;
    s3.x[0] = q; s3.h[0] = q_h; s3.l[0] = q_l;
    s3.x[1] = k; s3.h[1] = k_h; s3.l[1] = k_l;
    s3.x[2] = v; s3.h[2] = v_h; s3.l[2] = v_l;
    split3_k<<<dim3(SZB/4/256, 3), 256>>>(s3);
    W8 w8;
    for (int i = 0; i < 8; i++) { w8.w[i] = W[i]; w8.th[i] = WTh(i); w8.tl[i] = WTl(i); }
    tspw_k<<<dim3(32,32,8), tb>>>(w8);

    // ---------------- layer 1 ----------------
    gemm_bf3<5,true><<<gproj,256,SMEMB>>>(q_h,q_l, WTh(0),WTl(0), bW[0], q1b,0,0, res,0,    8192,1024,1024, 1.f, 0,0,0);
    gemm_bf3<1,true><<<gproj,256,SMEMB>>>(k_h,k_l, WTh(1),WTl(1), bW[1], kb, 0,0, 0,0,      8192,1024,1024, 1.f, 0,0,0);
    gemm_bf3<1,true><<<gproj,256,SMEMB>>>(v_h,v_l, WTh(2),WTl(2), bW[2], vb, 0,0, 0,0,      8192,1024,1024, 1.f, 0,0,0);

    ln_k<true ><<<8192,256>>>(q1b, gq1, Bq1, nq_h, nq_l);
    ln_k<true ><<<8192,256>>>(kb,  gk1, Bk1, nk_h, nk_l);
    ln_k<false><<<8192,256>>>(vb,  gv1, Bv1, nv, nullptr);
    tspb_k<<<dim3(32,64,4), tb>>>(nv, nvT_h, nvT_l, 2048, 1024, sLD, sLD);

    gemm_bf3<1,false><<<gS,256,SMEMB>>>(nq_h,nq_l, nk_h,nk_l, 0, Sbuf,0,0, 0,0, 2048,2048,1024, it, sLD,sLD,sLL);
    softmax_k<false><<<8192,256>>>(Sbuf, P_h, P_l);
    gemm_bf3<2,false><<<gO,256,SMEMB>>>(P_h,P_l, nvT_h,nvT_l, 0, 0,oa_h,oa_l, 0,0, 2048,1024,2048, 1.f, sLL,sDL,sLD);
    gemm_bf3<2,true ><<<gproj,256,SMEMB>>>(oa_h,oa_l, WTh(3),WTl(3), bW[3], 0,o1_h,o1_l, 0,0, 8192,1024,1024, 1.f, 0,0,0);

    // ---------------- layer 2 ----------------
    gemm_bf3<5,true><<<gproj,256,SMEMB>>>(o1_h,o1_l, WTh(4),WTl(4), bW[4], q2b,0,0, res,1024, 8192,1024,1024, 1.f, 0,0,0);
    gemm_bf3<1,true><<<gproj,256,SMEMB>>>(k_h,k_l,   WTh(5),WTl(5), bW[5], kb, 0,0, 0,0,      8192,1024,1024, 1.f, 0,0,0);
    gemm_bf3<1,true><<<gproj,256,SMEMB>>>(v_h,v_l,   WTh(6),WTl(6), bW[6], vb, 0,0, 0,0,      8192,1024,1024, 1.f, 0,0,0);

    ln_k<true ><<<8192,256>>>(q2b, gq2, Bq2, nq_h, nq_l);
    ln_k<true ><<<8192,256>>>(kb,  gk2, Bk2, nk_h, nk_l);
    ln_k<false><<<8192,256>>>(vb,  gv2, Bv2, nv, nullptr);
    tspb_k<<<dim3(32,64,4), tb>>>(nv, nvT_h, nvT_l, 2048, 1024, sLD, sLD);

    gemm_bf3<1,false><<<gS,256,SMEMB>>>(nq_h,nq_l, nk_h,nk_l, 0, a2,0,0, 0,0, 2048,2048,1024, it, sLD,sLD,sLL);
    softmax_k<true><<<8192,256>>>(a2, P_h, P_l);
    gemm_bf3<2,false><<<gO,256,SMEMB>>>(P_h,P_l, nvT_h,nvT_l, 0, 0,oa_h,oa_l, 0,0, 2048,1024,2048, 1.f, sLL,sDL,sLD);
    gemm_bf3<1,true ><<<gproj,256,SMEMB>>>(oa_h,oa_l, WTh(7),WTl(7), bW[7], out,0,0, 0,0, 8192,1024,1024, 1.f, 0,0,0);
}

// round 5
// speedup vs baseline: 1.1335x; 1.1335x over previous
#include <cuda_runtime.h>
#include <cuda_bf16.h>
#include <cstdint>

// ---------------------------------------------------------------------------
// B=4, L=2048, D=1024, fp32. Outputs: out(8.39M) | res(16.78M) | a2(16.78M).
// GEMMs via legacy mma.sync bf16 with 2-term bf16 split (3 products).
// R5: 2-stage pipeline (80KB smem) + <=128 regs -> 2 CTAs/SM.
// ---------------------------------------------------------------------------

#define SZB 8388608ll      // 8192*1024 elements
#define SSB 16777216ll     // 4*2048*2048 elements
#define WSZ 1048576ll      // 1024*1024 elements

__device__ float g_buf[151000064ull];   // 604MB scratch pool

using bf16 = __nv_bfloat16;

__device__ __forceinline__ uint32_t smem_u32(const void* p){
    uint32_t a;
    asm("{ .reg .u64 t; cvta.to.shared.u64 t, %1; cvt.u32.u64 %0, t; }" : "=r"(a) : "l"(p));
    return a;
}
__device__ __forceinline__ uint32_t pack2(float x, float y){
    __nv_bfloat162 t = __floats2bfloat162_rn(x, y);
    return *(uint32_t*)&t;
}
__device__ __forceinline__ void split1(float x, float& h, float& l){
    h = __bfloat162float(__float2bfloat16(x));
    l = x - h;
}

#define LDSM4(R, addr) \
    asm volatile("ldmatrix.sync.aligned.m8n8.x4.shared.b16 {%0,%1,%2,%3}, [%4];" \
        : "=r"((R)[0]), "=r"((R)[1]), "=r"((R)[2]), "=r"((R)[3]) : "r"(addr))

#define MMA16816(d, a, b) \
    asm volatile("mma.sync.aligned.m16n8k16.row.col.f32.bf16.bf16.f32 " \
        "{%0,%1,%2,%3}, {%4,%5,%6,%7}, {%8,%9}, {%0,%1,%2,%3};" \
        : "+f"((d)[0]), "+f"((d)[1]), "+f"((d)[2]), "+f"((d)[3]) \
        : "r"((a)[0]), "r"((a)[1]), "r"((a)[2]), "r"((a)[3]), "r"((b)[0]), "r"((b)[1]))

#define CP_ASYNC16(dst, src) \
    asm volatile("cp.async.cg.shared.global [%0], [%1], 16;" :: "r"(dst), "l"(src))

// ---------------------------------------------------------------------------
// GEMM: C = scale*(A @ B^T) (+bias).  A=(Ah,Al)[M,K] bf16, B=(Bh,Bl)[N,K] bf16.
// Products: AhBh + AhBl + AlBh.
// OM bit0: fp32 C; bit1: bf16 split (Ch,Cl); bit2: fp32 res (row stride 2048).
// 128x128 tile, BK=32, 2-stage cp.async, 8 warps (2x4), warp tile 64x32.
// 2 CTAs/SM (80KB smem, <=128 regs).
// ---------------------------------------------------------------------------
constexpr int TPAD  = 80;                 // padded row stride bytes
constexpr int TILEB = 128 * TPAD;         // 10240
constexpr int STGB  = 4 * TILEB;          // 40960
constexpr int SMEMB = 2 * STGB;           // 81920

template<int OM, bool BIAS>
__global__ void __launch_bounds__(256, 2) gemm_bf3(
    const bf16* __restrict__ Ah, const bf16* __restrict__ Al,
    const bf16* __restrict__ Bh, const bf16* __restrict__ Bl,
    const float* __restrict__ bias,
    float* __restrict__ Cf, bf16* __restrict__ Ch, bf16* __restrict__ Cl,
    float* __restrict__ Cres, int resOff,
    int M, int N, int K, float scale,
    long long sA, long long sB, long long sC)
{
    extern __shared__ char sm[];
    const uint32_t sb = smem_u32(sm);
    const int tid = threadIdx.x, lane = tid & 31, warp = tid >> 5;
    const int wm = warp >> 2, wn = warp & 3;
    const int bz = blockIdx.z;
    Ah += bz * sA;  Al += bz * sA;
    Bh += bz * sB;  Bl += bz * sB;
    const long long co = (long long)bz * sC;
    const int m0 = blockIdx.y * 128, n0 = blockIdx.x * 128;

    auto load_stage = [&](int slot, int k0){
        const uint32_t s = sb + slot * STGB;
        const bf16* srcs[4] = {Ah, Al, Bh, Bl};
#pragma unroll
        for (int t = 0; t < 4; t++) {
            const bf16* src = srcs[t];
            const int rbase = (t < 2) ? m0 : n0;
#pragma unroll
            for (int i = 0; i < 2; i++) {
                const int c = tid + i * 256;          // 0..511
                const int row = c >> 2, s4 = c & 3;
                const uint32_t dst = s + t * TILEB + row * TPAD + s4 * 16;
                const bf16* g = src + (long long)(rbase + row) * K + k0 + s4 * 8;
                CP_ASYNC16(dst, g);
            }
        }
    };

    const int NS = K / 32;
    load_stage(0, 0);
    asm volatile("cp.async.commit_group;" ::: "memory");

    float acc[4][4][4] = {};

    for (int s = 0; s < NS; s++) {
        asm volatile("cp.async.wait_group 0;" ::: "memory");
        __syncthreads();
        if (s + 1 < NS) {
            load_stage((s + 1) & 1, (s + 1) * 32);
            asm volatile("cp.async.commit_group;" ::: "memory");
        }

        const uint32_t st  = sb + (s & 1) * STGB;
        const uint32_t tAh = st, tAl = st + TILEB, tBh = st + 2*TILEB, tBl = st + 3*TILEB;

#pragma unroll
        for (int ks = 0; ks < 2; ks++) {
            const int kb = ks * 32;   // byte offset of 16-elem k slab
            uint32_t a[4][4], bh[4][2], bl[4][2];
            const uint32_t abyo = kb + ((lane >> 4) << 4);
            const uint32_t arow = wm * 64 + (lane & 15);
#pragma unroll
            for (int mi = 0; mi < 4; mi++)
                LDSM4(a[mi], tAh + (arow + mi * 16) * TPAD + abyo);
#pragma unroll
            for (int pi = 0; pi < 2; pi++) {
                const uint32_t r   = wn * 32 + pi * 16 + (lane & 7) + ((lane >> 4) << 3);
                const uint32_t byo = kb + (((lane >> 3) & 1) << 4);
                uint32_t v[4];
                LDSM4(v, tBh + r * TPAD + byo);
                bh[2*pi][0] = v[0]; bh[2*pi][1] = v[1];
                bh[2*pi+1][0] = v[2]; bh[2*pi+1][1] = v[3];
                LDSM4(v, tBl + r * TPAD + byo);
                bl[2*pi][0] = v[0]; bl[2*pi][1] = v[1];
                bl[2*pi+1][0] = v[2]; bl[2*pi+1][1] = v[3];
            }
            // products using Ah
#pragma unroll
            for (int mi = 0; mi < 4; mi++)
#pragma unroll
                for (int ni = 0; ni < 4; ni++)
                    MMA16816(acc[mi][ni], a[mi], bh[ni]);
#pragma unroll
            for (int mi = 0; mi < 4; mi++)
#pragma unroll
                for (int ni = 0; ni < 4; ni++)
                    MMA16816(acc[mi][ni], a[mi], bl[ni]);
            // reload a <- Al (reuse registers), product with Bh
#pragma unroll
            for (int mi = 0; mi < 4; mi++)
                LDSM4(a[mi], tAl + (arow + mi * 16) * TPAD + abyo);
#pragma unroll
            for (int mi = 0; mi < 4; mi++)
#pragma unroll
                for (int ni = 0; ni < 4; ni++)
                    MMA16816(acc[mi][ni], a[mi], bh[ni]);
        }
        __syncthreads();
    }

    // epilogue
#pragma unroll
    for (int mi = 0; mi < 4; mi++) {
        const int r0 = m0 + wm * 64 + mi * 16 + (lane >> 2);
#pragma unroll
        for (int ni = 0; ni < 4; ni++) {
            const int col = n0 + wn * 32 + ni * 8 + (lane & 3) * 2;
            float b0 = 0.f, b1 = 0.f;
            if (BIAS) { b0 = __ldg(bias + col); b1 = __ldg(bias + col + 1); }
            const float x0 = acc[mi][ni][0] * scale + b0;
            const float x1 = acc[mi][ni][1] * scale + b1;
            const float x2 = acc[mi][ni][2] * scale + b0;
            const float x3 = acc[mi][ni][3] * scale + b1;
            const long long g0 = co + (long long)r0 * N + col;
            const long long g1 = co + (long long)(r0 + 8) * N + col;
            if (OM & 1) {
                *(float2*)(Cf + g0) = make_float2(x0, x1);
                *(float2*)(Cf + g1) = make_float2(x2, x3);
            }
            if (OM & 2) {
                float h0, l0, h1, l1, h2, l2, h3, l3;
                split1(x0, h0, l0); split1(x1, h1, l1);
                split1(x2, h2, l2); split1(x3, h3, l3);
                *(uint32_t*)(Ch + g0) = pack2(h0, h1);
                *(uint32_t*)(Ch + g1) = pack2(h2, h3);
                *(uint32_t*)(Cl + g0) = pack2(l0, l1);
                *(uint32_t*)(Cl + g1) = pack2(l2, l3);
            }
            if (OM & 4) {     // residual copy, row stride 2048, col offset resOff
                const long long rg0 = (long long)r0 * 2048 + resOff + col;
                const long long rg1 = (long long)(r0 + 8) * 2048 + resOff + col;
                *(float2*)(Cres + rg0) = make_float2(x0, x1);
                *(float2*)(Cres + rg1) = make_float2(x2, x3);
            }
        }
    }
}

// ---------------------------------------------------------------------------
// batched fp32 -> bf16 hi/lo split (3 tensors)
// ---------------------------------------------------------------------------
struct Split3 { const float* x[3]; bf16* h[3]; bf16* l[3]; };

__global__ void __launch_bounds__(256) split3_k(Split3 j)
{
    const int z = blockIdx.y;
    const float* x = j.x[z];
    bf16* h = j.h[z]; bf16* l = j.l[z];
    const long long i = ((long long)blockIdx.x * 256 + threadIdx.x) * 4;
    const float4 v = *(const float4*)(x + i);
    float h0,l0,h1,l1,h2,l2,h3,l3;
    split1(v.x,h0,l0); split1(v.y,h1,l1); split1(v.z,h2,l2); split1(v.w,h3,l3);
    uint2 hp, lp;
    hp.x = pack2(h0,h1); hp.y = pack2(h2,h3);
    lp.x = pack2(l0,l1); lp.y = pack2(l2,l3);
    *(uint2*)(h + i) = hp;
    *(uint2*)(l + i) = lp;
}

// ---------------------------------------------------------------------------
// transpose + split: X[R,C] fp32 -> T[C,R] bf16 hi/lo  (z batches)
// ---------------------------------------------------------------------------
__global__ void __launch_bounds__(256) tspb_k(
    const float* __restrict__ X, bf16* __restrict__ Th, bf16* __restrict__ Tl,
    int R, int C, long long sIn, long long sOut)
{
    __shared__ float t[32][33];
    X  += (long long)blockIdx.z * sIn;
    Th += (long long)blockIdx.z * sOut;
    Tl += (long long)blockIdx.z * sOut;
    const int c0 = blockIdx.x * 32, r0 = blockIdx.y * 32;
    const int tx = threadIdx.x, ty = threadIdx.y;       // (32,8)
#pragma unroll
    for (int i = 0; i < 4; i++)
        t[ty + i * 8][tx] = X[(long long)(r0 + ty + i * 8) * C + c0 + tx];
    __syncthreads();
#pragma unroll
    for (int i = 0; i < 4; i++) {
        const float v = t[tx][ty + i * 8];
        float h, l; split1(v, h, l);
        const long long g = (long long)(c0 + ty + i * 8) * R + r0 + tx;
        Th[g] = __float2bfloat16(h);
        Tl[g] = __float2bfloat16(l);
    }
}

// batched weight transpose+split (8 weights, 1024x1024 each)
struct W8 { const float* w[8]; bf16* th[8]; bf16* tl[8]; };

__global__ void __launch_bounds__(256) tspw_k(W8 j)
{
    __shared__ float t[32][33];
    const int z = blockIdx.z;
    const float* X = j.w[z];
    bf16* Th = j.th[z]; bf16* Tl = j.tl[z];
    const int c0 = blockIdx.x * 32, r0 = blockIdx.y * 32;
    const int tx = threadIdx.x, ty = threadIdx.y;
#pragma unroll
    for (int i = 0; i < 4; i++)
        t[ty + i * 8][tx] = X[(long long)(r0 + ty + i * 8) * 1024 + c0 + tx];
    __syncthreads();
#pragma unroll
    for (int i = 0; i < 4; i++) {
        const float v = t[tx][ty + i * 8];
        float h, l; split1(v, h, l);
        const long long g = (long long)(c0 + ty + i * 8) * 1024 + r0 + tx;
        Th[g] = __float2bfloat16(h);
        Tl[g] = __float2bfloat16(l);
    }
}

// ---------------------------------------------------------------------------
// LayerNorm rows of 1024. SPLIT: bf16 hi/lo out; else fp32 out.
// ---------------------------------------------------------------------------
template<bool SPLIT>
__global__ void __launch_bounds__(256) ln_k(
    const float* __restrict__ x, const float* __restrict__ g,
    const float* __restrict__ b, void* __restrict__ y0, void* __restrict__ y1)
{
    const long long row = blockIdx.x;
    const float4 v = ((const float4*)(x + row * 1024))[threadIdx.x];

    float s  = v.x + v.y + v.z + v.w;
    float s2 = v.x*v.x + v.y*v.y + v.z*v.z + v.w*v.w;
    __shared__ float sh[8], sh2[8];
#pragma unroll
    for (int o = 16; o > 0; o >>= 1) {
        s  += __shfl_xor_sync(0xffffffffu, s, o);
        s2 += __shfl_xor_sync(0xffffffffu, s2, o);
    }
    const int lane = threadIdx.x & 31, warp = threadIdx.x >> 5;
    if (lane == 0) { sh[warp] = s; sh2[warp] = s2; }
    __syncthreads();
    float S = 0.f, S2 = 0.f;
#pragma unroll
    for (int i = 0; i < 8; i++) { S += sh[i]; S2 += sh2[i]; }
    const float mean = S * (1.0f / 1024.0f);
    const float var  = S2 * (1.0f / 1024.0f) - mean * mean;
    const float inv  = rsqrtf(var + 1e-6f);

    const float4 gg = ((const float4*)g)[threadIdx.x];
    const float4 bb = ((const float4*)b)[threadIdx.x];
    float4 o;
    o.x = (v.x - mean) * inv * gg.x + bb.x;
    o.y = (v.y - mean) * inv * gg.y + bb.y;
    o.z = (v.z - mean) * inv * gg.z + bb.z;
    o.w = (v.w - mean) * inv * gg.w + bb.w;
    if (SPLIT) {
        float h0,l0,h1,l1,h2,l2,h3,l3;
        split1(o.x,h0,l0); split1(o.y,h1,l1); split1(o.z,h2,l2); split1(o.w,h3,l3);
        uint2 hp, lp;
        hp.x = pack2(h0,h1); hp.y = pack2(h2,h3);
        lp.x = pack2(l0,l1); lp.y = pack2(l2,l3);
        ((uint2*)((bf16*)y0 + row * 1024))[threadIdx.x] = hp;
        ((uint2*)((bf16*)y1 + row * 1024))[threadIdx.x] = lp;
    } else {
        ((float4*)((float*)y0 + row * 1024))[threadIdx.x] = o;
    }
}

// ---------------------------------------------------------------------------
// row softmax (2048); writes bf16 split P; optionally fp32 back in place.
// ---------------------------------------------------------------------------
template<bool F32OUT>
__global__ void __launch_bounds__(256) softmax_k(
    float* __restrict__ S, bf16* __restrict__ Ph, bf16* __restrict__ Pl)
{
    const long long row = blockIdx.x;
    float* r = S + row * 2048;
    const int base = threadIdx.x * 8;

    float v[8];
    float4 a = *(const float4*)(r + base);
    float4 c = *(const float4*)(r + base + 4);
    v[0]=a.x; v[1]=a.y; v[2]=a.z; v[3]=a.w; v[4]=c.x; v[5]=c.y; v[6]=c.z; v[7]=c.w;

    float mx = v[0];
#pragma unroll
    for (int i = 1; i < 8; i++) mx = fmaxf(mx, v[i]);
    __shared__ float shm[8], shs[8];
#pragma unroll
    for (int o = 16; o > 0; o >>= 1) mx = fmaxf(mx, __shfl_xor_sync(0xffffffffu, mx, o));
    const int lane = threadIdx.x & 31, warp = threadIdx.x >> 5;
    if (lane == 0) shm[warp] = mx;
    __syncthreads();
    float M = shm[0];
#pragma unroll
    for (int i = 1; i < 8; i++) M = fmaxf(M, shm[i]);

    float sum = 0.f;
#pragma unroll
    for (int i = 0; i < 8; i++) { v[i] = __expf(v[i] - M); sum += v[i]; }
#pragma unroll
    for (int o = 16; o > 0; o >>= 1) sum += __shfl_xor_sync(0xffffffffu, sum, o);
    if (lane == 0) shs[warp] = sum;
    __syncthreads();
    float T = 0.f;
#pragma unroll
    for (int i = 0; i < 8; i++) T += shs[i];
    const float inv = 1.0f / T;

    uint4 hp, lp;
    float p0,p1,h0,l0,h1,l1;
    p0 = v[0]*inv; p1 = v[1]*inv; split1(p0,h0,l0); split1(p1,h1,l1);
    hp.x = pack2(h0,h1); lp.x = pack2(l0,l1); a.x = p0; a.y = p1;
    p0 = v[2]*inv; p1 = v[3]*inv; split1(p0,h0,l0); split1(p1,h1,l1);
    hp.y = pack2(h0,h1); lp.y = pack2(l0,l1); a.z = p0; a.w = p1;
    p0 = v[4]*inv; p1 = v[5]*inv; split1(p0,h0,l0); split1(p1,h1,l1);
    hp.z = pack2(h0,h1); lp.z = pack2(l0,l1); c.x = p0; c.y = p1;
    p0 = v[6]*inv; p1 = v[7]*inv; split1(p0,h0,l0); split1(p1,h1,l1);
    hp.w = pack2(h0,h1); lp.w = pack2(l0,l1); c.z = p0; c.w = p1;

    *(uint4*)(Ph + row * 2048 + base) = hp;
    *(uint4*)(Pl + row * 2048 + base) = lp;
    if (F32OUT) {
        *(float4*)(r + base)     = a;
        *(float4*)(r + base + 4) = c;
    }
}

// ---------------------------------------------------------------------------
extern "C" void kernel_launch(void* const* d_in, const int* in_sizes, int n_in,
                              void* d_out, int out_size)
{
    const float* q = (const float*)d_in[0];
    const float* k = (const float*)d_in[1];
    const float* v = (const float*)d_in[2];
    const float* W[8]  = {(const float*)d_in[3],  (const float*)d_in[5],
                          (const float*)d_in[7],  (const float*)d_in[9],
                          (const float*)d_in[11], (const float*)d_in[13],
                          (const float*)d_in[15], (const float*)d_in[17]};
    const float* bW[8] = {(const float*)d_in[4],  (const float*)d_in[6],
                          (const float*)d_in[8],  (const float*)d_in[10],
                          (const float*)d_in[12], (const float*)d_in[14],
                          (const float*)d_in[16], (const float*)d_in[18]};
    const float* gq1 = (const float*)d_in[19]; const float* Bq1 = (const float*)d_in[20];
    const float* gk1 = (const float*)d_in[21]; const float* Bk1 = (const float*)d_in[22];
    const float* gv1 = (const float*)d_in[23]; const float* Bv1 = (const float*)d_in[24];
    const float* gq2 = (const float*)d_in[25]; const float* Bq2 = (const float*)d_in[26];
    const float* gk2 = (const float*)d_in[27]; const float* Bk2 = (const float*)d_in[28];
    const float* gv2 = (const float*)d_in[29]; const float* Bv2 = (const float*)d_in[30];

    float* out = (float*)d_out;
    float* res = out + SZB;
    float* a2  = res + SSB;

    float* buf = nullptr;
    cudaGetSymbolAddress((void**)&buf, g_buf);
    char* P = (char*)buf;
    auto takeB = [&](long long bytes){ char* r = P; P += bytes; return r; };
    bf16* q_h  = (bf16*)takeB(SZB*2); bf16* q_l  = (bf16*)takeB(SZB*2);
    bf16* k_h  = (bf16*)takeB(SZB*2); bf16* k_l  = (bf16*)takeB(SZB*2);
    bf16* v_h  = (bf16*)takeB(SZB*2); bf16* v_l  = (bf16*)takeB(SZB*2);
    float* q1b = (float*)takeB(SZB*4);
    float* kb  = (float*)takeB(SZB*4);
    float* vb  = (float*)takeB(SZB*4);
    float* q2b = (float*)takeB(SZB*4);
    bf16* nq_h = (bf16*)takeB(SZB*2); bf16* nq_l = (bf16*)takeB(SZB*2);
    bf16* nk_h = (bf16*)takeB(SZB*2); bf16* nk_l = (bf16*)takeB(SZB*2);
    float* nv  = (float*)takeB(SZB*4);
    bf16* nvT_h= (bf16*)takeB(SZB*2); bf16* nvT_l= (bf16*)takeB(SZB*2);
    bf16* oa_h = (bf16*)takeB(SZB*2); bf16* oa_l = (bf16*)takeB(SZB*2);
    bf16* o1_h = (bf16*)takeB(SZB*2); bf16* o1_l = (bf16*)takeB(SZB*2);
    float* Sbuf= (float*)takeB(SSB*4);
    bf16* P_h  = (bf16*)takeB(SSB*2); bf16* P_l  = (bf16*)takeB(SSB*2);
    bf16* WTp  = (bf16*)takeB(8ll * 2 * WSZ * 2);
    auto WTh = [&](int i){ return WTp + (long long)i * 2 * WSZ; };
    auto WTl = [&](int i){ return WTp + (long long)i * 2 * WSZ + WSZ; };

    cudaFuncSetAttribute(gemm_bf3<1,true >, cudaFuncAttributeMaxDynamicSharedMemorySize, SMEMB);
    cudaFuncSetAttribute(gemm_bf3<1,false>, cudaFuncAttributeMaxDynamicSharedMemorySize, SMEMB);
    cudaFuncSetAttribute(gemm_bf3<2,true >, cudaFuncAttributeMaxDynamicSharedMemorySize, SMEMB);
    cudaFuncSetAttribute(gemm_bf3<2,false>, cudaFuncAttributeMaxDynamicSharedMemorySize, SMEMB);
    cudaFuncSetAttribute(gemm_bf3<5,true >, cudaFuncAttributeMaxDynamicSharedMemorySize, SMEMB);

    const dim3 tb(32, 8);
    const dim3 gproj(1024/128, 8192/128, 1);     // 8 x 64
    const dim3 gS(2048/128, 2048/128, 4);        // 16 x 16 x 4
    const dim3 gO(1024/128, 2048/128, 4);        // 8 x 16 x 4
    const float it = 1.0f / 32.0f;
    const long long sLD = 2048ll*1024, sLL = 2048ll*2048, sDL = 1024ll*2048;

    // operand prep (batched)
    Split3 s3;
    s3.x[0] = q; s3.h[0] = q_h; s3.l[0] = q_l;
    s3.x[1] = k; s3.h[1] = k_h; s3.l[1] = k_l;
    s3.x[2] = v; s3.h[2] = v_h; s3.l[2] = v_l;
    split3_k<<<dim3(SZB/4/256, 3), 256>>>(s3);
    W8 w8;
    for (int i = 0; i < 8; i++) { w8.w[i] = W[i]; w8.th[i] = WTh(i); w8.tl[i] = WTl(i); }
    tspw_k<<<dim3(32,32,8), tb>>>(w8);

    // ---------------- layer 1 ----------------
    gemm_bf3<5,true><<<gproj,256,SMEMB>>>(q_h,q_l, WTh(0),WTl(0), bW[0], q1b,0,0, res,0,    8192,1024,1024, 1.f, 0,0,0);
    gemm_bf3<1,true><<<gproj,256,SMEMB>>>(k_h,k_l, WTh(1),WTl(1), bW[1], kb, 0,0, 0,0,      8192,1024,1024, 1.f, 0,0,0);
    gemm_bf3<1,true><<<gproj,256,SMEMB>>>(v_h,v_l, WTh(2),WTl(2), bW[2], vb, 0,0, 0,0,      8192,1024,1024, 1.f, 0,0,0);

    ln_k<true ><<<8192,256>>>(q1b, gq1, Bq1, nq_h, nq_l);
    ln_k<true ><<<8192,256>>>(kb,  gk1, Bk1, nk_h, nk_l);
    ln_k<false><<<8192,256>>>(vb,  gv1, Bv1, nv, nullptr);
    tspb_k<<<dim3(32,64,4), tb>>>(nv, nvT_h, nvT_l, 2048, 1024, sLD, sLD);

    gemm_bf3<1,false><<<gS,256,SMEMB>>>(nq_h,nq_l, nk_h,nk_l, 0, Sbuf,0,0, 0,0, 2048,2048,1024, it, sLD,sLD,sLL);
    softmax_k<false><<<8192,256>>>(Sbuf, P_h, P_l);
    gemm_bf3<2,false><<<gO,256,SMEMB>>>(P_h,P_l, nvT_h,nvT_l, 0, 0,oa_h,oa_l, 0,0, 2048,1024,2048, 1.f, sLL,sDL,sLD);
    gemm_bf3<2,true ><<<gproj,256,SMEMB>>>(oa_h,oa_l, WTh(3),WTl(3), bW[3], 0,o1_h,o1_l, 0,0, 8192,1024,1024, 1.f, 0,0,0);

    // ---------------- layer 2 ----------------
    gemm_bf3<5,true><<<gproj,256,SMEMB>>>(o1_h,o1_l, WTh(4),WTl(4), bW[4], q2b,0,0, res,1024, 8192,1024,1024, 1.f, 0,0,0);
    gemm_bf3<1,true><<<gproj,256,SMEMB>>>(k_h,k_l,   WTh(5),WTl(5), bW[5], kb, 0,0, 0,0,      8192,1024,1024, 1.f, 0,0,0);
    gemm_bf3<1,true><<<gproj,256,SMEMB>>>(v_h,v_l,   WTh(6),WTl(6), bW[6], vb, 0,0, 0,0,      8192,1024,1024, 1.f, 0,0,0);

    ln_k<true ><<<8192,256>>>(q2b, gq2, Bq2, nq_h, nq_l);
    ln_k<true ><<<8192,256>>>(kb,  gk2, Bk2, nk_h, nk_l);
    ln_k<false><<<8192,256>>>(vb,  gv2, Bv2, nv, nullptr);
    tspb_k<<<dim3(32,64,4), tb>>>(nv, nvT_h, nvT_l, 2048, 1024, sLD, sLD);

    gemm_bf3<1,false><<<gS,256,SMEMB>>>(nq_h,nq_l, nk_h,nk_l, 0, a2,0,0, 0,0, 2048,2048,1024, it, sLD,sLD,sLL);
    softmax_k<true><<<8192,256>>>(a2, P_h, P_l);
    gemm_bf3<2,false><<<gO,256,SMEMB>>>(P_h,P_l, nvT_h,nvT_l, 0, 0,oa_h,oa_l, 0,0, 2048,1024,2048, 1.f, sLL,sDL,sLD);
    gemm_bf3<1,true ><<<gproj,256,SMEMB>>>(oa_h,oa_l, WTh(7),WTl(7), bW[7], out,0,0, 0,0, 8192,1024,1024, 1.f, 0,0,0);
}

// round 6
// speedup vs baseline: 1.2735x; 1.1236x over previous
#include <cuda_runtime.h>
#include <cuda_bf16.h>
#include <cstdint>

// ---------------------------------------------------------------------------
// B=4, L=2048, D=1024, fp32. Outputs: out(8.39M) | res(16.78M) | a2(16.78M).
// GEMMs via legacy mma.sync bf16 with 2-term bf16 split (3 products).
// R6: XOR-swizzled smem (64B rows), 3-stage cp.async pipeline, 2 CTAs/SM,
//     single __syncthreads per stage.
// ---------------------------------------------------------------------------

#define SZB 8388608ll      // 8192*1024 elements
#define SSB 16777216ll     // 4*2048*2048 elements
#define WSZ 1048576ll      // 1024*1024 elements

__device__ float g_buf[151000064ull];   // 604MB scratch pool

using bf16 = __nv_bfloat16;

__device__ __forceinline__ uint32_t smem_u32(const void* p){
    uint32_t a;
    asm("{ .reg .u64 t; cvta.to.shared.u64 t, %1; cvt.u32.u64 %0, t; }" : "=r"(a) : "l"(p));
    return a;
}
__device__ __forceinline__ uint32_t pack2(float x, float y){
    __nv_bfloat162 t = __floats2bfloat162_rn(x, y);
    return *(uint32_t*)&t;
}
__device__ __forceinline__ void split1(float x, float& h, float& l){
    h = __bfloat162float(__float2bfloat16(x));
    l = x - h;
}
// swizzled byte offset within a 128x64B tile: row r, 16B chunk c (0..3)
__device__ __forceinline__ uint32_t swz(uint32_t r, uint32_t c){
    return r * 64 + (((c ^ (r >> 1)) & 3) << 4) + (c & ~3u) * 16;
}

#define LDSM4(R, addr) \
    asm volatile("ldmatrix.sync.aligned.m8n8.x4.shared.b16 {%0,%1,%2,%3}, [%4];" \
        : "=r"((R)[0]), "=r"((R)[1]), "=r"((R)[2]), "=r"((R)[3]) : "r"(addr))

#define MMA16816(d, a, b) \
    asm volatile("mma.sync.aligned.m16n8k16.row.col.f32.bf16.bf16.f32 " \
        "{%0,%1,%2,%3}, {%4,%5,%6,%7}, {%8,%9}, {%0,%1,%2,%3};" \
        : "+f"((d)[0]), "+f"((d)[1]), "+f"((d)[2]), "+f"((d)[3]) \
        : "r"((a)[0]), "r"((a)[1]), "r"((a)[2]), "r"((a)[3]), "r"((b)[0]), "r"((b)[1]))

#define CP_ASYNC16(dst, src) \
    asm volatile("cp.async.cg.shared.global [%0], [%1], 16;" :: "r"(dst), "l"(src))

// ---------------------------------------------------------------------------
// GEMM: C = scale*(A @ B^T) (+bias).  A=(Ah,Al)[M,K] bf16, B=(Bh,Bl)[N,K] bf16.
// Products: AhBh + AhBl + AlBh.
// OM bit0: fp32 C; bit1: bf16 split (Ch,Cl); bit2: fp32 res (row stride 2048).
// 128x128 tile, BK=32, 3-stage cp.async (swizzled), 8 warps, warp tile 64x32.
// 2 CTAs/SM (96KB smem, <=128 regs).
// ---------------------------------------------------------------------------
constexpr int TILEB = 128 * 64;           // 8192  (one 128x32 bf16 tile, swizzled)
constexpr int STGB  = 4 * TILEB;          // 32768 (Ah, Al, Bh, Bl)
constexpr int SMEMB = 3 * STGB;           // 98304

template<int OM, bool BIAS>
__global__ void __launch_bounds__(256, 2) gemm_bf3(
    const bf16* __restrict__ Ah, const bf16* __restrict__ Al,
    const bf16* __restrict__ Bh, const bf16* __restrict__ Bl,
    const float* __restrict__ bias,
    float* __restrict__ Cf, bf16* __restrict__ Ch, bf16* __restrict__ Cl,
    float* __restrict__ Cres, int resOff,
    int M, int N, int K, float scale,
    long long sA, long long sB, long long sC)
{
    extern __shared__ char sm[];
    const uint32_t sb = smem_u32(sm);
    const int tid = threadIdx.x, lane = tid & 31, warp = tid >> 5;
    const int wm = warp >> 2, wn = warp & 3;
    const int bz = blockIdx.z;
    Ah += bz * sA;  Al += bz * sA;
    Bh += bz * sB;  Bl += bz * sB;
    const long long co = (long long)bz * sC;
    const int m0 = blockIdx.y * 128, n0 = blockIdx.x * 128;

    auto load_stage = [&](int slot, int k0){
        const uint32_t s = sb + slot * STGB;
        const bf16* srcs[4] = {Ah, Al, Bh, Bl};
#pragma unroll
        for (int t = 0; t < 4; t++) {
            const bf16* src = srcs[t];
            const int rbase = (t < 2) ? m0 : n0;
#pragma unroll
            for (int i = 0; i < 2; i++) {
                const int c = tid + i * 256;          // 0..511
                const uint32_t row = c >> 2, ch = c & 3;
                const uint32_t dst = s + t * TILEB + swz(row, ch);
                const bf16* g = src + (long long)(rbase + row) * K + k0 + ch * 8;
                CP_ASYNC16(dst, g);
            }
        }
    };

    const int NS = K / 32;
    load_stage(0, 0);
    asm volatile("cp.async.commit_group;" ::: "memory");
    load_stage(1, 32);
    asm volatile("cp.async.commit_group;" ::: "memory");

    float acc[4][4][4] = {};
    int slot = 0;

    for (int s = 0; s < NS; s++) {
        asm volatile("cp.async.wait_group 1;" ::: "memory");
        __syncthreads();
        if (s + 2 < NS) {
            int ns = slot + 2; if (ns >= 3) ns -= 3;
            load_stage(ns, (s + 2) * 32);
        }
        asm volatile("cp.async.commit_group;" ::: "memory");

        const uint32_t st  = sb + slot * STGB;
        const uint32_t tAh = st, tAl = st + TILEB, tBh = st + 2*TILEB, tBl = st + 3*TILEB;
        if (++slot == 3) slot = 0;

#pragma unroll
        for (int ks = 0; ks < 2; ks++) {
            uint32_t a[4][4], bh[4][2], bl[4][2];
            const uint32_t ach  = ks * 2 + (lane >> 4);
            const uint32_t arow = wm * 64 + (lane & 15);
#pragma unroll
            for (int mi = 0; mi < 4; mi++)
                LDSM4(a[mi], tAh + swz(arow + mi * 16, ach));
#pragma unroll
            for (int pi = 0; pi < 2; pi++) {
                const uint32_t brow = wn * 32 + pi * 16 + (lane & 7) + ((lane >> 4) << 3);
                const uint32_t bch  = ks * 2 + ((lane >> 3) & 1);
                uint32_t v[4];
                LDSM4(v, tBh + swz(brow, bch));
                bh[2*pi][0] = v[0]; bh[2*pi][1] = v[1];
                bh[2*pi+1][0] = v[2]; bh[2*pi+1][1] = v[3];
                LDSM4(v, tBl + swz(brow, bch));
                bl[2*pi][0] = v[0]; bl[2*pi][1] = v[1];
                bl[2*pi+1][0] = v[2]; bl[2*pi+1][1] = v[3];
            }
            // products using Ah
#pragma unroll
            for (int mi = 0; mi < 4; mi++)
#pragma unroll
                for (int ni = 0; ni < 4; ni++)
                    MMA16816(acc[mi][ni], a[mi], bh[ni]);
#pragma unroll
            for (int mi = 0; mi < 4; mi++)
#pragma unroll
                for (int ni = 0; ni < 4; ni++)
                    MMA16816(acc[mi][ni], a[mi], bl[ni]);
            // reload a <- Al (reuse registers), product with Bh
#pragma unroll
            for (int mi = 0; mi < 4; mi++)
                LDSM4(a[mi], tAl + swz(arow + mi * 16, ach));
#pragma unroll
            for (int mi = 0; mi < 4; mi++)
#pragma unroll
                for (int ni = 0; ni < 4; ni++)
                    MMA16816(acc[mi][ni], a[mi], bh[ni]);
        }
    }

    // epilogue
#pragma unroll
    for (int mi = 0; mi < 4; mi++) {
        const int r0 = m0 + wm * 64 + mi * 16 + (lane >> 2);
#pragma unroll
        for (int ni = 0; ni < 4; ni++) {
            const int col = n0 + wn * 32 + ni * 8 + (lane & 3) * 2;
            float b0 = 0.f, b1 = 0.f;
            if (BIAS) { b0 = __ldg(bias + col); b1 = __ldg(bias + col + 1); }
            const float x0 = acc[mi][ni][0] * scale + b0;
            const float x1 = acc[mi][ni][1] * scale + b1;
            const float x2 = acc[mi][ni][2] * scale + b0;
            const float x3 = acc[mi][ni][3] * scale + b1;
            const long long g0 = co + (long long)r0 * N + col;
            const long long g1 = co + (long long)(r0 + 8) * N + col;
            if (OM & 1) {
                *(float2*)(Cf + g0) = make_float2(x0, x1);
                *(float2*)(Cf + g1) = make_float2(x2, x3);
            }
            if (OM & 2) {
                float h0, l0, h1, l1, h2, l2, h3, l3;
                split1(x0, h0, l0); split1(x1, h1, l1);
                split1(x2, h2, l2); split1(x3, h3, l3);
                *(uint32_t*)(Ch + g0) = pack2(h0, h1);
                *(uint32_t*)(Ch + g1) = pack2(h2, h3);
                *(uint32_t*)(Cl + g0) = pack2(l0, l1);
                *(uint32_t*)(Cl + g1) = pack2(l2, l3);
            }
            if (OM & 4) {     // residual copy, row stride 2048, col offset resOff
                const long long rg0 = (long long)r0 * 2048 + resOff + col;
                const long long rg1 = (long long)(r0 + 8) * 2048 + resOff + col;
                *(float2*)(Cres + rg0) = make_float2(x0, x1);
                *(float2*)(Cres + rg1) = make_float2(x2, x3);
            }
        }
    }
}

// ---------------------------------------------------------------------------
// batched fp32 -> bf16 hi/lo split (3 tensors)
// ---------------------------------------------------------------------------
struct Split3 { const float* x[3]; bf16* h[3]; bf16* l[3]; };

__global__ void __launch_bounds__(256) split3_k(Split3 j)
{
    const int z = blockIdx.y;
    const float* x = j.x[z];
    bf16* h = j.h[z]; bf16* l = j.l[z];
    const long long i = ((long long)blockIdx.x * 256 + threadIdx.x) * 4;
    const float4 v = *(const float4*)(x + i);
    float h0,l0,h1,l1,h2,l2,h3,l3;
    split1(v.x,h0,l0); split1(v.y,h1,l1); split1(v.z,h2,l2); split1(v.w,h3,l3);
    uint2 hp, lp;
    hp.x = pack2(h0,h1); hp.y = pack2(h2,h3);
    lp.x = pack2(l0,l1); lp.y = pack2(l2,l3);
    *(uint2*)(h + i) = hp;
    *(uint2*)(l + i) = lp;
}

// ---------------------------------------------------------------------------
// transpose + split: X[R,C] fp32 -> T[C,R] bf16 hi/lo  (z batches)
// ---------------------------------------------------------------------------
__global__ void __launch_bounds__(256) tspb_k(
    const float* __restrict__ X, bf16* __restrict__ Th, bf16* __restrict__ Tl,
    int R, int C, long long sIn, long long sOut)
{
    __shared__ float t[32][33];
    X  += (long long)blockIdx.z * sIn;
    Th += (long long)blockIdx.z * sOut;
    Tl += (long long)blockIdx.z * sOut;
    const int c0 = blockIdx.x * 32, r0 = blockIdx.y * 32;
    const int tx = threadIdx.x, ty = threadIdx.y;       // (32,8)
#pragma unroll
    for (int i = 0; i < 4; i++)
        t[ty + i * 8][tx] = X[(long long)(r0 + ty + i * 8) * C + c0 + tx];
    __syncthreads();
#pragma unroll
    for (int i = 0; i < 4; i++) {
        const float v = t[tx][ty + i * 8];
        float h, l; split1(v, h, l);
        const long long g = (long long)(c0 + ty + i * 8) * R + r0 + tx;
        Th[g] = __float2bfloat16(h);
        Tl[g] = __float2bfloat16(l);
    }
}

// batched weight transpose+split (8 weights, 1024x1024 each)
struct W8 { const float* w[8]; bf16* th[8]; bf16* tl[8]; };

__global__ void __launch_bounds__(256) tspw_k(W8 j)
{
    __shared__ float t[32][33];
    const int z = blockIdx.z;
    const float* X = j.w[z];
    bf16* Th = j.th[z]; bf16* Tl = j.tl[z];
    const int c0 = blockIdx.x * 32, r0 = blockIdx.y * 32;
    const int tx = threadIdx.x, ty = threadIdx.y;
#pragma unroll
    for (int i = 0; i < 4; i++)
        t[ty + i * 8][tx] = X[(long long)(r0 + ty + i * 8) * 1024 + c0 + tx];
    __syncthreads();
#pragma unroll
    for (int i = 0; i < 4; i++) {
        const float v = t[tx][ty + i * 8];
        float h, l; split1(v, h, l);
        const long long g = (long long)(c0 + ty + i * 8) * 1024 + r0 + tx;
        Th[g] = __float2bfloat16(h);
        Tl[g] = __float2bfloat16(l);
    }
}

// ---------------------------------------------------------------------------
// LayerNorm rows of 1024. SPLIT: bf16 hi/lo out; else fp32 out.
// ---------------------------------------------------------------------------
template<bool SPLIT>
__global__ void __launch_bounds__(256) ln_k(
    const float* __restrict__ x, const float* __restrict__ g,
    const float* __restrict__ b, void* __restrict__ y0, void* __restrict__ y1)
{
    const long long row = blockIdx.x;
    const float4 v = ((const float4*)(x + row * 1024))[threadIdx.x];

    float s  = v.x + v.y + v.z + v.w;
    float s2 = v.x*v.x + v.y*v.y + v.z*v.z + v.w*v.w;
    __shared__ float sh[8], sh2[8];
#pragma unroll
    for (int o = 16; o > 0; o >>= 1) {
        s  += __shfl_xor_sync(0xffffffffu, s, o);
        s2 += __shfl_xor_sync(0xffffffffu, s2, o);
    }
    const int lane = threadIdx.x & 31, warp = threadIdx.x >> 5;
    if (lane == 0) { sh[warp] = s; sh2[warp] = s2; }
    __syncthreads();
    float S = 0.f, S2 = 0.f;
#pragma unroll
    for (int i = 0; i < 8; i++) { S += sh[i]; S2 += sh2[i]; }
    const float mean = S * (1.0f / 1024.0f);
    const float var  = S2 * (1.0f / 1024.0f) - mean * mean;
    const float inv  = rsqrtf(var + 1e-6f);

    const float4 gg = ((const float4*)g)[threadIdx.x];
    const float4 bb = ((const float4*)b)[threadIdx.x];
    float4 o;
    o.x = (v.x - mean) * inv * gg.x + bb.x;
    o.y = (v.y - mean) * inv * gg.y + bb.y;
    o.z = (v.z - mean) * inv * gg.z + bb.z;
    o.w = (v.w - mean) * inv * gg.w + bb.w;
    if (SPLIT) {
        float h0,l0,h1,l1,h2,l2,h3,l3;
        split1(o.x,h0,l0); split1(o.y,h1,l1); split1(o.z,h2,l2); split1(o.w,h3,l3);
        uint2 hp, lp;
        hp.x = pack2(h0,h1); hp.y = pack2(h2,h3);
        lp.x = pack2(l0,l1); lp.y = pack2(l2,l3);
        ((uint2*)((bf16*)y0 + row * 1024))[threadIdx.x] = hp;
        ((uint2*)((bf16*)y1 + row * 1024))[threadIdx.x] = lp;
    } else {
        ((float4*)((float*)y0 + row * 1024))[threadIdx.x] = o;
    }
}

// ---------------------------------------------------------------------------
// row softmax (2048); writes bf16 split P; optionally fp32 back in place.
// ---------------------------------------------------------------------------
template<bool F32OUT>
__global__ void __launch_bounds__(256) softmax_k(
    float* __restrict__ S, bf16* __restrict__ Ph, bf16* __restrict__ Pl)
{
    const long long row = blockIdx.x;
    float* r = S + row * 2048;
    const int base = threadIdx.x * 8;

    float v[8];
    float4 a = *(const float4*)(r + base);
    float4 c = *(const float4*)(r + base + 4);
    v[0]=a.x; v[1]=a.y; v[2]=a.z; v[3]=a.w; v[4]=c.x; v[5]=c.y; v[6]=c.z; v[7]=c.w;

    float mx = v[0];
#pragma unroll
    for (int i = 1; i < 8; i++) mx = fmaxf(mx, v[i]);
    __shared__ float shm[8], shs[8];
#pragma unroll
    for (int o = 16; o > 0; o >>= 1) mx = fmaxf(mx, __shfl_xor_sync(0xffffffffu, mx, o));
    const int lane = threadIdx.x & 31, warp = threadIdx.x >> 5;
    if (lane == 0) shm[warp] = mx;
    __syncthreads();
    float M = shm[0];
#pragma unroll
    for (int i = 1; i < 8; i++) M = fmaxf(M, shm[i]);

    float sum = 0.f;
#pragma unroll
    for (int i = 0; i < 8; i++) { v[i] = __expf(v[i] - M); sum += v[i]; }
#pragma unroll
    for (int o = 16; o > 0; o >>= 1) sum += __shfl_xor_sync(0xffffffffu, sum, o);
    if (lane == 0) shs[warp] = sum;
    __syncthreads();
    float T = 0.f;
#pragma unroll
    for (int i = 0; i < 8; i++) T += shs[i];
    const float inv = 1.0f / T;

    uint4 hp, lp;
    float p0,p1,h0,l0,h1,l1;
    p0 = v[0]*inv; p1 = v[1]*inv; split1(p0,h0,l0); split1(p1,h1,l1);
    hp.x = pack2(h0,h1); lp.x = pack2(l0,l1); a.x = p0; a.y = p1;
    p0 = v[2]*inv; p1 = v[3]*inv; split1(p0,h0,l0); split1(p1,h1,l1);
    hp.y = pack2(h0,h1); lp.y = pack2(l0,l1); a.z = p0; a.w = p1;
    p0 = v[4]*inv; p1 = v[5]*inv; split1(p0,h0,l0); split1(p1,h1,l1);
    hp.z = pack2(h0,h1); lp.z = pack2(l0,l1); c.x = p0; c.y = p1;
    p0 = v[6]*inv; p1 = v[7]*inv; split1(p0,h0,l0); split1(p1,h1,l1);
    hp.w = pack2(h0,h1); lp.w = pack2(l0,l1); c.z = p0; c.w = p1;

    *(uint4*)(Ph + row * 2048 + base) = hp;
    *(uint4*)(Pl + row * 2048 + base) = lp;
    if (F32OUT) {
        *(float4*)(r + base)     = a;
        *(float4*)(r + base + 4) = c;
    }
}

// ---------------------------------------------------------------------------
extern "C" void kernel_launch(void* const* d_in, const int* in_sizes, int n_in,
                              void* d_out, int out_size)
{
    const float* q = (const float*)d_in[0];
    const float* k = (const float*)d_in[1];
    const float* v = (const float*)d_in[2];
    const float* W[8]  = {(const float*)d_in[3],  (const float*)d_in[5],
                          (const float*)d_in[7],  (const float*)d_in[9],
                          (const float*)d_in[11], (const float*)d_in[13],
                          (const float*)d_in[15], (const float*)d_in[17]};
    const float* bW[8] = {(const float*)d_in[4],  (const float*)d_in[6],
                          (const float*)d_in[8],  (const float*)d_in[10],
                          (const float*)d_in[12], (const float*)d_in[14],
                          (const float*)d_in[16], (const float*)d_in[18]};
    const float* gq1 = (const float*)d_in[19]; const float* Bq1 = (const float*)d_in[20];
    const float* gk1 = (const float*)d_in[21]; const float* Bk1 = (const float*)d_in[22];
    const float* gv1 = (const float*)d_in[23]; const float* Bv1 = (const float*)d_in[24];
    const float* gq2 = (const float*)d_in[25]; const float* Bq2 = (const float*)d_in[26];
    const float* gk2 = (const float*)d_in[27]; const float* Bk2 = (const float*)d_in[28];
    const float* gv2 = (const float*)d_in[29]; const float* Bv2 = (const float*)d_in[30];

    float* out = (float*)d_out;
    float* res = out + SZB;
    float* a2  = res + SSB;

    float* buf = nullptr;
    cudaGetSymbolAddress((void**)&buf, g_buf);
    char* P = (char*)buf;
    auto takeB = [&](long long bytes){ char* r = P; P += bytes; return r; };
    bf16* q_h  = (bf16*)takeB(SZB*2); bf16* q_l  = (bf16*)takeB(SZB*2);
    bf16* k_h  = (bf16*)takeB(SZB*2); bf16* k_l  = (bf16*)takeB(SZB*2);
    bf16* v_h  = (bf16*)takeB(SZB*2); bf16* v_l  = (bf16*)takeB(SZB*2);
    float* q1b = (float*)takeB(SZB*4);
    float* kb  = (float*)takeB(SZB*4);
    float* vb  = (float*)takeB(SZB*4);
    float* q2b = (float*)takeB(SZB*4);
    bf16* nq_h = (bf16*)takeB(SZB*2); bf16* nq_l = (bf16*)takeB(SZB*2);
    bf16* nk_h = (bf16*)takeB(SZB*2); bf16* nk_l = (bf16*)takeB(SZB*2);
    float* nv  = (float*)takeB(SZB*4);
    bf16* nvT_h= (bf16*)takeB(SZB*2); bf16* nvT_l= (bf16*)takeB(SZB*2);
    bf16* oa_h = (bf16*)takeB(SZB*2); bf16* oa_l = (bf16*)takeB(SZB*2);
    bf16* o1_h = (bf16*)takeB(SZB*2); bf16* o1_l = (bf16*)takeB(SZB*2);
    float* Sbuf= (float*)takeB(SSB*4);
    bf16* P_h  = (bf16*)takeB(SSB*2); bf16* P_l  = (bf16*)takeB(SSB*2);
    bf16* WTp  = (bf16*)takeB(8ll * 2 * WSZ * 2);
    auto WTh = [&](int i){ return WTp + (long long)i * 2 * WSZ; };
    auto WTl = [&](int i){ return WTp + (long long)i * 2 * WSZ + WSZ; };

    cudaFuncSetAttribute(gemm_bf3<1,true >, cudaFuncAttributeMaxDynamicSharedMemorySize, SMEMB);
    cudaFuncSetAttribute(gemm_bf3<1,false>, cudaFuncAttributeMaxDynamicSharedMemorySize, SMEMB);
    cudaFuncSetAttribute(gemm_bf3<2,true >, cudaFuncAttributeMaxDynamicSharedMemorySize, SMEMB);
    cudaFuncSetAttribute(gemm_bf3<2,false>, cudaFuncAttributeMaxDynamicSharedMemorySize, SMEMB);
    cudaFuncSetAttribute(gemm_bf3<5,true >, cudaFuncAttributeMaxDynamicSharedMemorySize, SMEMB);

    const dim3 tb(32, 8);
    const dim3 gproj(1024/128, 8192/128, 1);     // 8 x 64
    const dim3 gS(2048/128, 2048/128, 4);        // 16 x 16 x 4
    const dim3 gO(1024/128, 2048/128, 4);        // 8 x 16 x 4
    const float it = 1.0f / 32.0f;
    const long long sLD = 2048ll*1024, sLL = 2048ll*2048, sDL = 1024ll*2048;

    // operand prep (batched)
    Split3 s3;
    s3.x[0] = q; s3.h[0] = q_h; s3.l[0] = q_l;
    s3.x[1] = k; s3.h[1] = k_h; s3.l[1] = k_l;
    s3.x[2] = v; s3.h[2] = v_h; s3.l[2] = v_l;
    split3_k<<<dim3(SZB/4/256, 3), 256>>>(s3);
    W8 w8;
    for (int i = 0; i < 8; i++) { w8.w[i] = W[i]; w8.th[i] = WTh(i); w8.tl[i] = WTl(i); }
    tspw_k<<<dim3(32,32,8), tb>>>(w8);

    // ---------------- layer 1 ----------------
    gemm_bf3<5,true><<<gproj,256,SMEMB>>>(q_h,q_l, WTh(0),WTl(0), bW[0], q1b,0,0, res,0,    8192,1024,1024, 1.f, 0,0,0);
    gemm_bf3<1,true><<<gproj,256,SMEMB>>>(k_h,k_l, WTh(1),WTl(1), bW[1], kb, 0,0, 0,0,      8192,1024,1024, 1.f, 0,0,0);
    gemm_bf3<1,true><<<gproj,256,SMEMB>>>(v_h,v_l, WTh(2),WTl(2), bW[2], vb, 0,0, 0,0,      8192,1024,1024, 1.f, 0,0,0);

    ln_k<true ><<<8192,256>>>(q1b, gq1, Bq1, nq_h, nq_l);
    ln_k<true ><<<8192,256>>>(kb,  gk1, Bk1, nk_h, nk_l);
    ln_k<false><<<8192,256>>>(vb,  gv1, Bv1, nv, nullptr);
    tspb_k<<<dim3(32,64,4), tb>>>(nv, nvT_h, nvT_l, 2048, 1024, sLD, sLD);

    gemm_bf3<1,false><<<gS,256,SMEMB>>>(nq_h,nq_l, nk_h,nk_l, 0, Sbuf,0,0, 0,0, 2048,2048,1024, it, sLD,sLD,sLL);
    softmax_k<false><<<8192,256>>>(Sbuf, P_h, P_l);
    gemm_bf3<2,false><<<gO,256,SMEMB>>>(P_h,P_l, nvT_h,nvT_l, 0, 0,oa_h,oa_l, 0,0, 2048,1024,2048, 1.f, sLL,sDL,sLD);
    gemm_bf3<2,true ><<<gproj,256,SMEMB>>>(oa_h,oa_l, WTh(3),WTl(3), bW[3], 0,o1_h,o1_l, 0,0, 8192,1024,1024, 1.f, 0,0,0);

    // ---------------- layer 2 ----------------
    gemm_bf3<5,true><<<gproj,256,SMEMB>>>(o1_h,o1_l, WTh(4),WTl(4), bW[4], q2b,0,0, res,1024, 8192,1024,1024, 1.f, 0,0,0);
    gemm_bf3<1,true><<<gproj,256,SMEMB>>>(k_h,k_l,   WTh(5),WTl(5), bW[5], kb, 0,0, 0,0,      8192,1024,1024, 1.f, 0,0,0);
    gemm_bf3<1,true><<<gproj,256,SMEMB>>>(v_h,v_l,   WTh(6),WTl(6), bW[6], vb, 0,0, 0,0,      8192,1024,1024, 1.f, 0,0,0);

    ln_k<true ><<<8192,256>>>(q2b, gq2, Bq2, nq_h, nq_l);
    ln_k<true ><<<8192,256>>>(kb,  gk2, Bk2, nk_h, nk_l);
    ln_k<false><<<8192,256>>>(vb,  gv2, Bv2, nv, nullptr);
    tspb_k<<<dim3(32,64,4), tb>>>(nv, nvT_h, nvT_l, 2048, 1024, sLD, sLD);

    gemm_bf3<1,false><<<gS,256,SMEMB>>>(nq_h,nq_l, nk_h,nk_l, 0, a2,0,0, 0,0, 2048,2048,1024, it, sLD,sLD,sLL);
    softmax_k<true><<<8192,256>>>(a2, P_h, P_l);
    gemm_bf3<2,false><<<gO,256,SMEMB>>>(P_h,P_l, nvT_h,nvT_l, 0, 0,oa_h,oa_l, 0,0, 2048,1024,2048, 1.f, sLL,sDL,sLD);
    gemm_bf3<1,true ><<<gproj,256,SMEMB>>>(oa_h,oa_l, WTh(7),WTl(7), bW[7], out,0,0, 0,0, 8192,1024,1024, 1.f, 0,0,0);
}

// round 8
// speedup vs baseline: 1.3029x; 1.0230x over previous
#include <cuda_runtime.h>
#include <cuda_bf16.h>
#include <cstdint>

// ---------------------------------------------------------------------------
// B=4, L=2048, D=1024, fp32. Outputs: out(8.39M) | res(16.78M) | a2(16.78M).
// GEMMs via legacy mma.sync bf16, 2-term bf16 split (3 products).
// R8 = R7 with fixed scratch-pool size (R7 overflowed 637MB > 604MB pool).
// ---------------------------------------------------------------------------

#define SZB 8388608ll
#define SSB 16777216ll
#define WSZ 1048576ll

__device__ float g_buf[160000000ull];   // 640MB scratch pool (need ~637.6MB)

using bf16 = __nv_bfloat16;

__device__ __forceinline__ uint32_t smem_u32(const void* p){
    uint32_t a;
    asm("{ .reg .u64 t; cvta.to.shared.u64 t, %1; cvt.u32.u64 %0, t; }" : "=r"(a) : "l"(p));
    return a;
}
__device__ __forceinline__ uint32_t pack2(float x, float y){
    __nv_bfloat162 t = __floats2bfloat162_rn(x, y);
    return *(uint32_t*)&t;
}
__device__ __forceinline__ void split1(float x, float& h, float& l){
    h = __bfloat162float(__float2bfloat16(x));
    l = x - h;
}
// swizzled byte offset within a 128-row x 64B tile (A tiles, NT B tiles)
__device__ __forceinline__ uint32_t swz(uint32_t r, uint32_t c){
    return r * 64 + (((c ^ (r >> 1)) & 3) << 4) + (c & ~3u) * 16;
}
// swizzled byte offset within a 32-row x 256B tile (NN B tiles)
__device__ __forceinline__ uint32_t swzN(uint32_t r, uint32_t c){
    return r * 256 + ((c ^ (r & 7)) << 4);
}

#define LDSM4(R, addr) \
    asm volatile("ldmatrix.sync.aligned.m8n8.x4.shared.b16 {%0,%1,%2,%3}, [%4];" \
        : "=r"((R)[0]), "=r"((R)[1]), "=r"((R)[2]), "=r"((R)[3]) : "r"(addr))

#define LDSM4T(R, addr) \
    asm volatile("ldmatrix.sync.aligned.m8n8.x4.trans.shared.b16 {%0,%1,%2,%3}, [%4];" \
        : "=r"((R)[0]), "=r"((R)[1]), "=r"((R)[2]), "=r"((R)[3]) : "r"(addr))

#define MMA16816(d, a, b) \
    asm volatile("mma.sync.aligned.m16n8k16.row.col.f32.bf16.bf16.f32 " \
        "{%0,%1,%2,%3}, {%4,%5,%6,%7}, {%8,%9}, {%0,%1,%2,%3};" \
        : "+f"((d)[0]), "+f"((d)[1]), "+f"((d)[2]), "+f"((d)[3]) \
        : "r"((a)[0]), "r"((a)[1]), "r"((a)[2]), "r"((a)[3]), "r"((b)[0]), "r"((b)[1]))

#define CP_ASYNC16(dst, src) \
    asm volatile("cp.async.cg.shared.global [%0], [%1], 16;" :: "r"(dst), "l"(src))

constexpr int TILEB = 128 * 64;           // 8192 bytes (also 32x256 for NN B)
constexpr int STGB  = 4 * TILEB;          // 32768
constexpr int SMEMB = 3 * STGB;           // 98304

// ---------------------------------------------------------------------------
// NT GEMM: C = scale*(A @ B^T)(+bias). A[M,K], B[N,K] bf16 splits.
// OM bit0: fp32 C; bit1: bf16 split out; bit2: fp32 res write.
// ---------------------------------------------------------------------------
template<int OM, bool BIAS>
__global__ void __launch_bounds__(256, 2) gemm_bf3(
    const bf16* __restrict__ Ah, const bf16* __restrict__ Al,
    const bf16* __restrict__ Bh, const bf16* __restrict__ Bl,
    const float* __restrict__ bias,
    float* __restrict__ Cf, bf16* __restrict__ Ch, bf16* __restrict__ Cl,
    float* __restrict__ Cres, int resOff,
    int M, int N, int K, float scale,
    long long sA, long long sB, long long sC)
{
    extern __shared__ char sm[];
    const uint32_t sb = smem_u32(sm);
    const int tid = threadIdx.x, lane = tid & 31, warp = tid >> 5;
    const int wm = warp >> 2, wn = warp & 3;
    const int bz = blockIdx.z;
    Ah += bz * sA;  Al += bz * sA;
    Bh += bz * sB;  Bl += bz * sB;
    const long long co = (long long)bz * sC;
    const int m0 = blockIdx.y * 128, n0 = blockIdx.x * 128;

    auto load_stage = [&](int slot, int k0){
        const uint32_t s = sb + slot * STGB;
        const bf16* srcs[4] = {Ah, Al, Bh, Bl};
#pragma unroll
        for (int t = 0; t < 4; t++) {
            const bf16* src = srcs[t];
            const int rbase = (t < 2) ? m0 : n0;
#pragma unroll
            for (int i = 0; i < 2; i++) {
                const int c = tid + i * 256;
                const uint32_t row = c >> 2, ch = c & 3;
                const uint32_t dst = s + t * TILEB + swz(row, ch);
                const bf16* g = src + (long long)(rbase + row) * K + k0 + ch * 8;
                CP_ASYNC16(dst, g);
            }
        }
    };

    const int NS = K / 32;
    load_stage(0, 0);
    asm volatile("cp.async.commit_group;" ::: "memory");
    load_stage(1, 32);
    asm volatile("cp.async.commit_group;" ::: "memory");

    float acc[4][4][4] = {};
    int slot = 0;

    for (int s = 0; s < NS; s++) {
        asm volatile("cp.async.wait_group 1;" ::: "memory");
        __syncthreads();
        if (s + 2 < NS) {
            int ns = slot + 2; if (ns >= 3) ns -= 3;
            load_stage(ns, (s + 2) * 32);
        }
        asm volatile("cp.async.commit_group;" ::: "memory");

        const uint32_t st  = sb + slot * STGB;
        const uint32_t tAh = st, tAl = st + TILEB, tBh = st + 2*TILEB, tBl = st + 3*TILEB;
        if (++slot == 3) slot = 0;

#pragma unroll
        for (int ks = 0; ks < 2; ks++) {
            uint32_t a[4][4], bh[4][2], bl[4][2];
            const uint32_t ach  = ks * 2 + (lane >> 4);
            const uint32_t arow = wm * 64 + (lane & 15);
#pragma unroll
            for (int mi = 0; mi < 4; mi++)
                LDSM4(a[mi], tAh + swz(arow + mi * 16, ach));
#pragma unroll
            for (int pi = 0; pi < 2; pi++) {
                const uint32_t brow = wn * 32 + pi * 16 + (lane & 7) + ((lane >> 4) << 3);
                const uint32_t bch  = ks * 2 + ((lane >> 3) & 1);
                uint32_t v[4];
                LDSM4(v, tBh + swz(brow, bch));
                bh[2*pi][0] = v[0]; bh[2*pi][1] = v[1];
                bh[2*pi+1][0] = v[2]; bh[2*pi+1][1] = v[3];
                LDSM4(v, tBl + swz(brow, bch));
                bl[2*pi][0] = v[0]; bl[2*pi][1] = v[1];
                bl[2*pi+1][0] = v[2]; bl[2*pi+1][1] = v[3];
            }
#pragma unroll
            for (int mi = 0; mi < 4; mi++)
#pragma unroll
                for (int ni = 0; ni < 4; ni++)
                    MMA16816(acc[mi][ni], a[mi], bh[ni]);
#pragma unroll
            for (int mi = 0; mi < 4; mi++)
#pragma unroll
                for (int ni = 0; ni < 4; ni++)
                    MMA16816(acc[mi][ni], a[mi], bl[ni]);
#pragma unroll
            for (int mi = 0; mi < 4; mi++)
                LDSM4(a[mi], tAl + swz(arow + mi * 16, ach));
#pragma unroll
            for (int mi = 0; mi < 4; mi++)
#pragma unroll
                for (int ni = 0; ni < 4; ni++)
                    MMA16816(acc[mi][ni], a[mi], bh[ni]);
        }
    }

#pragma unroll
    for (int mi = 0; mi < 4; mi++) {
        const int r0 = m0 + wm * 64 + mi * 16 + (lane >> 2);
#pragma unroll
        for (int ni = 0; ni < 4; ni++) {
            const int col = n0 + wn * 32 + ni * 8 + (lane & 3) * 2;
            float b0 = 0.f, b1 = 0.f;
            if (BIAS) { b0 = __ldg(bias + col); b1 = __ldg(bias + col + 1); }
            const float x0 = acc[mi][ni][0] * scale + b0;
            const float x1 = acc[mi][ni][1] * scale + b1;
            const float x2 = acc[mi][ni][2] * scale + b0;
            const float x3 = acc[mi][ni][3] * scale + b1;
            const long long g0 = co + (long long)r0 * N + col;
            const long long g1 = co + (long long)(r0 + 8) * N + col;
            if (OM & 1) {
                *(float2*)(Cf + g0) = make_float2(x0, x1);
                *(float2*)(Cf + g1) = make_float2(x2, x3);
            }
            if (OM & 2) {
                float h0, l0, h1, l1, h2, l2, h3, l3;
                split1(x0, h0, l0); split1(x1, h1, l1);
                split1(x2, h2, l2); split1(x3, h3, l3);
                *(uint32_t*)(Ch + g0) = pack2(h0, h1);
                *(uint32_t*)(Ch + g1) = pack2(h2, h3);
                *(uint32_t*)(Cl + g0) = pack2(l0, l1);
                *(uint32_t*)(Cl + g1) = pack2(l2, l3);
            }
            if (OM & 4) {
                const long long rg0 = (long long)r0 * 2048 + resOff + col;
                const long long rg1 = (long long)(r0 + 8) * 2048 + resOff + col;
                *(float2*)(Cres + rg0) = make_float2(x0, x1);
                *(float2*)(Cres + rg1) = make_float2(x2, x3);
            }
        }
    }
}

// ---------------------------------------------------------------------------
// NN GEMM: C = A @ B, A[M,K], B[K,N] (row-major), bf16 splits; out = bf16 split.
// ---------------------------------------------------------------------------
__global__ void __launch_bounds__(256, 2) gemm_nn(
    const bf16* __restrict__ Ah, const bf16* __restrict__ Al,
    const bf16* __restrict__ Bh, const bf16* __restrict__ Bl,
    bf16* __restrict__ Ch, bf16* __restrict__ Cl,
    int M, int N, int K,
    long long sA, long long sB, long long sC)
{
    extern __shared__ char sm[];
    const uint32_t sb = smem_u32(sm);
    const int tid = threadIdx.x, lane = tid & 31, warp = tid >> 5;
    const int wm = warp >> 2, wn = warp & 3;
    const int bz = blockIdx.z;
    Ah += bz * sA;  Al += bz * sA;
    Bh += bz * sB;  Bl += bz * sB;
    const long long co = (long long)bz * sC;
    const int m0 = blockIdx.y * 128, n0 = blockIdx.x * 128;

    auto load_stage = [&](int slot, int k0){
        const uint32_t s = sb + slot * STGB;
#pragma unroll
        for (int i = 0; i < 2; i++) {
            const int c = tid + i * 256;
            const uint32_t row = c >> 2, ch = c & 3;
            const long long g = (long long)(m0 + row) * K + k0 + ch * 8;
            CP_ASYNC16(s + swz(row, ch),          Ah + g);
            CP_ASYNC16(s + TILEB + swz(row, ch),  Al + g);
        }
#pragma unroll
        for (int i = 0; i < 2; i++) {
            const int c = tid + i * 256;
            const uint32_t row = c >> 4, ch = c & 15;
            const long long g = (long long)(k0 + row) * N + n0 + ch * 8;
            CP_ASYNC16(s + 2*TILEB + swzN(row, ch), Bh + g);
            CP_ASYNC16(s + 3*TILEB + swzN(row, ch), Bl + g);
        }
    };

    const int NS = K / 32;
    load_stage(0, 0);
    asm volatile("cp.async.commit_group;" ::: "memory");
    load_stage(1, 32);
    asm volatile("cp.async.commit_group;" ::: "memory");

    float acc[4][4][4] = {};
    int slot = 0;

    for (int s = 0; s < NS; s++) {
        asm volatile("cp.async.wait_group 1;" ::: "memory");
        __syncthreads();
        if (s + 2 < NS) {
            int ns = slot + 2; if (ns >= 3) ns -= 3;
            load_stage(ns, (s + 2) * 32);
        }
        asm volatile("cp.async.commit_group;" ::: "memory");

        const uint32_t st  = sb + slot * STGB;
        const uint32_t tAh = st, tAl = st + TILEB, tBh = st + 2*TILEB, tBl = st + 3*TILEB;
        if (++slot == 3) slot = 0;

#pragma unroll
        for (int ks = 0; ks < 2; ks++) {
            uint32_t a[4][4], bh[4][2], bl[4][2];
            const uint32_t ach  = ks * 2 + (lane >> 4);
            const uint32_t arow = wm * 64 + (lane & 15);
#pragma unroll
            for (int mi = 0; mi < 4; mi++)
                LDSM4(a[mi], tAh + swz(arow + mi * 16, ach));
            const uint32_t brr = ks * 16 + (lane & 7) + (((lane >> 3) & 1) << 3);
#pragma unroll
            for (int pi = 0; pi < 2; pi++) {
                const uint32_t bcc = ((wn * 32 + pi * 16) >> 3) + (lane >> 4);
                uint32_t v[4];
                LDSM4T(v, tBh + swzN(brr, bcc));
                bh[2*pi][0] = v[0]; bh[2*pi][1] = v[1];
                bh[2*pi+1][0] = v[2]; bh[2*pi+1][1] = v[3];
                LDSM4T(v, tBl + swzN(brr, bcc));
                bl[2*pi][0] = v[0]; bl[2*pi][1] = v[1];
                bl[2*pi+1][0] = v[2]; bl[2*pi+1][1] = v[3];
            }
#pragma unroll
            for (int mi = 0; mi < 4; mi++)
#pragma unroll
                for (int ni = 0; ni < 4; ni++)
                    MMA16816(acc[mi][ni], a[mi], bh[ni]);
#pragma unroll
            for (int mi = 0; mi < 4; mi++)
#pragma unroll
                for (int ni = 0; ni < 4; ni++)
                    MMA16816(acc[mi][ni], a[mi], bl[ni]);
#pragma unroll
            for (int mi = 0; mi < 4; mi++)
                LDSM4(a[mi], tAl + swz(arow + mi * 16, ach));
#pragma unroll
            for (int mi = 0; mi < 4; mi++)
#pragma unroll
                for (int ni = 0; ni < 4; ni++)
                    MMA16816(acc[mi][ni], a[mi], bh[ni]);
        }
    }

#pragma unroll
    for (int mi = 0; mi < 4; mi++) {
        const int r0 = m0 + wm * 64 + mi * 16 + (lane >> 2);
#pragma unroll
        for (int ni = 0; ni < 4; ni++) {
            const int col = n0 + wn * 32 + ni * 8 + (lane & 3) * 2;
            const float x0 = acc[mi][ni][0], x1 = acc[mi][ni][1];
            const float x2 = acc[mi][ni][2], x3 = acc[mi][ni][3];
            const long long g0 = co + (long long)r0 * N + col;
            const long long g1 = co + (long long)(r0 + 8) * N + col;
            float h0, l0, h1, l1, h2, l2, h3, l3;
            split1(x0, h0, l0); split1(x1, h1, l1);
            split1(x2, h2, l2); split1(x3, h3, l3);
            *(uint32_t*)(Ch + g0) = pack2(h0, h1);
            *(uint32_t*)(Ch + g1) = pack2(h2, h3);
            *(uint32_t*)(Cl + g0) = pack2(l0, l1);
            *(uint32_t*)(Cl + g1) = pack2(l2, l3);
        }
    }
}

// ---------------------------------------------------------------------------
// 5-way fused projection GEMM. z==0 additionally writes fp32 res at col 0.
// ---------------------------------------------------------------------------
struct Proj5 {
    const bf16* Ah[5]; const bf16* Al[5];
    const bf16* Bh[5]; const bf16* Bl[5];
    const float* bias[5];
    float* Cf[5];
    float* res;
};

__global__ void __launch_bounds__(256, 2) proj5_k(Proj5 j)
{
    extern __shared__ char sm[];
    const uint32_t sb = smem_u32(sm);
    const int tid = threadIdx.x, lane = tid & 31, warp = tid >> 5;
    const int wm = warp >> 2, wn = warp & 3;
    const int z = blockIdx.z;
    const bf16* Ah = j.Ah[z]; const bf16* Al = j.Al[z];
    const bf16* Bh = j.Bh[z]; const bf16* Bl = j.Bl[z];
    const float* bias = j.bias[z];
    float* Cf = j.Cf[z];
    const int m0 = blockIdx.y * 128, n0 = blockIdx.x * 128;
    constexpr int K = 1024, N = 1024;

    auto load_stage = [&](int slot, int k0){
        const uint32_t s = sb + slot * STGB;
        const bf16* srcs[4] = {Ah, Al, Bh, Bl};
#pragma unroll
        for (int t = 0; t < 4; t++) {
            const bf16* src = srcs[t];
            const int rbase = (t < 2) ? m0 : n0;
#pragma unroll
            for (int i = 0; i < 2; i++) {
                const int c = tid + i * 256;
                const uint32_t row = c >> 2, ch = c & 3;
                const uint32_t dst = s + t * TILEB + swz(row, ch);
                const bf16* g = src + (long long)(rbase + row) * K + k0 + ch * 8;
                CP_ASYNC16(dst, g);
            }
        }
    };

    const int NS = K / 32;
    load_stage(0, 0);
    asm volatile("cp.async.commit_group;" ::: "memory");
    load_stage(1, 32);
    asm volatile("cp.async.commit_group;" ::: "memory");

    float acc[4][4][4] = {};
    int slot = 0;

    for (int s = 0; s < NS; s++) {
        asm volatile("cp.async.wait_group 1;" ::: "memory");
        __syncthreads();
        if (s + 2 < NS) {
            int ns = slot + 2; if (ns >= 3) ns -= 3;
            load_stage(ns, (s + 2) * 32);
        }
        asm volatile("cp.async.commit_group;" ::: "memory");

        const uint32_t st  = sb + slot * STGB;
        const uint32_t tAh = st, tAl = st + TILEB, tBh = st + 2*TILEB, tBl = st + 3*TILEB;
        if (++slot == 3) slot = 0;

#pragma unroll
        for (int ks = 0; ks < 2; ks++) {
            uint32_t a[4][4], bh[4][2], bl[4][2];
            const uint32_t ach  = ks * 2 + (lane >> 4);
            const uint32_t arow = wm * 64 + (lane & 15);
#pragma unroll
            for (int mi = 0; mi < 4; mi++)
                LDSM4(a[mi], tAh + swz(arow + mi * 16, ach));
#pragma unroll
            for (int pi = 0; pi < 2; pi++) {
                const uint32_t brow = wn * 32 + pi * 16 + (lane & 7) + ((lane >> 4) << 3);
                const uint32_t bch  = ks * 2 + ((lane >> 3) & 1);
                uint32_t v[4];
                LDSM4(v, tBh + swz(brow, bch));
                bh[2*pi][0] = v[0]; bh[2*pi][1] = v[1];
                bh[2*pi+1][0] = v[2]; bh[2*pi+1][1] = v[3];
                LDSM4(v, tBl + swz(brow, bch));
                bl[2*pi][0] = v[0]; bl[2*pi][1] = v[1];
                bl[2*pi+1][0] = v[2]; bl[2*pi+1][1] = v[3];
            }
#pragma unroll
            for (int mi = 0; mi < 4; mi++)
#pragma unroll
                for (int ni = 0; ni < 4; ni++)
                    MMA16816(acc[mi][ni], a[mi], bh[ni]);
#pragma unroll
            for (int mi = 0; mi < 4; mi++)
#pragma unroll
                for (int ni = 0; ni < 4; ni++)
                    MMA16816(acc[mi][ni], a[mi], bl[ni]);
#pragma unroll
            for (int mi = 0; mi < 4; mi++)
                LDSM4(a[mi], tAl + swz(arow + mi * 16, ach));
#pragma unroll
            for (int mi = 0; mi < 4; mi++)
#pragma unroll
                for (int ni = 0; ni < 4; ni++)
                    MMA16816(acc[mi][ni], a[mi], bh[ni]);
        }
    }

    const bool doRes = (z == 0);
#pragma unroll
    for (int mi = 0; mi < 4; mi++) {
        const int r0 = m0 + wm * 64 + mi * 16 + (lane >> 2);
#pragma unroll
        for (int ni = 0; ni < 4; ni++) {
            const int col = n0 + wn * 32 + ni * 8 + (lane & 3) * 2;
            const float b0 = __ldg(bias + col), b1 = __ldg(bias + col + 1);
            const float x0 = acc[mi][ni][0] + b0;
            const float x1 = acc[mi][ni][1] + b1;
            const float x2 = acc[mi][ni][2] + b0;
            const float x3 = acc[mi][ni][3] + b1;
            const long long g0 = (long long)r0 * N + col;
            const long long g1 = (long long)(r0 + 8) * N + col;
            *(float2*)(Cf + g0) = make_float2(x0, x1);
            *(float2*)(Cf + g1) = make_float2(x2, x3);
            if (doRes) {
                *(float2*)(j.res + (long long)r0 * 2048 + col)       = make_float2(x0, x1);
                *(float2*)(j.res + (long long)(r0 + 8) * 2048 + col) = make_float2(x2, x3);
            }
        }
    }
}

// ---------------------------------------------------------------------------
struct Split3 { const float* x[3]; bf16* h[3]; bf16* l[3]; };

__global__ void __launch_bounds__(256) split3_k(Split3 j)
{
    const int z = blockIdx.y;
    const float* x = j.x[z];
    bf16* h = j.h[z]; bf16* l = j.l[z];
    const long long i = ((long long)blockIdx.x * 256 + threadIdx.x) * 4;
    const float4 v = *(const float4*)(x + i);
    float h0,l0,h1,l1,h2,l2,h3,l3;
    split1(v.x,h0,l0); split1(v.y,h1,l1); split1(v.z,h2,l2); split1(v.w,h3,l3);
    uint2 hp, lp;
    hp.x = pack2(h0,h1); hp.y = pack2(h2,h3);
    lp.x = pack2(l0,l1); lp.y = pack2(l2,l3);
    *(uint2*)(h + i) = hp;
    *(uint2*)(l + i) = lp;
}

struct W8 { const float* w[8]; bf16* th[8]; bf16* tl[8]; };

__global__ void __launch_bounds__(256) tspw_k(W8 j)
{
    __shared__ float t[32][33];
    const int z = blockIdx.z;
    const float* X = j.w[z];
    bf16* Th = j.th[z]; bf16* Tl = j.tl[z];
    const int c0 = blockIdx.x * 32, r0 = blockIdx.y * 32;
    const int tx = threadIdx.x, ty = threadIdx.y;
#pragma unroll
    for (int i = 0; i < 4; i++)
        t[ty + i * 8][tx] = X[(long long)(r0 + ty + i * 8) * 1024 + c0 + tx];
    __syncthreads();
#pragma unroll
    for (int i = 0; i < 4; i++) {
        const float v = t[tx][ty + i * 8];
        float h, l; split1(v, h, l);
        const long long g = (long long)(c0 + ty + i * 8) * 1024 + r0 + tx;
        Th[g] = __float2bfloat16(h);
        Tl[g] = __float2bfloat16(l);
    }
}

// ---------------------------------------------------------------------------
struct LN3 {
    const float* x[3]; const float* g[3]; const float* b[3];
    bf16* yh[3]; bf16* yl[3];
};

__global__ void __launch_bounds__(256) ln3_k(LN3 j)
{
    const int z = blockIdx.y;
    const float* x = j.x[z];
    const long long row = blockIdx.x;
    const float4 v = ((const float4*)(x + row * 1024))[threadIdx.x];

    float s  = v.x + v.y + v.z + v.w;
    float s2 = v.x*v.x + v.y*v.y + v.z*v.z + v.w*v.w;
    __shared__ float sh[8], sh2[8];
#pragma unroll
    for (int o = 16; o > 0; o >>= 1) {
        s  += __shfl_xor_sync(0xffffffffu, s, o);
        s2 += __shfl_xor_sync(0xffffffffu, s2, o);
    }
    const int lane = threadIdx.x & 31, warp = threadIdx.x >> 5;
    if (lane == 0) { sh[warp] = s; sh2[warp] = s2; }
    __syncthreads();
    float S = 0.f, S2 = 0.f;
#pragma unroll
    for (int i = 0; i < 8; i++) { S += sh[i]; S2 += sh2[i]; }
    const float mean = S * (1.0f / 1024.0f);
    const float var  = S2 * (1.0f / 1024.0f) - mean * mean;
    const float inv  = rsqrtf(var + 1e-6f);

    const float4 gg = ((const float4*)j.g[z])[threadIdx.x];
    const float4 bb = ((const float4*)j.b[z])[threadIdx.x];
    float4 o;
    o.x = (v.x - mean) * inv * gg.x + bb.x;
    o.y = (v.y - mean) * inv * gg.y + bb.y;
    o.z = (v.z - mean) * inv * gg.z + bb.z;
    o.w = (v.w - mean) * inv * gg.w + bb.w;
    float h0,l0,h1,l1,h2,l2,h3,l3;
    split1(o.x,h0,l0); split1(o.y,h1,l1); split1(o.z,h2,l2); split1(o.w,h3,l3);
    uint2 hp, lp;
    hp.x = pack2(h0,h1); hp.y = pack2(h2,h3);
    lp.x = pack2(l0,l1); lp.y = pack2(l2,l3);
    ((uint2*)(j.yh[z] + row * 1024))[threadIdx.x] = hp;
    ((uint2*)(j.yl[z] + row * 1024))[threadIdx.x] = lp;
}

// ---------------------------------------------------------------------------
template<bool F32OUT>
__global__ void __launch_bounds__(256) softmax_k(
    float* __restrict__ S, bf16* __restrict__ Ph, bf16* __restrict__ Pl)
{
    const long long row = blockIdx.x;
    float* r = S + row * 2048;
    const int base = threadIdx.x * 8;

    float v[8];
    float4 a = *(const float4*)(r + base);
    float4 c = *(const float4*)(r + base + 4);
    v[0]=a.x; v[1]=a.y; v[2]=a.z; v[3]=a.w; v[4]=c.x; v[5]=c.y; v[6]=c.z; v[7]=c.w;

    float mx = v[0];
#pragma unroll
    for (int i = 1; i < 8; i++) mx = fmaxf(mx, v[i]);
    __shared__ float shm[8], shs[8];
#pragma unroll
    for (int o = 16; o > 0; o >>= 1) mx = fmaxf(mx, __shfl_xor_sync(0xffffffffu, mx, o));
    const int lane = threadIdx.x & 31, warp = threadIdx.x >> 5;
    if (lane == 0) shm[warp] = mx;
    __syncthreads();
    float M = shm[0];
#pragma unroll
    for (int i = 1; i < 8; i++) M = fmaxf(M, shm[i]);

    float sum = 0.f;
#pragma unroll
    for (int i = 0; i < 8; i++) { v[i] = __expf(v[i] - M); sum += v[i]; }
#pragma unroll
    for (int o = 16; o > 0; o >>= 1) sum += __shfl_xor_sync(0xffffffffu, sum, o);
    if (lane == 0) shs[warp] = sum;
    __syncthreads();
    float T = 0.f;
#pragma unroll
    for (int i = 0; i < 8; i++) T += shs[i];
    const float inv = 1.0f / T;

    uint4 hp, lp;
    float p0,p1,h0,l0,h1,l1;
    p0 = v[0]*inv; p1 = v[1]*inv; split1(p0,h0,l0); split1(p1,h1,l1);
    hp.x = pack2(h0,h1); lp.x = pack2(l0,l1); a.x = p0; a.y = p1;
    p0 = v[2]*inv; p1 = v[3]*inv; split1(p0,h0,l0); split1(p1,h1,l1);
    hp.y = pack2(h0,h1); lp.y = pack2(l0,l1); a.z = p0; a.w = p1;
    p0 = v[4]*inv; p1 = v[5]*inv; split1(p0,h0,l0); split1(p1,h1,l1);
    hp.z = pack2(h0,h1); lp.z = pack2(l0,l1); c.x = p0; c.y = p1;
    p0 = v[6]*inv; p1 = v[7]*inv; split1(p0,h0,l0); split1(p1,h1,l1);
    hp.w = pack2(h0,h1); lp.w = pack2(l0,l1); c.z = p0; c.w = p1;

    *(uint4*)(Ph + row * 2048 + base) = hp;
    *(uint4*)(Pl + row * 2048 + base) = lp;
    if (F32OUT) {
        *(float4*)(r + base)     = a;
        *(float4*)(r + base + 4) = c;
    }
}

// ---------------------------------------------------------------------------
extern "C" void kernel_launch(void* const* d_in, const int* in_sizes, int n_in,
                              void* d_out, int out_size)
{
    const float* q = (const float*)d_in[0];
    const float* k = (const float*)d_in[1];
    const float* v = (const float*)d_in[2];
    const float* W[8]  = {(const float*)d_in[3],  (const float*)d_in[5],
                          (const float*)d_in[7],  (const float*)d_in[9],
                          (const float*)d_in[11], (const float*)d_in[13],
                          (const float*)d_in[15], (const float*)d_in[17]};
    const float* bW[8] = {(const float*)d_in[4],  (const float*)d_in[6],
                          (const float*)d_in[8],  (const float*)d_in[10],
                          (const float*)d_in[12], (const float*)d_in[14],
                          (const float*)d_in[16], (const float*)d_in[18]};
    const float* gq1 = (const float*)d_in[19]; const float* Bq1 = (const float*)d_in[20];
    const float* gk1 = (const float*)d_in[21]; const float* Bk1 = (const float*)d_in[22];
    const float* gv1 = (const float*)d_in[23]; const float* Bv1 = (const float*)d_in[24];
    const float* gq2 = (const float*)d_in[25]; const float* Bq2 = (const float*)d_in[26];
    const float* gk2 = (const float*)d_in[27]; const float* Bk2 = (const float*)d_in[28];
    const float* gv2 = (const float*)d_in[29]; const float* Bv2 = (const float*)d_in[30];

    float* out = (float*)d_out;
    float* res = out + SZB;
    float* a2  = res + SSB;

    float* buf = nullptr;
    cudaGetSymbolAddress((void**)&buf, g_buf);
    char* P = (char*)buf;
    auto takeB = [&](long long bytes){ char* r = P; P += bytes; return r; };
    bf16* q_h  = (bf16*)takeB(SZB*2); bf16* q_l  = (bf16*)takeB(SZB*2);
    bf16* k_h  = (bf16*)takeB(SZB*2); bf16* k_l  = (bf16*)takeB(SZB*2);
    bf16* v_h  = (bf16*)takeB(SZB*2); bf16* v_l  = (bf16*)takeB(SZB*2);
    float* q1b = (float*)takeB(SZB*4);
    float* kb  = (float*)takeB(SZB*4);
    float* vb  = (float*)takeB(SZB*4);
    float* k2b = (float*)takeB(SZB*4);
    float* v2b = (float*)takeB(SZB*4);
    float* q2b = (float*)takeB(SZB*4);
    bf16* nq_h = (bf16*)takeB(SZB*2); bf16* nq_l = (bf16*)takeB(SZB*2);
    bf16* nk_h = (bf16*)takeB(SZB*2); bf16* nk_l = (bf16*)takeB(SZB*2);
    bf16* nv_h = (bf16*)takeB(SZB*2); bf16* nv_l = (bf16*)takeB(SZB*2);
    bf16* oa_h = (bf16*)takeB(SZB*2); bf16* oa_l = (bf16*)takeB(SZB*2);
    bf16* o1_h = (bf16*)takeB(SZB*2); bf16* o1_l = (bf16*)takeB(SZB*2);
    float* Sbuf= (float*)takeB(SSB*4);
    bf16* P_h  = (bf16*)takeB(SSB*2); bf16* P_l  = (bf16*)takeB(SSB*2);
    bf16* WTp  = (bf16*)takeB(8ll * 2 * WSZ * 2);
    auto WTh = [&](int i){ return WTp + (long long)i * 2 * WSZ; };
    auto WTl = [&](int i){ return WTp + (long long)i * 2 * WSZ + WSZ; };

    cudaFuncSetAttribute(gemm_bf3<1,true >, cudaFuncAttributeMaxDynamicSharedMemorySize, SMEMB);
    cudaFuncSetAttribute(gemm_bf3<1,false>, cudaFuncAttributeMaxDynamicSharedMemorySize, SMEMB);
    cudaFuncSetAttribute(gemm_bf3<2,true >, cudaFuncAttributeMaxDynamicSharedMemorySize, SMEMB);
    cudaFuncSetAttribute(gemm_bf3<5,true >, cudaFuncAttributeMaxDynamicSharedMemorySize, SMEMB);
    cudaFuncSetAttribute(gemm_nn,           cudaFuncAttributeMaxDynamicSharedMemorySize, SMEMB);
    cudaFuncSetAttribute(proj5_k,           cudaFuncAttributeMaxDynamicSharedMemorySize, SMEMB);

    const dim3 tb(32, 8);
    const dim3 gproj(8, 64, 1);
    const dim3 gproj5(8, 64, 5);
    const dim3 gS(16, 16, 4);
    const dim3 gO(8, 16, 4);
    const float it = 1.0f / 32.0f;
    const long long sLD = 2048ll*1024, sLL = 2048ll*2048;

    // prep
    Split3 s3;
    s3.x[0] = q; s3.h[0] = q_h; s3.l[0] = q_l;
    s3.x[1] = k; s3.h[1] = k_h; s3.l[1] = k_l;
    s3.x[2] = v; s3.h[2] = v_h; s3.l[2] = v_l;
    split3_k<<<dim3(SZB/4/256, 3), 256>>>(s3);
    W8 w8;
    for (int i = 0; i < 8; i++) { w8.w[i] = W[i]; w8.th[i] = WTh(i); w8.tl[i] = WTl(i); }
    tspw_k<<<dim3(32,32,8), tb>>>(w8);

    // all 5 input-dependent projections in one launch
    Proj5 p5;
    p5.Ah[0]=q_h; p5.Al[0]=q_l; p5.Bh[0]=WTh(0); p5.Bl[0]=WTl(0); p5.bias[0]=bW[0]; p5.Cf[0]=q1b;
    p5.Ah[1]=k_h; p5.Al[1]=k_l; p5.Bh[1]=WTh(1); p5.Bl[1]=WTl(1); p5.bias[1]=bW[1]; p5.Cf[1]=kb;
    p5.Ah[2]=v_h; p5.Al[2]=v_l; p5.Bh[2]=WTh(2); p5.Bl[2]=WTl(2); p5.bias[2]=bW[2]; p5.Cf[2]=vb;
    p5.Ah[3]=k_h; p5.Al[3]=k_l; p5.Bh[3]=WTh(5); p5.Bl[3]=WTl(5); p5.bias[3]=bW[5]; p5.Cf[3]=k2b;
    p5.Ah[4]=v_h; p5.Al[4]=v_l; p5.Bh[4]=WTh(6); p5.Bl[4]=WTl(6); p5.bias[4]=bW[6]; p5.Cf[4]=v2b;
    p5.res = res;
    proj5_k<<<gproj5, 256, SMEMB>>>(p5);

    // ---------------- layer 1 ----------------
    LN3 l1;
    l1.x[0]=q1b; l1.g[0]=gq1; l1.b[0]=Bq1; l1.yh[0]=nq_h; l1.yl[0]=nq_l;
    l1.x[1]=kb;  l1.g[1]=gk1; l1.b[1]=Bk1; l1.yh[1]=nk_h; l1.yl[1]=nk_l;
    l1.x[2]=vb;  l1.g[2]=gv1; l1.b[2]=Bv1; l1.yh[2]=nv_h; l1.yl[2]=nv_l;
    ln3_k<<<dim3(8192,3), 256>>>(l1);

    gemm_bf3<1,false><<<gS,256,SMEMB>>>(nq_h,nq_l, nk_h,nk_l, 0, Sbuf,0,0, 0,0, 2048,2048,1024, it, sLD,sLD,sLL);
    softmax_k<false><<<8192,256>>>(Sbuf, P_h, P_l);
    gemm_nn<<<gO,256,SMEMB>>>(P_h,P_l, nv_h,nv_l, oa_h,oa_l, 2048,1024,2048, sLL,sLD,sLD);
    gemm_bf3<2,true ><<<gproj,256,SMEMB>>>(oa_h,oa_l, WTh(3),WTl(3), bW[3], 0,o1_h,o1_l, 0,0, 8192,1024,1024, 1.f, 0,0,0);
    gemm_bf3<5,true ><<<gproj,256,SMEMB>>>(o1_h,o1_l, WTh(4),WTl(4), bW[4], q2b,0,0, res,1024, 8192,1024,1024, 1.f, 0,0,0);

    // ---------------- layer 2 ----------------
    LN3 l2;
    l2.x[0]=q2b; l2.g[0]=gq2; l2.b[0]=Bq2; l2.yh[0]=nq_h; l2.yl[0]=nq_l;
    l2.x[1]=k2b; l2.g[1]=gk2; l2.b[1]=Bk2; l2.yh[1]=nk_h; l2.yl[1]=nk_l;
    l2.x[2]=v2b; l2.g[2]=gv2; l2.b[2]=Bv2; l2.yh[2]=nv_h; l2.yl[2]=nv_l;
    ln3_k<<<dim3(8192,3), 256>>>(l2);

    gemm_bf3<1,false><<<gS,256,SMEMB>>>(nq_h,nq_l, nk_h,nk_l, 0, a2,0,0, 0,0, 2048,2048,1024, it, sLD,sLD,sLL);
    softmax_k<true><<<8192,256>>>(a2, P_h, P_l);
    gemm_nn<<<gO,256,SMEMB>>>(P_h,P_l, nv_h,nv_l, oa_h,oa_l, 2048,1024,2048, sLL,sLD,sLD);
    gemm_bf3<1,true ><<<gproj,256,SMEMB>>>(oa_h,oa_l, WTh(7),WTl(7), bW[7], out,0,0, 0,0, 8192,1024,1024, 1.f, 0,0,0);
}

// round 10
// speedup vs baseline: 1.3729x; 1.0537x over previous
#include <cuda_runtime.h>
#include <cuda_bf16.h>
#include <cstdint>

// ---------------------------------------------------------------------------
// B=4, L=2048, D=1024, fp32. Outputs: out(8.39M) | res(16.78M) | a2(16.78M).
// GEMMs via legacy mma.sync bf16, 2-term bf16 split (3 products).
// R9 = R8 + warp-per-row LayerNorm (no barriers, pure shfl reduction).
// ---------------------------------------------------------------------------

#define SZB 8388608ll
#define SSB 16777216ll
#define WSZ 1048576ll

__device__ float g_buf[160000000ull];   // 640MB scratch pool

using bf16 = __nv_bfloat16;

__device__ __forceinline__ uint32_t smem_u32(const void* p){
    uint32_t a;
    asm("{ .reg .u64 t; cvta.to.shared.u64 t, %1; cvt.u32.u64 %0, t; }" : "=r"(a) : "l"(p));
    return a;
}
__device__ __forceinline__ uint32_t pack2(float x, float y){
    __nv_bfloat162 t = __floats2bfloat162_rn(x, y);
    return *(uint32_t*)&t;
}
__device__ __forceinline__ void split1(float x, float& h, float& l){
    h = __bfloat162float(__float2bfloat16(x));
    l = x - h;
}
// swizzled byte offset within a 128-row x 64B tile (A tiles, NT B tiles)
__device__ __forceinline__ uint32_t swz(uint32_t r, uint32_t c){
    return r * 64 + (((c ^ (r >> 1)) & 3) << 4) + (c & ~3u) * 16;
}
// swizzled byte offset within a 32-row x 256B tile (NN B tiles)
__device__ __forceinline__ uint32_t swzN(uint32_t r, uint32_t c){
    return r * 256 + ((c ^ (r & 7)) << 4);
}

#define LDSM4(R, addr) \
    asm volatile("ldmatrix.sync.aligned.m8n8.x4.shared.b16 {%0,%1,%2,%3}, [%4];" \
        : "=r"((R)[0]), "=r"((R)[1]), "=r"((R)[2]), "=r"((R)[3]) : "r"(addr))

#define LDSM4T(R, addr) \
    asm volatile("ldmatrix.sync.aligned.m8n8.x4.trans.shared.b16 {%0,%1,%2,%3}, [%4];" \
        : "=r"((R)[0]), "=r"((R)[1]), "=r"((R)[2]), "=r"((R)[3]) : "r"(addr))

#define MMA16816(d, a, b) \
    asm volatile("mma.sync.aligned.m16n8k16.row.col.f32.bf16.bf16.f32 " \
        "{%0,%1,%2,%3}, {%4,%5,%6,%7}, {%8,%9}, {%0,%1,%2,%3};" \
        : "+f"((d)[0]), "+f"((d)[1]), "+f"((d)[2]), "+f"((d)[3]) \
        : "r"((a)[0]), "r"((a)[1]), "r"((a)[2]), "r"((a)[3]), "r"((b)[0]), "r"((b)[1]))

#define CP_ASYNC16(dst, src) \
    asm volatile("cp.async.cg.shared.global [%0], [%1], 16;" :: "r"(dst), "l"(src))

constexpr int TILEB = 128 * 64;           // 8192 bytes (also 32x256 for NN B)
constexpr int STGB  = 4 * TILEB;          // 32768
constexpr int SMEMB = 3 * STGB;           // 98304

// ---------------------------------------------------------------------------
// NT GEMM: C = scale*(A @ B^T)(+bias). A[M,K], B[N,K] bf16 splits.
// OM bit0: fp32 C; bit1: bf16 split out; bit2: fp32 res write.
// ---------------------------------------------------------------------------
template<int OM, bool BIAS>
__global__ void __launch_bounds__(256, 2) gemm_bf3(
    const bf16* __restrict__ Ah, const bf16* __restrict__ Al,
    const bf16* __restrict__ Bh, const bf16* __restrict__ Bl,
    const float* __restrict__ bias,
    float* __restrict__ Cf, bf16* __restrict__ Ch, bf16* __restrict__ Cl,
    float* __restrict__ Cres, int resOff,
    int M, int N, int K, float scale,
    long long sA, long long sB, long long sC)
{
    extern __shared__ char sm[];
    const uint32_t sb = smem_u32(sm);
    const int tid = threadIdx.x, lane = tid & 31, warp = tid >> 5;
    const int wm = warp >> 2, wn = warp & 3;
    const int bz = blockIdx.z;
    Ah += bz * sA;  Al += bz * sA;
    Bh += bz * sB;  Bl += bz * sB;
    const long long co = (long long)bz * sC;
    const int m0 = blockIdx.y * 128, n0 = blockIdx.x * 128;

    auto load_stage = [&](int slot, int k0){
        const uint32_t s = sb + slot * STGB;
        const bf16* srcs[4] = {Ah, Al, Bh, Bl};
#pragma unroll
        for (int t = 0; t < 4; t++) {
            const bf16* src = srcs[t];
            const int rbase = (t < 2) ? m0 : n0;
#pragma unroll
            for (int i = 0; i < 2; i++) {
                const int c = tid + i * 256;
                const uint32_t row = c >> 2, ch = c & 3;
                const uint32_t dst = s + t * TILEB + swz(row, ch);
                const bf16* g = src + (long long)(rbase + row) * K + k0 + ch * 8;
                CP_ASYNC16(dst, g);
            }
        }
    };

    const int NS = K / 32;
    load_stage(0, 0);
    asm volatile("cp.async.commit_group;" ::: "memory");
    load_stage(1, 32);
    asm volatile("cp.async.commit_group;" ::: "memory");

    float acc[4][4][4] = {};
    int slot = 0;

    for (int s = 0; s < NS; s++) {
        asm volatile("cp.async.wait_group 1;" ::: "memory");
        __syncthreads();
        if (s + 2 < NS) {
            int ns = slot + 2; if (ns >= 3) ns -= 3;
            load_stage(ns, (s + 2) * 32);
        }
        asm volatile("cp.async.commit_group;" ::: "memory");

        const uint32_t st  = sb + slot * STGB;
        const uint32_t tAh = st, tAl = st + TILEB, tBh = st + 2*TILEB, tBl = st + 3*TILEB;
        if (++slot == 3) slot = 0;

#pragma unroll
        for (int ks = 0; ks < 2; ks++) {
            uint32_t a[4][4], bh[4][2], bl[4][2];
            const uint32_t ach  = ks * 2 + (lane >> 4);
            const uint32_t arow = wm * 64 + (lane & 15);
#pragma unroll
            for (int mi = 0; mi < 4; mi++)
                LDSM4(a[mi], tAh + swz(arow + mi * 16, ach));
#pragma unroll
            for (int pi = 0; pi < 2; pi++) {
                const uint32_t brow = wn * 32 + pi * 16 + (lane & 7) + ((lane >> 4) << 3);
                const uint32_t bch  = ks * 2 + ((lane >> 3) & 1);
                uint32_t v[4];
                LDSM4(v, tBh + swz(brow, bch));
                bh[2*pi][0] = v[0]; bh[2*pi][1] = v[1];
                bh[2*pi+1][0] = v[2]; bh[2*pi+1][1] = v[3];
                LDSM4(v, tBl + swz(brow, bch));
                bl[2*pi][0] = v[0]; bl[2*pi][1] = v[1];
                bl[2*pi+1][0] = v[2]; bl[2*pi+1][1] = v[3];
            }
#pragma unroll
            for (int mi = 0; mi < 4; mi++)
#pragma unroll
                for (int ni = 0; ni < 4; ni++)
                    MMA16816(acc[mi][ni], a[mi], bh[ni]);
#pragma unroll
            for (int mi = 0; mi < 4; mi++)
#pragma unroll
                for (int ni = 0; ni < 4; ni++)
                    MMA16816(acc[mi][ni], a[mi], bl[ni]);
#pragma unroll
            for (int mi = 0; mi < 4; mi++)
                LDSM4(a[mi], tAl + swz(arow + mi * 16, ach));
#pragma unroll
            for (int mi = 0; mi < 4; mi++)
#pragma unroll
                for (int ni = 0; ni < 4; ni++)
                    MMA16816(acc[mi][ni], a[mi], bh[ni]);
        }
    }

#pragma unroll
    for (int mi = 0; mi < 4; mi++) {
        const int r0 = m0 + wm * 64 + mi * 16 + (lane >> 2);
#pragma unroll
        for (int ni = 0; ni < 4; ni++) {
            const int col = n0 + wn * 32 + ni * 8 + (lane & 3) * 2;
            float b0 = 0.f, b1 = 0.f;
            if (BIAS) { b0 = __ldg(bias + col); b1 = __ldg(bias + col + 1); }
            const float x0 = acc[mi][ni][0] * scale + b0;
            const float x1 = acc[mi][ni][1] * scale + b1;
            const float x2 = acc[mi][ni][2] * scale + b0;
            const float x3 = acc[mi][ni][3] * scale + b1;
            const long long g0 = co + (long long)r0 * N + col;
            const long long g1 = co + (long long)(r0 + 8) * N + col;
            if (OM & 1) {
                *(float2*)(Cf + g0) = make_float2(x0, x1);
                *(float2*)(Cf + g1) = make_float2(x2, x3);
            }
            if (OM & 2) {
                float h0, l0, h1, l1, h2, l2, h3, l3;
                split1(x0, h0, l0); split1(x1, h1, l1);
                split1(x2, h2, l2); split1(x3, h3, l3);
                *(uint32_t*)(Ch + g0) = pack2(h0, h1);
                *(uint32_t*)(Ch + g1) = pack2(h2, h3);
                *(uint32_t*)(Cl + g0) = pack2(l0, l1);
                *(uint32_t*)(Cl + g1) = pack2(l2, l3);
            }
            if (OM & 4) {
                const long long rg0 = (long long)r0 * 2048 + resOff + col;
                const long long rg1 = (long long)(r0 + 8) * 2048 + resOff + col;
                *(float2*)(Cres + rg0) = make_float2(x0, x1);
                *(float2*)(Cres + rg1) = make_float2(x2, x3);
            }
        }
    }
}

// ---------------------------------------------------------------------------
// NN GEMM: C = A @ B, A[M,K], B[K,N] (row-major), bf16 splits; out = bf16 split.
// ---------------------------------------------------------------------------
__global__ void __launch_bounds__(256, 2) gemm_nn(
    const bf16* __restrict__ Ah, const bf16* __restrict__ Al,
    const bf16* __restrict__ Bh, const bf16* __restrict__ Bl,
    bf16* __restrict__ Ch, bf16* __restrict__ Cl,
    int M, int N, int K,
    long long sA, long long sB, long long sC)
{
    extern __shared__ char sm[];
    const uint32_t sb = smem_u32(sm);
    const int tid = threadIdx.x, lane = tid & 31, warp = tid >> 5;
    const int wm = warp >> 2, wn = warp & 3;
    const int bz = blockIdx.z;
    Ah += bz * sA;  Al += bz * sA;
    Bh += bz * sB;  Bl += bz * sB;
    const long long co = (long long)bz * sC;
    const int m0 = blockIdx.y * 128, n0 = blockIdx.x * 128;

    auto load_stage = [&](int slot, int k0){
        const uint32_t s = sb + slot * STGB;
#pragma unroll
        for (int i = 0; i < 2; i++) {
            const int c = tid + i * 256;
            const uint32_t row = c >> 2, ch = c & 3;
            const long long g = (long long)(m0 + row) * K + k0 + ch * 8;
            CP_ASYNC16(s + swz(row, ch),          Ah + g);
            CP_ASYNC16(s + TILEB + swz(row, ch),  Al + g);
        }
#pragma unroll
        for (int i = 0; i < 2; i++) {
            const int c = tid + i * 256;
            const uint32_t row = c >> 4, ch = c & 15;
            const long long g = (long long)(k0 + row) * N + n0 + ch * 8;
            CP_ASYNC16(s + 2*TILEB + swzN(row, ch), Bh + g);
            CP_ASYNC16(s + 3*TILEB + swzN(row, ch), Bl + g);
        }
    };

    const int NS = K / 32;
    load_stage(0, 0);
    asm volatile("cp.async.commit_group;" ::: "memory");
    load_stage(1, 32);
    asm volatile("cp.async.commit_group;" ::: "memory");

    float acc[4][4][4] = {};
    int slot = 0;

    for (int s = 0; s < NS; s++) {
        asm volatile("cp.async.wait_group 1;" ::: "memory");
        __syncthreads();
        if (s + 2 < NS) {
            int ns = slot + 2; if (ns >= 3) ns -= 3;
            load_stage(ns, (s + 2) * 32);
        }
        asm volatile("cp.async.commit_group;" ::: "memory");

        const uint32_t st  = sb + slot * STGB;
        const uint32_t tAh = st, tAl = st + TILEB, tBh = st + 2*TILEB, tBl = st + 3*TILEB;
        if (++slot == 3) slot = 0;

#pragma unroll
        for (int ks = 0; ks < 2; ks++) {
            uint32_t a[4][4], bh[4][2], bl[4][2];
            const uint32_t ach  = ks * 2 + (lane >> 4);
            const uint32_t arow = wm * 64 + (lane & 15);
#pragma unroll
            for (int mi = 0; mi < 4; mi++)
                LDSM4(a[mi], tAh + swz(arow + mi * 16, ach));
            const uint32_t brr = ks * 16 + (lane & 7) + (((lane >> 3) & 1) << 3);
#pragma unroll
            for (int pi = 0; pi < 2; pi++) {
                const uint32_t bcc = ((wn * 32 + pi * 16) >> 3) + (lane >> 4);
                uint32_t v[4];
                LDSM4T(v, tBh + swzN(brr, bcc));
                bh[2*pi][0] = v[0]; bh[2*pi][1] = v[1];
                bh[2*pi+1][0] = v[2]; bh[2*pi+1][1] = v[3];
                LDSM4T(v, tBl + swzN(brr, bcc));
                bl[2*pi][0] = v[0]; bl[2*pi][1] = v[1];
                bl[2*pi+1][0] = v[2]; bl[2*pi+1][1] = v[3];
            }
#pragma unroll
            for (int mi = 0; mi < 4; mi++)
#pragma unroll
                for (int ni = 0; ni < 4; ni++)
                    MMA16816(acc[mi][ni], a[mi], bh[ni]);
#pragma unroll
            for (int mi = 0; mi < 4; mi++)
#pragma unroll
                for (int ni = 0; ni < 4; ni++)
                    MMA16816(acc[mi][ni], a[mi], bl[ni]);
#pragma unroll
            for (int mi = 0; mi < 4; mi++)
                LDSM4(a[mi], tAl + swz(arow + mi * 16, ach));
#pragma unroll
            for (int mi = 0; mi < 4; mi++)
#pragma unroll
                for (int ni = 0; ni < 4; ni++)
                    MMA16816(acc[mi][ni], a[mi], bh[ni]);
        }
    }

#pragma unroll
    for (int mi = 0; mi < 4; mi++) {
        const int r0 = m0 + wm * 64 + mi * 16 + (lane >> 2);
#pragma unroll
        for (int ni = 0; ni < 4; ni++) {
            const int col = n0 + wn * 32 + ni * 8 + (lane & 3) * 2;
            const float x0 = acc[mi][ni][0], x1 = acc[mi][ni][1];
            const float x2 = acc[mi][ni][2], x3 = acc[mi][ni][3];
            const long long g0 = co + (long long)r0 * N + col;
            const long long g1 = co + (long long)(r0 + 8) * N + col;
            float h0, l0, h1, l1, h2, l2, h3, l3;
            split1(x0, h0, l0); split1(x1, h1, l1);
            split1(x2, h2, l2); split1(x3, h3, l3);
            *(uint32_t*)(Ch + g0) = pack2(h0, h1);
            *(uint32_t*)(Ch + g1) = pack2(h2, h3);
            *(uint32_t*)(Cl + g0) = pack2(l0, l1);
            *(uint32_t*)(Cl + g1) = pack2(l2, l3);
        }
    }
}

// ---------------------------------------------------------------------------
// 5-way fused projection GEMM. z==0 additionally writes fp32 res at col 0.
// ---------------------------------------------------------------------------
struct Proj5 {
    const bf16* Ah[5]; const bf16* Al[5];
    const bf16* Bh[5]; const bf16* Bl[5];
    const float* bias[5];
    float* Cf[5];
    float* res;
};

__global__ void __launch_bounds__(256, 2) proj5_k(Proj5 j)
{
    extern __shared__ char sm[];
    const uint32_t sb = smem_u32(sm);
    const int tid = threadIdx.x, lane = tid & 31, warp = tid >> 5;
    const int wm = warp >> 2, wn = warp & 3;
    const int z = blockIdx.z;
    const bf16* Ah = j.Ah[z]; const bf16* Al = j.Al[z];
    const bf16* Bh = j.Bh[z]; const bf16* Bl = j.Bl[z];
    const float* bias = j.bias[z];
    float* Cf = j.Cf[z];
    const int m0 = blockIdx.y * 128, n0 = blockIdx.x * 128;
    constexpr int K = 1024, N = 1024;

    auto load_stage = [&](int slot, int k0){
        const uint32_t s = sb + slot * STGB;
        const bf16* srcs[4] = {Ah, Al, Bh, Bl};
#pragma unroll
        for (int t = 0; t < 4; t++) {
            const bf16* src = srcs[t];
            const int rbase = (t < 2) ? m0 : n0;
#pragma unroll
            for (int i = 0; i < 2; i++) {
                const int c = tid + i * 256;
                const uint32_t row = c >> 2, ch = c & 3;
                const uint32_t dst = s + t * TILEB + swz(row, ch);
                const bf16* g = src + (long long)(rbase + row) * K + k0 + ch * 8;
                CP_ASYNC16(dst, g);
            }
        }
    };

    const int NS = K / 32;
    load_stage(0, 0);
    asm volatile("cp.async.commit_group;" ::: "memory");
    load_stage(1, 32);
    asm volatile("cp.async.commit_group;" ::: "memory");

    float acc[4][4][4] = {};
    int slot = 0;

    for (int s = 0; s < NS; s++) {
        asm volatile("cp.async.wait_group 1;" ::: "memory");
        __syncthreads();
        if (s + 2 < NS) {
            int ns = slot + 2; if (ns >= 3) ns -= 3;
            load_stage(ns, (s + 2) * 32);
        }
        asm volatile("cp.async.commit_group;" ::: "memory");

        const uint32_t st  = sb + slot * STGB;
        const uint32_t tAh = st, tAl = st + TILEB, tBh = st + 2*TILEB, tBl = st + 3*TILEB;
        if (++slot == 3) slot = 0;

#pragma unroll
        for (int ks = 0; ks < 2; ks++) {
            uint32_t a[4][4], bh[4][2], bl[4][2];
            const uint32_t ach  = ks * 2 + (lane >> 4);
            const uint32_t arow = wm * 64 + (lane & 15);
#pragma unroll
            for (int mi = 0; mi < 4; mi++)
                LDSM4(a[mi], tAh + swz(arow + mi * 16, ach));
#pragma unroll
            for (int pi = 0; pi < 2; pi++) {
                const uint32_t brow = wn * 32 + pi * 16 + (lane & 7) + ((lane >> 4) << 3);
                const uint32_t bch  = ks * 2 + ((lane >> 3) & 1);
                uint32_t v[4];
                LDSM4(v, tBh + swz(brow, bch));
                bh[2*pi][0] = v[0]; bh[2*pi][1] = v[1];
                bh[2*pi+1][0] = v[2]; bh[2*pi+1][1] = v[3];
                LDSM4(v, tBl + swz(brow, bch));
                bl[2*pi][0] = v[0]; bl[2*pi][1] = v[1];
                bl[2*pi+1][0] = v[2]; bl[2*pi+1][1] = v[3];
            }
#pragma unroll
            for (int mi = 0; mi < 4; mi++)
#pragma unroll
                for (int ni = 0; ni < 4; ni++)
                    MMA16816(acc[mi][ni], a[mi], bh[ni]);
#pragma unroll
            for (int mi = 0; mi < 4; mi++)
#pragma unroll
                for (int ni = 0; ni < 4; ni++)
                    MMA16816(acc[mi][ni], a[mi], bl[ni]);
#pragma unroll
            for (int mi = 0; mi < 4; mi++)
                LDSM4(a[mi], tAl + swz(arow + mi * 16, ach));
#pragma unroll
            for (int mi = 0; mi < 4; mi++)
#pragma unroll
                for (int ni = 0; ni < 4; ni++)
                    MMA16816(acc[mi][ni], a[mi], bh[ni]);
        }
    }

    const bool doRes = (z == 0);
#pragma unroll
    for (int mi = 0; mi < 4; mi++) {
        const int r0 = m0 + wm * 64 + mi * 16 + (lane >> 2);
#pragma unroll
        for (int ni = 0; ni < 4; ni++) {
            const int col = n0 + wn * 32 + ni * 8 + (lane & 3) * 2;
            const float b0 = __ldg(bias + col), b1 = __ldg(bias + col + 1);
            const float x0 = acc[mi][ni][0] + b0;
            const float x1 = acc[mi][ni][1] + b1;
            const float x2 = acc[mi][ni][2] + b0;
            const float x3 = acc[mi][ni][3] + b1;
            const long long g0 = (long long)r0 * N + col;
            const long long g1 = (long long)(r0 + 8) * N + col;
            *(float2*)(Cf + g0) = make_float2(x0, x1);
            *(float2*)(Cf + g1) = make_float2(x2, x3);
            if (doRes) {
                *(float2*)(j.res + (long long)r0 * 2048 + col)       = make_float2(x0, x1);
                *(float2*)(j.res + (long long)(r0 + 8) * 2048 + col) = make_float2(x2, x3);
            }
        }
    }
}

// ---------------------------------------------------------------------------
struct Split3 { const float* x[3]; bf16* h[3]; bf16* l[3]; };

__global__ void __launch_bounds__(256) split3_k(Split3 j)
{
    const int z = blockIdx.y;
    const float* x = j.x[z];
    bf16* h = j.h[z]; bf16* l = j.l[z];
    const long long i = ((long long)blockIdx.x * 256 + threadIdx.x) * 4;
    const float4 v = *(const float4*)(x + i);
    float h0,l0,h1,l1,h2,l2,h3,l3;
    split1(v.x,h0,l0); split1(v.y,h1,l1); split1(v.z,h2,l2); split1(v.w,h3,l3);
    uint2 hp, lp;
    hp.x = pack2(h0,h1); hp.y = pack2(h2,h3);
    lp.x = pack2(l0,l1); lp.y = pack2(l2,l3);
    *(uint2*)(h + i) = hp;
    *(uint2*)(l + i) = lp;
}

struct W8 { const float* w[8]; bf16* th[8]; bf16* tl[8]; };

__global__ void __launch_bounds__(256) tspw_k(W8 j)
{
    __shared__ float t[32][33];
    const int z = blockIdx.z;
    const float* X = j.w[z];
    bf16* Th = j.th[z]; bf16* Tl = j.tl[z];
    const int c0 = blockIdx.x * 32, r0 = blockIdx.y * 32;
    const int tx = threadIdx.x, ty = threadIdx.y;
#pragma unroll
    for (int i = 0; i < 4; i++)
        t[ty + i * 8][tx] = X[(long long)(r0 + ty + i * 8) * 1024 + c0 + tx];
    __syncthreads();
#pragma unroll
    for (int i = 0; i < 4; i++) {
        const float v = t[tx][ty + i * 8];
        float h, l; split1(v, h, l);
        const long long g = (long long)(c0 + ty + i * 8) * 1024 + r0 + tx;
        Th[g] = __float2bfloat16(h);
        Tl[g] = __float2bfloat16(l);
    }
}

// ---------------------------------------------------------------------------
// fused 3x LayerNorm, warp-per-row: one warp owns a 1024-float row.
// No smem, no barriers; pure shfl reduction. Block = 8 warps = 8 rows.
// ---------------------------------------------------------------------------
struct LN3 {
    const float* x[3]; const float* g[3]; const float* b[3];
    bf16* yh[3]; bf16* yl[3];
};

__global__ void __launch_bounds__(256) ln3_k(LN3 j)
{
    const int z = blockIdx.y;
    const int lane = threadIdx.x & 31, warp = threadIdx.x >> 5;
    const long long row = (long long)blockIdx.x * 8 + warp;

    const float4* xr = (const float4*)(j.x[z] + row * 1024);
    float4 xv[8];
#pragma unroll
    for (int i = 0; i < 8; i++) xv[i] = xr[lane + i * 32];

    float s = 0.f, s2 = 0.f;
#pragma unroll
    for (int i = 0; i < 8; i++) {
        s  += xv[i].x + xv[i].y + xv[i].z + xv[i].w;
        s2 += xv[i].x*xv[i].x + xv[i].y*xv[i].y + xv[i].z*xv[i].z + xv[i].w*xv[i].w;
    }
#pragma unroll
    for (int o = 16; o > 0; o >>= 1) {
        s  += __shfl_xor_sync(0xffffffffu, s, o);
        s2 += __shfl_xor_sync(0xffffffffu, s2, o);
    }
    const float mean = s * (1.0f / 1024.0f);
    const float var  = s2 * (1.0f / 1024.0f) - mean * mean;
    const float inv  = rsqrtf(var + 1e-6f);

    const float4* gr = (const float4*)j.g[z];
    const float4* br = (const float4*)j.b[z];
    uint2* yh = (uint2*)(j.yh[z] + row * 1024);
    uint2* yl = (uint2*)(j.yl[z] + row * 1024);
#pragma unroll
    for (int i = 0; i < 8; i++) {
        const float4 gg = gr[lane + i * 32];
        const float4 bb = br[lane + i * 32];
        float4 o;
        o.x = (xv[i].x - mean) * inv * gg.x + bb.x;
        o.y = (xv[i].y - mean) * inv * gg.y + bb.y;
        o.z = (xv[i].z - mean) * inv * gg.z + bb.z;
        o.w = (xv[i].w - mean) * inv * gg.w + bb.w;
        float h0,l0,h1,l1,h2,l2,h3,l3;
        split1(o.x,h0,l0); split1(o.y,h1,l1); split1(o.z,h2,l2); split1(o.w,h3,l3);
        uint2 hp, lp;
        hp.x = pack2(h0,h1); hp.y = pack2(h2,h3);
        lp.x = pack2(l0,l1); lp.y = pack2(l2,l3);
        yh[lane + i * 32] = hp;
        yl[lane + i * 32] = lp;
    }
}

// ---------------------------------------------------------------------------
template<bool F32OUT>
__global__ void __launch_bounds__(256) softmax_k(
    float* __restrict__ S, bf16* __restrict__ Ph, bf16* __restrict__ Pl)
{
    const long long row = blockIdx.x;
    float* r = S + row * 2048;
    const int base = threadIdx.x * 8;

    float v[8];
    float4 a = *(const float4*)(r + base);
    float4 c = *(const float4*)(r + base + 4);
    v[0]=a.x; v[1]=a.y; v[2]=a.z; v[3]=a.w; v[4]=c.x; v[5]=c.y; v[6]=c.z; v[7]=c.w;

    float mx = v[0];
#pragma unroll
    for (int i = 1; i < 8; i++) mx = fmaxf(mx, v[i]);
    __shared__ float shm[8], shs[8];
#pragma unroll
    for (int o = 16; o > 0; o >>= 1) mx = fmaxf(mx, __shfl_xor_sync(0xffffffffu, mx, o));
    const int lane = threadIdx.x & 31, warp = threadIdx.x >> 5;
    if (lane == 0) shm[warp] = mx;
    __syncthreads();
    float M = shm[0];
#pragma unroll
    for (int i = 1; i < 8; i++) M = fmaxf(M, shm[i]);

    float sum = 0.f;
#pragma unroll
    for (int i = 0; i < 8; i++) { v[i] = __expf(v[i] - M); sum += v[i]; }
#pragma unroll
    for (int o = 16; o > 0; o >>= 1) sum += __shfl_xor_sync(0xffffffffu, sum, o);
    if (lane == 0) shs[warp] = sum;
    __syncthreads();
    float T = 0.f;
#pragma unroll
    for (int i = 0; i < 8; i++) T += shs[i];
    const float inv = 1.0f / T;

    uint4 hp, lp;
    float p0,p1,h0,l0,h1,l1;
    p0 = v[0]*inv; p1 = v[1]*inv; split1(p0,h0,l0); split1(p1,h1,l1);
    hp.x = pack2(h0,h1); lp.x = pack2(l0,l1); a.x = p0; a.y = p1;
    p0 = v[2]*inv; p1 = v[3]*inv; split1(p0,h0,l0); split1(p1,h1,l1);
    hp.y = pack2(h0,h1); lp.y = pack2(l0,l1); a.z = p0; a.w = p1;
    p0 = v[4]*inv; p1 = v[5]*inv; split1(p0,h0,l0); split1(p1,h1,l1);
    hp.z = pack2(h0,h1); lp.z = pack2(l0,l1); c.x = p0; c.y = p1;
    p0 = v[6]*inv; p1 = v[7]*inv; split1(p0,h0,l0); split1(p1,h1,l1);
    hp.w = pack2(h0,h1); lp.w = pack2(l0,l1); c.z = p0; c.w = p1;

    *(uint4*)(Ph + row * 2048 + base) = hp;
    *(uint4*)(Pl + row * 2048 + base) = lp;
    if (F32OUT) {
        *(float4*)(r + base)     = a;
        *(float4*)(r + base + 4) = c;
    }
}

// ---------------------------------------------------------------------------
extern "C" void kernel_launch(void* const* d_in, const int* in_sizes, int n_in,
                              void* d_out, int out_size)
{
    const float* q = (const float*)d_in[0];
    const float* k = (const float*)d_in[1];
    const float* v = (const float*)d_in[2];
    const float* W[8]  = {(const float*)d_in[3],  (const float*)d_in[5],
                          (const float*)d_in[7],  (const float*)d_in[9],
                          (const float*)d_in[11], (const float*)d_in[13],
                          (const float*)d_in[15], (const float*)d_in[17]};
    const float* bW[8] = {(const float*)d_in[4],  (const float*)d_in[6],
                          (const float*)d_in[8],  (const float*)d_in[10],
                          (const float*)d_in[12], (const float*)d_in[14],
                          (const float*)d_in[16], (const float*)d_in[18]};
    const float* gq1 = (const float*)d_in[19]; const float* Bq1 = (const float*)d_in[20];
    const float* gk1 = (const float*)d_in[21]; const float* Bk1 = (const float*)d_in[22];
    const float* gv1 = (const float*)d_in[23]; const float* Bv1 = (const float*)d_in[24];
    const float* gq2 = (const float*)d_in[25]; const float* Bq2 = (const float*)d_in[26];
    const float* gk2 = (const float*)d_in[27]; const float* Bk2 = (const float*)d_in[28];
    const float* gv2 = (const float*)d_in[29]; const float* Bv2 = (const float*)d_in[30];

    float* out = (float*)d_out;
    float* res = out + SZB;
    float* a2  = res + SSB;

    float* buf = nullptr;
    cudaGetSymbolAddress((void**)&buf, g_buf);
    char* P = (char*)buf;
    auto takeB = [&](long long bytes){ char* r = P; P += bytes; return r; };
    bf16* q_h  = (bf16*)takeB(SZB*2); bf16* q_l  = (bf16*)takeB(SZB*2);
    bf16* k_h  = (bf16*)takeB(SZB*2); bf16* k_l  = (bf16*)takeB(SZB*2);
    bf16* v_h  = (bf16*)takeB(SZB*2); bf16* v_l  = (bf16*)takeB(SZB*2);
    float* q1b = (float*)takeB(SZB*4);
    float* kb  = (float*)takeB(SZB*4);
    float* vb  = (float*)takeB(SZB*4);
    float* k2b = (float*)takeB(SZB*4);
    float* v2b = (float*)takeB(SZB*4);
    float* q2b = (float*)takeB(SZB*4);
    bf16* nq_h = (bf16*)takeB(SZB*2); bf16* nq_l = (bf16*)takeB(SZB*2);
    bf16* nk_h = (bf16*)takeB(SZB*2); bf16* nk_l = (bf16*)takeB(SZB*2);
    bf16* nv_h = (bf16*)takeB(SZB*2); bf16* nv_l = (bf16*)takeB(SZB*2);
    bf16* oa_h = (bf16*)takeB(SZB*2); bf16* oa_l = (bf16*)takeB(SZB*2);
    bf16* o1_h = (bf16*)takeB(SZB*2); bf16* o1_l = (bf16*)takeB(SZB*2);
    float* Sbuf= (float*)takeB(SSB*4);
    bf16* P_h  = (bf16*)takeB(SSB*2); bf16* P_l  = (bf16*)takeB(SSB*2);
    bf16* WTp  = (bf16*)takeB(8ll * 2 * WSZ * 2);
    auto WTh = [&](int i){ return WTp + (long long)i * 2 * WSZ; };
    auto WTl = [&](int i){ return WTp + (long long)i * 2 * WSZ + WSZ; };

    cudaFuncSetAttribute(gemm_bf3<1,true >, cudaFuncAttributeMaxDynamicSharedMemorySize, SMEMB);
    cudaFuncSetAttribute(gemm_bf3<1,false>, cudaFuncAttributeMaxDynamicSharedMemorySize, SMEMB);
    cudaFuncSetAttribute(gemm_bf3<2,true >, cudaFuncAttributeMaxDynamicSharedMemorySize, SMEMB);
    cudaFuncSetAttribute(gemm_bf3<5,true >, cudaFuncAttributeMaxDynamicSharedMemorySize, SMEMB);
    cudaFuncSetAttribute(gemm_nn,           cudaFuncAttributeMaxDynamicSharedMemorySize, SMEMB);
    cudaFuncSetAttribute(proj5_k,           cudaFuncAttributeMaxDynamicSharedMemorySize, SMEMB);

    const dim3 tb(32, 8);
    const dim3 gproj(8, 64, 1);
    const dim3 gproj5(8, 64, 5);
    const dim3 gS(16, 16, 4);
    const dim3 gO(8, 16, 4);
    const float it = 1.0f / 32.0f;
    const long long sLD = 2048ll*1024, sLL = 2048ll*2048;

    // prep
    Split3 s3;
    s3.x[0] = q; s3.h[0] = q_h; s3.l[0] = q_l;
    s3.x[1] = k; s3.h[1] = k_h; s3.l[1] = k_l;
    s3.x[2] = v; s3.h[2] = v_h; s3.l[2] = v_l;
    split3_k<<<dim3(SZB/4/256, 3), 256>>>(s3);
    W8 w8;
    for (int i = 0; i < 8; i++) { w8.w[i] = W[i]; w8.th[i] = WTh(i); w8.tl[i] = WTl(i); }
    tspw_k<<<dim3(32,32,8), tb>>>(w8);

    // all 5 input-dependent projections in one launch
    Proj5 p5;
    p5.Ah[0]=q_h; p5.Al[0]=q_l; p5.Bh[0]=WTh(0); p5.Bl[0]=WTl(0); p5.bias[0]=bW[0]; p5.Cf[0]=q1b;
    p5.Ah[1]=k_h; p5.Al[1]=k_l; p5.Bh[1]=WTh(1); p5.Bl[1]=WTl(1); p5.bias[1]=bW[1]; p5.Cf[1]=kb;
    p5.Ah[2]=v_h; p5.Al[2]=v_l; p5.Bh[2]=WTh(2); p5.Bl[2]=WTl(2); p5.bias[2]=bW[2]; p5.Cf[2]=vb;
    p5.Ah[3]=k_h; p5.Al[3]=k_l; p5.Bh[3]=WTh(5); p5.Bl[3]=WTl(5); p5.bias[3]=bW[5]; p5.Cf[3]=k2b;
    p5.Ah[4]=v_h; p5.Al[4]=v_l; p5.Bh[4]=WTh(6); p5.Bl[4]=WTl(6); p5.bias[4]=bW[6]; p5.Cf[4]=v2b;
    p5.res = res;
    proj5_k<<<gproj5, 256, SMEMB>>>(p5);

    // ---------------- layer 1 ----------------
    LN3 l1;
    l1.x[0]=q1b; l1.g[0]=gq1; l1.b[0]=Bq1; l1.yh[0]=nq_h; l1.yl[0]=nq_l;
    l1.x[1]=kb;  l1.g[1]=gk1; l1.b[1]=Bk1; l1.yh[1]=nk_h; l1.yl[1]=nk_l;
    l1.x[2]=vb;  l1.g[2]=gv1; l1.b[2]=Bv1; l1.yh[2]=nv_h; l1.yl[2]=nv_l;
    ln3_k<<<dim3(1024,3), 256>>>(l1);

    gemm_bf3<1,false><<<gS,256,SMEMB>>>(nq_h,nq_l, nk_h,nk_l, 0, Sbuf,0,0, 0,0, 2048,2048,1024, it, sLD,sLD,sLL);
    softmax_k<false><<<8192,256>>>(Sbuf, P_h, P_l);
    gemm_nn<<<gO,256,SMEMB>>>(P_h,P_l, nv_h,nv_l, oa_h,oa_l, 2048,1024,2048, sLL,sLD,sLD);
    gemm_bf3<2,true ><<<gproj,256,SMEMB>>>(oa_h,oa_l, WTh(3),WTl(3), bW[3], 0,o1_h,o1_l, 0,0, 8192,1024,1024, 1.f, 0,0,0);
    gemm_bf3<5,true ><<<gproj,256,SMEMB>>>(o1_h,o1_l, WTh(4),WTl(4), bW[4], q2b,0,0, res,1024, 8192,1024,1024, 1.f, 0,0,0);

    // ---------------- layer 2 ----------------
    LN3 l2;
    l2.x[0]=q2b; l2.g[0]=gq2; l2.b[0]=Bq2; l2.yh[0]=nq_h; l2.yl[0]=nq_l;
    l2.x[1]=k2b; l2.g[1]=gk2; l2.b[1]=Bk2; l2.yh[1]=nk_h; l2.yl[1]=nk_l;
    l2.x[2]=v2b; l2.g[2]=gv2; l2.b[2]=Bv2; l2.yh[2]=nv_h; l2.yl[2]=nv_l;
    ln3_k<<<dim3(1024,3), 256>>>(l2);

    gemm_bf3<1,false><<<gS,256,SMEMB>>>(nq_h,nq_l, nk_h,nk_l, 0, a2,0,0, 0,0, 2048,2048,1024, it, sLD,sLD,sLL);
    softmax_k<true><<<8192,256>>>(a2, P_h, P_l);
    gemm_nn<<<gO,256,SMEMB>>>(P_h,P_l, nv_h,nv_l, oa_h,oa_l, 2048,1024,2048, sLL,sLD,sLD);
    gemm_bf3<1,true ><<<gproj,256,SMEMB>>>(oa_h,oa_l, WTh(7),WTl(7), bW[7], out,0,0, 0,0, 8192,1024,1024, 1.f, 0,0,0);
}

// round 11
// speedup vs baseline: 1.3761x; 1.0024x over previous
#include <cuda_runtime.h>
#include <cuda_bf16.h>
#include <cstdint>

// ---------------------------------------------------------------------------
// B=4, L=2048, D=1024, fp32. Outputs: out(8.39M) | res(16.78M) | a2(16.78M).
// GEMMs via legacy mma.sync bf16, 2-term bf16 split (3 products).
// R11 = R10 + warp-per-row softmax + interleaved LDSM/MMA groups in GEMMs.
// ---------------------------------------------------------------------------

#define SZB 8388608ll
#define SSB 16777216ll
#define WSZ 1048576ll

__device__ float g_buf[160000000ull];   // 640MB scratch pool

using bf16 = __nv_bfloat16;

__device__ __forceinline__ uint32_t smem_u32(const void* p){
    uint32_t a;
    asm("{ .reg .u64 t; cvta.to.shared.u64 t, %1; cvt.u32.u64 %0, t; }" : "=r"(a) : "l"(p));
    return a;
}
__device__ __forceinline__ uint32_t pack2(float x, float y){
    __nv_bfloat162 t = __floats2bfloat162_rn(x, y);
    return *(uint32_t*)&t;
}
__device__ __forceinline__ void split1(float x, float& h, float& l){
    h = __bfloat162float(__float2bfloat16(x));
    l = x - h;
}
// swizzled byte offset within a 128-row x 64B tile (A tiles, NT B tiles)
__device__ __forceinline__ uint32_t swz(uint32_t r, uint32_t c){
    return r * 64 + (((c ^ (r >> 1)) & 3) << 4) + (c & ~3u) * 16;
}
// swizzled byte offset within a 32-row x 256B tile (NN B tiles)
__device__ __forceinline__ uint32_t swzN(uint32_t r, uint32_t c){
    return r * 256 + ((c ^ (r & 7)) << 4);
}

#define LDSM4(R, addr) \
    asm volatile("ldmatrix.sync.aligned.m8n8.x4.shared.b16 {%0,%1,%2,%3}, [%4];" \
        : "=r"((R)[0]), "=r"((R)[1]), "=r"((R)[2]), "=r"((R)[3]) : "r"(addr))

#define LDSM4T(R, addr) \
    asm volatile("ldmatrix.sync.aligned.m8n8.x4.trans.shared.b16 {%0,%1,%2,%3}, [%4];" \
        : "=r"((R)[0]), "=r"((R)[1]), "=r"((R)[2]), "=r"((R)[3]) : "r"(addr))

#define MMA16816(d, a, b) \
    asm volatile("mma.sync.aligned.m16n8k16.row.col.f32.bf16.bf16.f32 " \
        "{%0,%1,%2,%3}, {%4,%5,%6,%7}, {%8,%9}, {%0,%1,%2,%3};" \
        : "+f"((d)[0]), "+f"((d)[1]), "+f"((d)[2]), "+f"((d)[3]) \
        : "r"((a)[0]), "r"((a)[1]), "r"((a)[2]), "r"((a)[3]), "r"((b)[0]), "r"((b)[1]))

#define CP_ASYNC16(dst, src) \
    asm volatile("cp.async.cg.shared.global [%0], [%1], 16;" :: "r"(dst), "l"(src))

constexpr int TILEB = 128 * 64;           // 8192 bytes (also 32x256 for NN B)
constexpr int STGB  = 4 * TILEB;          // 32768
constexpr int SMEMB = 3 * STGB;           // 98304

// ---------------------------------------------------------------------------
// NT GEMM: C = scale*(A @ B^T)(+bias). A[M,K], B[N,K] bf16 splits.
// OM bit0: fp32 C; bit1: bf16 split out; bit2: fp32 res write.
// ---------------------------------------------------------------------------
template<int OM, bool BIAS>
__global__ void __launch_bounds__(256, 2) gemm_bf3(
    const bf16* __restrict__ Ah, const bf16* __restrict__ Al,
    const bf16* __restrict__ Bh, const bf16* __restrict__ Bl,
    const float* __restrict__ bias,
    float* __restrict__ Cf, bf16* __restrict__ Ch, bf16* __restrict__ Cl,
    float* __restrict__ Cres, int resOff,
    int M, int N, int K, float scale,
    long long sA, long long sB, long long sC)
{
    extern __shared__ char sm[];
    const uint32_t sb = smem_u32(sm);
    const int tid = threadIdx.x, lane = tid & 31, warp = tid >> 5;
    const int wm = warp >> 2, wn = warp & 3;
    const int bz = blockIdx.z;
    Ah += bz * sA;  Al += bz * sA;
    Bh += bz * sB;  Bl += bz * sB;
    const long long co = (long long)bz * sC;
    const int m0 = blockIdx.y * 128, n0 = blockIdx.x * 128;

    auto load_stage = [&](int slot, int k0){
        const uint32_t s = sb + slot * STGB;
        const bf16* srcs[4] = {Ah, Al, Bh, Bl};
#pragma unroll
        for (int t = 0; t < 4; t++) {
            const bf16* src = srcs[t];
            const int rbase = (t < 2) ? m0 : n0;
#pragma unroll
            for (int i = 0; i < 2; i++) {
                const int c = tid + i * 256;
                const uint32_t row = c >> 2, ch = c & 3;
                const uint32_t dst = s + t * TILEB + swz(row, ch);
                const bf16* g = src + (long long)(rbase + row) * K + k0 + ch * 8;
                CP_ASYNC16(dst, g);
            }
        }
    };

    const int NS = K / 32;
    load_stage(0, 0);
    asm volatile("cp.async.commit_group;" ::: "memory");
    load_stage(1, 32);
    asm volatile("cp.async.commit_group;" ::: "memory");

    float acc[4][4][4] = {};
    int slot = 0;

    for (int s = 0; s < NS; s++) {
        asm volatile("cp.async.wait_group 1;" ::: "memory");
        __syncthreads();
        if (s + 2 < NS) {
            int ns = slot + 2; if (ns >= 3) ns -= 3;
            load_stage(ns, (s + 2) * 32);
        }
        asm volatile("cp.async.commit_group;" ::: "memory");

        const uint32_t st  = sb + slot * STGB;
        const uint32_t tAh = st, tAl = st + TILEB, tBh = st + 2*TILEB, tBl = st + 3*TILEB;
        if (++slot == 3) slot = 0;

#pragma unroll
        for (int ks = 0; ks < 2; ks++) {
            uint32_t a[4][4], bh[4][2], bl[4][2];
            const uint32_t ach  = ks * 2 + (lane >> 4);
            const uint32_t arow = wm * 64 + (lane & 15);
            const uint32_t brow = wn * 32 + (lane & 7) + ((lane >> 4) << 3);
            const uint32_t bch  = ks * 2 + ((lane >> 3) & 1);
            // group 1: A-high + B-high fragments
#pragma unroll
            for (int mi = 0; mi < 4; mi++)
                LDSM4(a[mi], tAh + swz(arow + mi * 16, ach));
#pragma unroll
            for (int pi = 0; pi < 2; pi++) {
                uint32_t v[4];
                LDSM4(v, tBh + swz(brow + pi * 16, bch));
                bh[2*pi][0] = v[0]; bh[2*pi][1] = v[1];
                bh[2*pi+1][0] = v[2]; bh[2*pi+1][1] = v[3];
            }
#pragma unroll
            for (int mi = 0; mi < 4; mi++)
#pragma unroll
                for (int ni = 0; ni < 4; ni++)
                    MMA16816(acc[mi][ni], a[mi], bh[ni]);
            // group 2: B-low fragments, hidden under previous MMAs
#pragma unroll
            for (int pi = 0; pi < 2; pi++) {
                uint32_t v[4];
                LDSM4(v, tBl + swz(brow + pi * 16, bch));
                bl[2*pi][0] = v[0]; bl[2*pi][1] = v[1];
                bl[2*pi+1][0] = v[2]; bl[2*pi+1][1] = v[3];
            }
#pragma unroll
            for (int mi = 0; mi < 4; mi++)
#pragma unroll
                for (int ni = 0; ni < 4; ni++)
                    MMA16816(acc[mi][ni], a[mi], bl[ni]);
            // group 3: A-low fragments (reuse regs), hidden under previous MMAs
#pragma unroll
            for (int mi = 0; mi < 4; mi++)
                LDSM4(a[mi], tAl + swz(arow + mi * 16, ach));
#pragma unroll
            for (int mi = 0; mi < 4; mi++)
#pragma unroll
                for (int ni = 0; ni < 4; ni++)
                    MMA16816(acc[mi][ni], a[mi], bh[ni]);
        }
    }

#pragma unroll
    for (int mi = 0; mi < 4; mi++) {
        const int r0 = m0 + wm * 64 + mi * 16 + (lane >> 2);
#pragma unroll
        for (int ni = 0; ni < 4; ni++) {
            const int col = n0 + wn * 32 + ni * 8 + (lane & 3) * 2;
            float b0 = 0.f, b1 = 0.f;
            if (BIAS) { b0 = __ldg(bias + col); b1 = __ldg(bias + col + 1); }
            const float x0 = acc[mi][ni][0] * scale + b0;
            const float x1 = acc[mi][ni][1] * scale + b1;
            const float x2 = acc[mi][ni][2] * scale + b0;
            const float x3 = acc[mi][ni][3] * scale + b1;
            const long long g0 = co + (long long)r0 * N + col;
            const long long g1 = co + (long long)(r0 + 8) * N + col;
            if (OM & 1) {
                *(float2*)(Cf + g0) = make_float2(x0, x1);
                *(float2*)(Cf + g1) = make_float2(x2, x3);
            }
            if (OM & 2) {
                float h0, l0, h1, l1, h2, l2, h3, l3;
                split1(x0, h0, l0); split1(x1, h1, l1);
                split1(x2, h2, l2); split1(x3, h3, l3);
                *(uint32_t*)(Ch + g0) = pack2(h0, h1);
                *(uint32_t*)(Ch + g1) = pack2(h2, h3);
                *(uint32_t*)(Cl + g0) = pack2(l0, l1);
                *(uint32_t*)(Cl + g1) = pack2(l2, l3);
            }
            if (OM & 4) {
                const long long rg0 = (long long)r0 * 2048 + resOff + col;
                const long long rg1 = (long long)(r0 + 8) * 2048 + resOff + col;
                *(float2*)(Cres + rg0) = make_float2(x0, x1);
                *(float2*)(Cres + rg1) = make_float2(x2, x3);
            }
        }
    }
}

// ---------------------------------------------------------------------------
// NN GEMM: C = A @ B, A[M,K], B[K,N] (row-major), bf16 splits; out = bf16 split.
// ---------------------------------------------------------------------------
__global__ void __launch_bounds__(256, 2) gemm_nn(
    const bf16* __restrict__ Ah, const bf16* __restrict__ Al,
    const bf16* __restrict__ Bh, const bf16* __restrict__ Bl,
    bf16* __restrict__ Ch, bf16* __restrict__ Cl,
    int M, int N, int K,
    long long sA, long long sB, long long sC)
{
    extern __shared__ char sm[];
    const uint32_t sb = smem_u32(sm);
    const int tid = threadIdx.x, lane = tid & 31, warp = tid >> 5;
    const int wm = warp >> 2, wn = warp & 3;
    const int bz = blockIdx.z;
    Ah += bz * sA;  Al += bz * sA;
    Bh += bz * sB;  Bl += bz * sB;
    const long long co = (long long)bz * sC;
    const int m0 = blockIdx.y * 128, n0 = blockIdx.x * 128;

    auto load_stage = [&](int slot, int k0){
        const uint32_t s = sb + slot * STGB;
#pragma unroll
        for (int i = 0; i < 2; i++) {
            const int c = tid + i * 256;
            const uint32_t row = c >> 2, ch = c & 3;
            const long long g = (long long)(m0 + row) * K + k0 + ch * 8;
            CP_ASYNC16(s + swz(row, ch),          Ah + g);
            CP_ASYNC16(s + TILEB + swz(row, ch),  Al + g);
        }
#pragma unroll
        for (int i = 0; i < 2; i++) {
            const int c = tid + i * 256;
            const uint32_t row = c >> 4, ch = c & 15;
            const long long g = (long long)(k0 + row) * N + n0 + ch * 8;
            CP_ASYNC16(s + 2*TILEB + swzN(row, ch), Bh + g);
            CP_ASYNC16(s + 3*TILEB + swzN(row, ch), Bl + g);
        }
    };

    const int NS = K / 32;
    load_stage(0, 0);
    asm volatile("cp.async.commit_group;" ::: "memory");
    load_stage(1, 32);
    asm volatile("cp.async.commit_group;" ::: "memory");

    float acc[4][4][4] = {};
    int slot = 0;

    for (int s = 0; s < NS; s++) {
        asm volatile("cp.async.wait_group 1;" ::: "memory");
        __syncthreads();
        if (s + 2 < NS) {
            int ns = slot + 2; if (ns >= 3) ns -= 3;
            load_stage(ns, (s + 2) * 32);
        }
        asm volatile("cp.async.commit_group;" ::: "memory");

        const uint32_t st  = sb + slot * STGB;
        const uint32_t tAh = st, tAl = st + TILEB, tBh = st + 2*TILEB, tBl = st + 3*TILEB;
        if (++slot == 3) slot = 0;

#pragma unroll
        for (int ks = 0; ks < 2; ks++) {
            uint32_t a[4][4], bh[4][2], bl[4][2];
            const uint32_t ach  = ks * 2 + (lane >> 4);
            const uint32_t arow = wm * 64 + (lane & 15);
            const uint32_t brr  = ks * 16 + (lane & 7) + (((lane >> 3) & 1) << 3);
            // group 1: A-high + B-high
#pragma unroll
            for (int mi = 0; mi < 4; mi++)
                LDSM4(a[mi], tAh + swz(arow + mi * 16, ach));
#pragma unroll
            for (int pi = 0; pi < 2; pi++) {
                const uint32_t bcc = ((wn * 32 + pi * 16) >> 3) + (lane >> 4);
                uint32_t v[4];
                LDSM4T(v, tBh + swzN(brr, bcc));
                bh[2*pi][0] = v[0]; bh[2*pi][1] = v[1];
                bh[2*pi+1][0] = v[2]; bh[2*pi+1][1] = v[3];
            }
#pragma unroll
            for (int mi = 0; mi < 4; mi++)
#pragma unroll
                for (int ni = 0; ni < 4; ni++)
                    MMA16816(acc[mi][ni], a[mi], bh[ni]);
            // group 2: B-low
#pragma unroll
            for (int pi = 0; pi < 2; pi++) {
                const uint32_t bcc = ((wn * 32 + pi * 16) >> 3) + (lane >> 4);
                uint32_t v[4];
                LDSM4T(v, tBl + swzN(brr, bcc));
                bl[2*pi][0] = v[0]; bl[2*pi][1] = v[1];
                bl[2*pi+1][0] = v[2]; bl[2*pi+1][1] = v[3];
            }
#pragma unroll
            for (int mi = 0; mi < 4; mi++)
#pragma unroll
                for (int ni = 0; ni < 4; ni++)
                    MMA16816(acc[mi][ni], a[mi], bl[ni]);
            // group 3: A-low (reuse regs)
#pragma unroll
            for (int mi = 0; mi < 4; mi++)
                LDSM4(a[mi], tAl + swz(arow + mi * 16, ach));
#pragma unroll
            for (int mi = 0; mi < 4; mi++)
#pragma unroll
                for (int ni = 0; ni < 4; ni++)
                    MMA16816(acc[mi][ni], a[mi], bh[ni]);
        }
    }

#pragma unroll
    for (int mi = 0; mi < 4; mi++) {
        const int r0 = m0 + wm * 64 + mi * 16 + (lane >> 2);
#pragma unroll
        for (int ni = 0; ni < 4; ni++) {
            const int col = n0 + wn * 32 + ni * 8 + (lane & 3) * 2;
            const float x0 = acc[mi][ni][0], x1 = acc[mi][ni][1];
            const float x2 = acc[mi][ni][2], x3 = acc[mi][ni][3];
            const long long g0 = co + (long long)r0 * N + col;
            const long long g1 = co + (long long)(r0 + 8) * N + col;
            float h0, l0, h1, l1, h2, l2, h3, l3;
            split1(x0, h0, l0); split1(x1, h1, l1);
            split1(x2, h2, l2); split1(x3, h3, l3);
            *(uint32_t*)(Ch + g0) = pack2(h0, h1);
            *(uint32_t*)(Ch + g1) = pack2(h2, h3);
            *(uint32_t*)(Cl + g0) = pack2(l0, l1);
            *(uint32_t*)(Cl + g1) = pack2(l2, l3);
        }
    }
}

// ---------------------------------------------------------------------------
// 5-way fused projection GEMM. z==0 additionally writes fp32 res at col 0.
// ---------------------------------------------------------------------------
struct Proj5 {
    const bf16* Ah[5]; const bf16* Al[5];
    const bf16* Bh[5]; const bf16* Bl[5];
    const float* bias[5];
    float* Cf[5];
    float* res;
};

__global__ void __launch_bounds__(256, 2) proj5_k(Proj5 j)
{
    extern __shared__ char sm[];
    const uint32_t sb = smem_u32(sm);
    const int tid = threadIdx.x, lane = tid & 31, warp = tid >> 5;
    const int wm = warp >> 2, wn = warp & 3;
    const int z = blockIdx.z;
    const bf16* Ah = j.Ah[z]; const bf16* Al = j.Al[z];
    const bf16* Bh = j.Bh[z]; const bf16* Bl = j.Bl[z];
    const float* bias = j.bias[z];
    float* Cf = j.Cf[z];
    const int m0 = blockIdx.y * 128, n0 = blockIdx.x * 128;
    constexpr int K = 1024, N = 1024;

    auto load_stage = [&](int slot, int k0){
        const uint32_t s = sb + slot * STGB;
        const bf16* srcs[4] = {Ah, Al, Bh, Bl};
#pragma unroll
        for (int t = 0; t < 4; t++) {
            const bf16* src = srcs[t];
            const int rbase = (t < 2) ? m0 : n0;
#pragma unroll
            for (int i = 0; i < 2; i++) {
                const int c = tid + i * 256;
                const uint32_t row = c >> 2, ch = c & 3;
                const uint32_t dst = s + t * TILEB + swz(row, ch);
                const bf16* g = src + (long long)(rbase + row) * K + k0 + ch * 8;
                CP_ASYNC16(dst, g);
            }
        }
    };

    const int NS = K / 32;
    load_stage(0, 0);
    asm volatile("cp.async.commit_group;" ::: "memory");
    load_stage(1, 32);
    asm volatile("cp.async.commit_group;" ::: "memory");

    float acc[4][4][4] = {};
    int slot = 0;

    for (int s = 0; s < NS; s++) {
        asm volatile("cp.async.wait_group 1;" ::: "memory");
        __syncthreads();
        if (s + 2 < NS) {
            int ns = slot + 2; if (ns >= 3) ns -= 3;
            load_stage(ns, (s + 2) * 32);
        }
        asm volatile("cp.async.commit_group;" ::: "memory");

        const uint32_t st  = sb + slot * STGB;
        const uint32_t tAh = st, tAl = st + TILEB, tBh = st + 2*TILEB, tBl = st + 3*TILEB;
        if (++slot == 3) slot = 0;

#pragma unroll
        for (int ks = 0; ks < 2; ks++) {
            uint32_t a[4][4], bh[4][2], bl[4][2];
            const uint32_t ach  = ks * 2 + (lane >> 4);
            const uint32_t arow = wm * 64 + (lane & 15);
            const uint32_t brow = wn * 32 + (lane & 7) + ((lane >> 4) << 3);
            const uint32_t bch  = ks * 2 + ((lane >> 3) & 1);
#pragma unroll
            for (int mi = 0; mi < 4; mi++)
                LDSM4(a[mi], tAh + swz(arow + mi * 16, ach));
#pragma unroll
            for (int pi = 0; pi < 2; pi++) {
                uint32_t v[4];
                LDSM4(v, tBh + swz(brow + pi * 16, bch));
                bh[2*pi][0] = v[0]; bh[2*pi][1] = v[1];
                bh[2*pi+1][0] = v[2]; bh[2*pi+1][1] = v[3];
            }
#pragma unroll
            for (int mi = 0; mi < 4; mi++)
#pragma unroll
                for (int ni = 0; ni < 4; ni++)
                    MMA16816(acc[mi][ni], a[mi], bh[ni]);
#pragma unroll
            for (int pi = 0; pi < 2; pi++) {
                uint32_t v[4];
                LDSM4(v, tBl + swz(brow + pi * 16, bch));
                bl[2*pi][0] = v[0]; bl[2*pi][1] = v[1];
                bl[2*pi+1][0] = v[2]; bl[2*pi+1][1] = v[3];
            }
#pragma unroll
            for (int mi = 0; mi < 4; mi++)
#pragma unroll
                for (int ni = 0; ni < 4; ni++)
                    MMA16816(acc[mi][ni], a[mi], bl[ni]);
#pragma unroll
            for (int mi = 0; mi < 4; mi++)
                LDSM4(a[mi], tAl + swz(arow + mi * 16, ach));
#pragma unroll
            for (int mi = 0; mi < 4; mi++)
#pragma unroll
                for (int ni = 0; ni < 4; ni++)
                    MMA16816(acc[mi][ni], a[mi], bh[ni]);
        }
    }

    const bool doRes = (z == 0);
#pragma unroll
    for (int mi = 0; mi < 4; mi++) {
        const int r0 = m0 + wm * 64 + mi * 16 + (lane >> 2);
#pragma unroll
        for (int ni = 0; ni < 4; ni++) {
            const int col = n0 + wn * 32 + ni * 8 + (lane & 3) * 2;
            const float b0 = __ldg(bias + col), b1 = __ldg(bias + col + 1);
            const float x0 = acc[mi][ni][0] + b0;
            const float x1 = acc[mi][ni][1] + b1;
            const float x2 = acc[mi][ni][2] + b0;
            const float x3 = acc[mi][ni][3] + b1;
            const long long g0 = (long long)r0 * N + col;
            const long long g1 = (long long)(r0 + 8) * N + col;
            *(float2*)(Cf + g0) = make_float2(x0, x1);
            *(float2*)(Cf + g1) = make_float2(x2, x3);
            if (doRes) {
                *(float2*)(j.res + (long long)r0 * 2048 + col)       = make_float2(x0, x1);
                *(float2*)(j.res + (long long)(r0 + 8) * 2048 + col) = make_float2(x2, x3);
            }
        }
    }
}

// ---------------------------------------------------------------------------
struct Split3 { const float* x[3]; bf16* h[3]; bf16* l[3]; };

__global__ void __launch_bounds__(256) split3_k(Split3 j)
{
    const int z = blockIdx.y;
    const float* x = j.x[z];
    bf16* h = j.h[z]; bf16* l = j.l[z];
    const long long i = ((long long)blockIdx.x * 256 + threadIdx.x) * 4;
    const float4 v = *(const float4*)(x + i);
    float h0,l0,h1,l1,h2,l2,h3,l3;
    split1(v.x,h0,l0); split1(v.y,h1,l1); split1(v.z,h2,l2); split1(v.w,h3,l3);
    uint2 hp, lp;
    hp.x = pack2(h0,h1); hp.y = pack2(h2,h3);
    lp.x = pack2(l0,l1); lp.y = pack2(l2,l3);
    *(uint2*)(h + i) = hp;
    *(uint2*)(l + i) = lp;
}

struct W8 { const float* w[8]; bf16* th[8]; bf16* tl[8]; };

__global__ void __launch_bounds__(256) tspw_k(W8 j)
{
    __shared__ float t[32][33];
    const int z = blockIdx.z;
    const float* X = j.w[z];
    bf16* Th = j.th[z]; bf16* Tl = j.tl[z];
    const int c0 = blockIdx.x * 32, r0 = blockIdx.y * 32;
    const int tx = threadIdx.x, ty = threadIdx.y;
#pragma unroll
    for (int i = 0; i < 4; i++)
        t[ty + i * 8][tx] = X[(long long)(r0 + ty + i * 8) * 1024 + c0 + tx];
    __syncthreads();
#pragma unroll
    for (int i = 0; i < 4; i++) {
        const float v = t[tx][ty + i * 8];
        float h, l; split1(v, h, l);
        const long long g = (long long)(c0 + ty + i * 8) * 1024 + r0 + tx;
        Th[g] = __float2bfloat16(h);
        Tl[g] = __float2bfloat16(l);
    }
}

// ---------------------------------------------------------------------------
// fused 3x LayerNorm, warp-per-row.
// ---------------------------------------------------------------------------
struct LN3 {
    const float* x[3]; const float* g[3]; const float* b[3];
    bf16* yh[3]; bf16* yl[3];
};

__global__ void __launch_bounds__(256) ln3_k(LN3 j)
{
    const int z = blockIdx.y;
    const int lane = threadIdx.x & 31, warp = threadIdx.x >> 5;
    const long long row = (long long)blockIdx.x * 8 + warp;

    const float4* xr = (const float4*)(j.x[z] + row * 1024);
    float4 xv[8];
#pragma unroll
    for (int i = 0; i < 8; i++) xv[i] = xr[lane + i * 32];

    float s = 0.f, s2 = 0.f;
#pragma unroll
    for (int i = 0; i < 8; i++) {
        s  += xv[i].x + xv[i].y + xv[i].z + xv[i].w;
        s2 += xv[i].x*xv[i].x + xv[i].y*xv[i].y + xv[i].z*xv[i].z + xv[i].w*xv[i].w;
    }
#pragma unroll
    for (int o = 16; o > 0; o >>= 1) {
        s  += __shfl_xor_sync(0xffffffffu, s, o);
        s2 += __shfl_xor_sync(0xffffffffu, s2, o);
    }
    const float mean = s * (1.0f / 1024.0f);
    const float var  = s2 * (1.0f / 1024.0f) - mean * mean;
    const float inv  = rsqrtf(var + 1e-6f);

    const float4* gr = (const float4*)j.g[z];
    const float4* br = (const float4*)j.b[z];
    uint2* yh = (uint2*)(j.yh[z] + row * 1024);
    uint2* yl = (uint2*)(j.yl[z] + row * 1024);
#pragma unroll
    for (int i = 0; i < 8; i++) {
        const float4 gg = gr[lane + i * 32];
        const float4 bb = br[lane + i * 32];
        float4 o;
        o.x = (xv[i].x - mean) * inv * gg.x + bb.x;
        o.y = (xv[i].y - mean) * inv * gg.y + bb.y;
        o.z = (xv[i].z - mean) * inv * gg.z + bb.z;
        o.w = (xv[i].w - mean) * inv * gg.w + bb.w;
        float h0,l0,h1,l1,h2,l2,h3,l3;
        split1(o.x,h0,l0); split1(o.y,h1,l1); split1(o.z,h2,l2); split1(o.w,h3,l3);
        uint2 hp, lp;
        hp.x = pack2(h0,h1); hp.y = pack2(h2,h3);
        lp.x = pack2(l0,l1); lp.y = pack2(l2,l3);
        yh[lane + i * 32] = hp;
        yl[lane + i * 32] = lp;
    }
}

// ---------------------------------------------------------------------------
// row softmax (2048), warp-per-row; writes bf16 split P; optional fp32 in place.
// ---------------------------------------------------------------------------
template<bool F32OUT>
__global__ void __launch_bounds__(256) softmax_k(
    float* __restrict__ S, bf16* __restrict__ Ph, bf16* __restrict__ Pl)
{
    const int lane = threadIdx.x & 31, warp = threadIdx.x >> 5;
    const long long row = (long long)blockIdx.x * 8 + warp;
    float4* r4 = (float4*)(S + row * 2048);

    float4 v[16];
#pragma unroll
    for (int i = 0; i < 16; i++) v[i] = r4[lane + i * 32];

    float mx = v[0].x;
#pragma unroll
    for (int i = 0; i < 16; i++) {
        mx = fmaxf(mx, fmaxf(fmaxf(v[i].x, v[i].y), fmaxf(v[i].z, v[i].w)));
    }
#pragma unroll
    for (int o = 16; o > 0; o >>= 1) mx = fmaxf(mx, __shfl_xor_sync(0xffffffffu, mx, o));

    float sum = 0.f;
#pragma unroll
    for (int i = 0; i < 16; i++) {
        v[i].x = __expf(v[i].x - mx); v[i].y = __expf(v[i].y - mx);
        v[i].z = __expf(v[i].z - mx); v[i].w = __expf(v[i].w - mx);
        sum += v[i].x + v[i].y + v[i].z + v[i].w;
    }
#pragma unroll
    for (int o = 16; o > 0; o >>= 1) sum += __shfl_xor_sync(0xffffffffu, sum, o);
    const float inv = 1.0f / sum;

    uint2* ph = (uint2*)(Ph + row * 2048);
    uint2* pl = (uint2*)(Pl + row * 2048);
#pragma unroll
    for (int i = 0; i < 16; i++) {
        float4 p;
        p.x = v[i].x * inv; p.y = v[i].y * inv;
        p.z = v[i].z * inv; p.w = v[i].w * inv;
        float h0,l0,h1,l1,h2,l2,h3,l3;
        split1(p.x,h0,l0); split1(p.y,h1,l1); split1(p.z,h2,l2); split1(p.w,h3,l3);
        uint2 hp, lp;
        hp.x = pack2(h0,h1); hp.y = pack2(h2,h3);
        lp.x = pack2(l0,l1); lp.y = pack2(l2,l3);
        ph[lane + i * 32] = hp;
        pl[lane + i * 32] = lp;
        if (F32OUT) r4[lane + i * 32] = p;
    }
}

// ---------------------------------------------------------------------------
extern "C" void kernel_launch(void* const* d_in, const int* in_sizes, int n_in,
                              void* d_out, int out_size)
{
    const float* q = (const float*)d_in[0];
    const float* k = (const float*)d_in[1];
    const float* v = (const float*)d_in[2];
    const float* W[8]  = {(const float*)d_in[3],  (const float*)d_in[5],
                          (const float*)d_in[7],  (const float*)d_in[9],
                          (const float*)d_in[11], (const float*)d_in[13],
                          (const float*)d_in[15], (const float*)d_in[17]};
    const float* bW[8] = {(const float*)d_in[4],  (const float*)d_in[6],
                          (const float*)d_in[8],  (const float*)d_in[10],
                          (const float*)d_in[12], (const float*)d_in[14],
                          (const float*)d_in[16], (const float*)d_in[18]};
    const float* gq1 = (const float*)d_in[19]; const float* Bq1 = (const float*)d_in[20];
    const float* gk1 = (const float*)d_in[21]; const float* Bk1 = (const float*)d_in[22];
    const float* gv1 = (const float*)d_in[23]; const float* Bv1 = (const float*)d_in[24];
    const float* gq2 = (const float*)d_in[25]; const float* Bq2 = (const float*)d_in[26];
    const float* gk2 = (const float*)d_in[27]; const float* Bk2 = (const float*)d_in[28];
    const float* gv2 = (const float*)d_in[29]; const float* Bv2 = (const float*)d_in[30];

    float* out = (float*)d_out;
    float* res = out + SZB;
    float* a2  = res + SSB;

    float* buf = nullptr;
    cudaGetSymbolAddress((void**)&buf, g_buf);
    char* P = (char*)buf;
    auto takeB = [&](long long bytes){ char* r = P; P += bytes; return r; };
    bf16* q_h  = (bf16*)takeB(SZB*2); bf16* q_l  = (bf16*)takeB(SZB*2);
    bf16* k_h  = (bf16*)takeB(SZB*2); bf16* k_l  = (bf16*)takeB(SZB*2);
    bf16* v_h  = (bf16*)takeB(SZB*2); bf16* v_l  = (bf16*)takeB(SZB*2);
    float* q1b = (float*)takeB(SZB*4);
    float* kb  = (float*)takeB(SZB*4);
    float* vb  = (float*)takeB(SZB*4);
    float* k2b = (float*)takeB(SZB*4);
    float* v2b = (float*)takeB(SZB*4);
    float* q2b = (float*)takeB(SZB*4);
    bf16* nq_h = (bf16*)takeB(SZB*2); bf16* nq_l = (bf16*)takeB(SZB*2);
    bf16* nk_h = (bf16*)takeB(SZB*2); bf16* nk_l = (bf16*)takeB(SZB*2);
    bf16* nv_h = (bf16*)takeB(SZB*2); bf16* nv_l = (bf16*)takeB(SZB*2);
    bf16* oa_h = (bf16*)takeB(SZB*2); bf16* oa_l = (bf16*)takeB(SZB*2);
    bf16* o1_h = (bf16*)takeB(SZB*2); bf16* o1_l = (bf16*)takeB(SZB*2);
    float* Sbuf= (float*)takeB(SSB*4);
    bf16* P_h  = (bf16*)takeB(SSB*2); bf16* P_l  = (bf16*)takeB(SSB*2);
    bf16* WTp  = (bf16*)takeB(8ll * 2 * WSZ * 2);
    auto WTh = [&](int i){ return WTp + (long long)i * 2 * WSZ; };
    auto WTl = [&](int i){ return WTp + (long long)i * 2 * WSZ + WSZ; };

    cudaFuncSetAttribute(gemm_bf3<1,true >, cudaFuncAttributeMaxDynamicSharedMemorySize, SMEMB);
    cudaFuncSetAttribute(gemm_bf3<1,false>, cudaFuncAttributeMaxDynamicSharedMemorySize, SMEMB);
    cudaFuncSetAttribute(gemm_bf3<2,true >, cudaFuncAttributeMaxDynamicSharedMemorySize, SMEMB);
    cudaFuncSetAttribute(gemm_bf3<5,true >, cudaFuncAttributeMaxDynamicSharedMemorySize, SMEMB);
    cudaFuncSetAttribute(gemm_nn,           cudaFuncAttributeMaxDynamicSharedMemorySize, SMEMB);
    cudaFuncSetAttribute(proj5_k,           cudaFuncAttributeMaxDynamicSharedMemorySize, SMEMB);

    const dim3 tb(32, 8);
    const dim3 gproj(8, 64, 1);
    const dim3 gproj5(8, 64, 5);
    const dim3 gS(16, 16, 4);
    const dim3 gO(8, 16, 4);
    const float it = 1.0f / 32.0f;
    const long long sLD = 2048ll*1024, sLL = 2048ll*2048;

    // prep
    Split3 s3;
    s3.x[0] = q; s3.h[0] = q_h; s3.l[0] = q_l;
    s3.x[1] = k; s3.h[1] = k_h; s3.l[1] = k_l;
    s3.x[2] = v; s3.h[2] = v_h; s3.l[2] = v_l;
    split3_k<<<dim3(SZB/4/256, 3), 256>>>(s3);
    W8 w8;
    for (int i = 0; i < 8; i++) { w8.w[i] = W[i]; w8.th[i] = WTh(i); w8.tl[i] = WTl(i); }
    tspw_k<<<dim3(32,32,8), tb>>>(w8);

    Proj5 p5;
    p5.Ah[0]=q_h; p5.Al[0]=q_l; p5.Bh[0]=WTh(0); p5.Bl[0]=WTl(0); p5.bias[0]=bW[0]; p5.Cf[0]=q1b;
    p5.Ah[1]=k_h; p5.Al[1]=k_l; p5.Bh[1]=WTh(1); p5.Bl[1]=WTl(1); p5.bias[1]=bW[1]; p5.Cf[1]=kb;
    p5.Ah[2]=v_h; p5.Al[2]=v_l; p5.Bh[2]=WTh(2); p5.Bl[2]=WTl(2); p5.bias[2]=bW[2]; p5.Cf[2]=vb;
    p5.Ah[3]=k_h; p5.Al[3]=k_l; p5.Bh[3]=WTh(5); p5.Bl[3]=WTl(5); p5.bias[3]=bW[5]; p5.Cf[3]=k2b;
    p5.Ah[4]=v_h; p5.Al[4]=v_l; p5.Bh[4]=WTh(6); p5.Bl[4]=WTl(6); p5.bias[4]=bW[6]; p5.Cf[4]=v2b;
    p5.res = res;
    proj5_k<<<gproj5, 256, SMEMB>>>(p5);

    // ---------------- layer 1 ----------------
    LN3 l1;
    l1.x[0]=q1b; l1.g[0]=gq1; l1.b[0]=Bq1; l1.yh[0]=nq_h; l1.yl[0]=nq_l;
    l1.x[1]=kb;  l1.g[1]=gk1; l1.b[1]=Bk1; l1.yh[1]=nk_h; l1.yl[1]=nk_l;
    l1.x[2]=vb;  l1.g[2]=gv1; l1.b[2]=Bv1; l1.yh[2]=nv_h; l1.yl[2]=nv_l;
    ln3_k<<<dim3(1024,3), 256>>>(l1);

    gemm_bf3<1,false><<<gS,256,SMEMB>>>(nq_h,nq_l, nk_h,nk_l, 0, Sbuf,0,0, 0,0, 2048,2048,1024, it, sLD,sLD,sLL);
    softmax_k<false><<<1024,256>>>(Sbuf, P_h, P_l);
    gemm_nn<<<gO,256,SMEMB>>>(P_h,P_l, nv_h,nv_l, oa_h,oa_l, 2048,1024,2048, sLL,sLD,sLD);
    gemm_bf3<2,true ><<<gproj,256,SMEMB>>>(oa_h,oa_l, WTh(3),WTl(3), bW[3], 0,o1_h,o1_l, 0,0, 8192,1024,1024, 1.f, 0,0,0);
    gemm_bf3<5,true ><<<gproj,256,SMEMB>>>(o1_h,o1_l, WTh(4),WTl(4), bW[4], q2b,0,0, res,1024, 8192,1024,1024, 1.f, 0,0,0);

    // ---------------- layer 2 ----------------
    LN3 l2;
    l2.x[0]=q2b; l2.g[0]=gq2; l2.b[0]=Bq2; l2.yh[0]=nq_h; l2.yl[0]=nq_l;
    l2.x[1]=k2b; l2.g[1]=gk2; l2.b[1]=Bk2; l2.yh[1]=nk_h; l2.yl[1]=nk_l;
    l2.x[2]=v2b; l2.g[2]=gv2; l2.b[2]=Bv2; l2.yh[2]=nv_h; l2.yl[2]=nv_l;
    ln3_k<<<dim3(1024,3), 256>>>(l2);

    gemm_bf3<1,false><<<gS,256,SMEMB>>>(nq_h,nq_l, nk_h,nk_l, 0, a2,0,0, 0,0, 2048,2048,1024, it, sLD,sLD,sLL);
    softmax_k<true><<<1024,256>>>(a2, P_h, P_l);
    gemm_nn<<<gO,256,SMEMB>>>(P_h,P_l, nv_h,nv_l, oa_h,oa_l, 2048,1024,2048, sLL,sLD,sLD);
    gemm_bf3<1,true ><<<gproj,256,SMEMB>>>(oa_h,oa_l, WTh(7),WTl(7), bW[7], out,0,0, 0,0, 8192,1024,1024, 1.f, 0,0,0);
}

// round 13
// speedup vs baseline: 1.4754x; 1.0722x over previous
#include <cuda_runtime.h>
#include <cuda_bf16.h>
#include <cstdint>

// ---------------------------------------------------------------------------
// B=4, L=2048, D=1024, fp32. Outputs: out(8.39M) | res(16.78M) | a2(16.78M).
// GEMMs via legacy mma.sync bf16, 2-term bf16 split (3 products).
// R13 = R12 with correct cp.async protocol: wait_group THEN __syncthreads
//       (R12 had them swapped -> cross-thread smem race -> NaN).
//       Prefetch remains embedded after the first MMA group.
// ---------------------------------------------------------------------------

#define SZB 8388608ll
#define SSB 16777216ll
#define WSZ 1048576ll

__device__ float g_buf[160000000ull];   // 640MB scratch pool

using bf16 = __nv_bfloat16;

__device__ __forceinline__ uint32_t smem_u32(const void* p){
    uint32_t a;
    asm("{ .reg .u64 t; cvta.to.shared.u64 t, %1; cvt.u32.u64 %0, t; }" : "=r"(a) : "l"(p));
    return a;
}
__device__ __forceinline__ uint32_t pack2(float x, float y){
    __nv_bfloat162 t = __floats2bfloat162_rn(x, y);
    return *(uint32_t*)&t;
}
__device__ __forceinline__ void split1(float x, float& h, float& l){
    h = __bfloat162float(__float2bfloat16(x));
    l = x - h;
}
// swizzled byte offset within a 128-row x 64B tile (A tiles, NT B tiles)
__device__ __forceinline__ uint32_t swz(uint32_t r, uint32_t c){
    return r * 64 + (((c ^ (r >> 1)) & 3) << 4) + (c & ~3u) * 16;
}
// swizzled byte offset within a 32-row x 256B tile (NN B tiles)
__device__ __forceinline__ uint32_t swzN(uint32_t r, uint32_t c){
    return r * 256 + ((c ^ (r & 7)) << 4);
}

#define LDSM4(R, addr) \
    asm volatile("ldmatrix.sync.aligned.m8n8.x4.shared.b16 {%0,%1,%2,%3}, [%4];" \
        : "=r"((R)[0]), "=r"((R)[1]), "=r"((R)[2]), "=r"((R)[3]) : "r"(addr))

#define LDSM4T(R, addr) \
    asm volatile("ldmatrix.sync.aligned.m8n8.x4.trans.shared.b16 {%0,%1,%2,%3}, [%4];" \
        : "=r"((R)[0]), "=r"((R)[1]), "=r"((R)[2]), "=r"((R)[3]) : "r"(addr))

#define MMA16816(d, a, b) \
    asm volatile("mma.sync.aligned.m16n8k16.row.col.f32.bf16.bf16.f32 " \
        "{%0,%1,%2,%3}, {%4,%5,%6,%7}, {%8,%9}, {%0,%1,%2,%3};" \
        : "+f"((d)[0]), "+f"((d)[1]), "+f"((d)[2]), "+f"((d)[3]) \
        : "r"((a)[0]), "r"((a)[1]), "r"((a)[2]), "r"((a)[3]), "r"((b)[0]), "r"((b)[1]))

#define CP_ASYNC16(dst, src) \
    asm volatile("cp.async.cg.shared.global [%0], [%1], 16;" :: "r"(dst), "l"(src))

constexpr int TILEB = 128 * 64;           // 8192 bytes (also 32x256 for NN B)
constexpr int STGB  = 4 * TILEB;          // 32768
constexpr int SMEMB = 3 * STGB;           // 98304

// ---------------------------------------------------------------------------
// NT GEMM: C = scale*(A @ B^T)(+bias). A[M,K], B[N,K] bf16 splits.
// OM bit0: fp32 C; bit1: bf16 split out; bit2: fp32 res write.
// ---------------------------------------------------------------------------
template<int OM, bool BIAS>
__global__ void __launch_bounds__(256, 2) gemm_bf3(
    const bf16* __restrict__ Ah, const bf16* __restrict__ Al,
    const bf16* __restrict__ Bh, const bf16* __restrict__ Bl,
    const float* __restrict__ bias,
    float* __restrict__ Cf, bf16* __restrict__ Ch, bf16* __restrict__ Cl,
    float* __restrict__ Cres, int resOff,
    int M, int N, int K, float scale,
    long long sA, long long sB, long long sC)
{
    extern __shared__ char sm[];
    const uint32_t sb = smem_u32(sm);
    const int tid = threadIdx.x, lane = tid & 31, warp = tid >> 5;
    const int wm = warp >> 2, wn = warp & 3;
    const int bz = blockIdx.z;
    Ah += bz * sA;  Al += bz * sA;
    Bh += bz * sB;  Bl += bz * sB;
    const long long co = (long long)bz * sC;
    const int m0 = blockIdx.y * 128, n0 = blockIdx.x * 128;

    auto load_stage = [&](int slot, int k0){
        const uint32_t s = sb + slot * STGB;
        const bf16* srcs[4] = {Ah, Al, Bh, Bl};
#pragma unroll
        for (int t = 0; t < 4; t++) {
            const bf16* src = srcs[t];
            const int rbase = (t < 2) ? m0 : n0;
#pragma unroll
            for (int i = 0; i < 2; i++) {
                const int c = tid + i * 256;
                const uint32_t row = c >> 2, ch = c & 3;
                const uint32_t dst = s + t * TILEB + swz(row, ch);
                const bf16* g = src + (long long)(rbase + row) * K + k0 + ch * 8;
                CP_ASYNC16(dst, g);
            }
        }
    };

    const int NS = K / 32;
    load_stage(0, 0);
    asm volatile("cp.async.commit_group;" ::: "memory");
    load_stage(1, 32);
    asm volatile("cp.async.commit_group;" ::: "memory");

    float acc[4][4][4] = {};
    int slot = 0;

    for (int s = 0; s < NS; s++) {
        asm volatile("cp.async.wait_group 1;" ::: "memory");
        __syncthreads();

        const uint32_t st  = sb + slot * STGB;
        const uint32_t tAh = st, tAl = st + TILEB, tBh = st + 2*TILEB, tBl = st + 3*TILEB;
        if (++slot == 3) slot = 0;

        // ---- ks = 0: first LDSM+MMA group, then embedded prefetch ----
        uint32_t a[4][4], bh[4][2], bl[4][2];
        {
            const uint32_t ach  = (lane >> 4);
            const uint32_t arow = wm * 64 + (lane & 15);
            const uint32_t brow = wn * 32 + (lane & 7) + ((lane >> 4) << 3);
            const uint32_t bch  = ((lane >> 3) & 1);
#pragma unroll
            for (int mi = 0; mi < 4; mi++)
                LDSM4(a[mi], tAh + swz(arow + mi * 16, ach));
#pragma unroll
            for (int pi = 0; pi < 2; pi++) {
                uint32_t v[4];
                LDSM4(v, tBh + swz(brow + pi * 16, bch));
                bh[2*pi][0] = v[0]; bh[2*pi][1] = v[1];
                bh[2*pi+1][0] = v[2]; bh[2*pi+1][1] = v[3];
            }
#pragma unroll
            for (int mi = 0; mi < 4; mi++)
#pragma unroll
                for (int ni = 0; ni < 4; ni++)
                    MMA16816(acc[mi][ni], a[mi], bh[ni]);

            // prefetch next stage, hidden under the MMAs above
            if (s + 2 < NS) {
                int ns = slot + 1; if (ns >= 3) ns -= 3;
                load_stage(ns, (s + 2) * 32);
            }
            asm volatile("cp.async.commit_group;" ::: "memory");

#pragma unroll
            for (int pi = 0; pi < 2; pi++) {
                uint32_t v[4];
                LDSM4(v, tBl + swz(brow + pi * 16, bch));
                bl[2*pi][0] = v[0]; bl[2*pi][1] = v[1];
                bl[2*pi+1][0] = v[2]; bl[2*pi+1][1] = v[3];
            }
#pragma unroll
            for (int mi = 0; mi < 4; mi++)
#pragma unroll
                for (int ni = 0; ni < 4; ni++)
                    MMA16816(acc[mi][ni], a[mi], bl[ni]);
#pragma unroll
            for (int mi = 0; mi < 4; mi++)
                LDSM4(a[mi], tAl + swz(arow + mi * 16, ach));
#pragma unroll
            for (int mi = 0; mi < 4; mi++)
#pragma unroll
                for (int ni = 0; ni < 4; ni++)
                    MMA16816(acc[mi][ni], a[mi], bh[ni]);
        }
        // ---- ks = 1 ----
        {
            const uint32_t ach  = 2 + (lane >> 4);
            const uint32_t arow = wm * 64 + (lane & 15);
            const uint32_t brow = wn * 32 + (lane & 7) + ((lane >> 4) << 3);
            const uint32_t bch  = 2 + ((lane >> 3) & 1);
#pragma unroll
            for (int mi = 0; mi < 4; mi++)
                LDSM4(a[mi], tAh + swz(arow + mi * 16, ach));
#pragma unroll
            for (int pi = 0; pi < 2; pi++) {
                uint32_t v[4];
                LDSM4(v, tBh + swz(brow + pi * 16, bch));
                bh[2*pi][0] = v[0]; bh[2*pi][1] = v[1];
                bh[2*pi+1][0] = v[2]; bh[2*pi+1][1] = v[3];
            }
#pragma unroll
            for (int mi = 0; mi < 4; mi++)
#pragma unroll
                for (int ni = 0; ni < 4; ni++)
                    MMA16816(acc[mi][ni], a[mi], bh[ni]);
#pragma unroll
            for (int pi = 0; pi < 2; pi++) {
                uint32_t v[4];
                LDSM4(v, tBl + swz(brow + pi * 16, bch));
                bl[2*pi][0] = v[0]; bl[2*pi][1] = v[1];
                bl[2*pi+1][0] = v[2]; bl[2*pi+1][1] = v[3];
            }
#pragma unroll
            for (int mi = 0; mi < 4; mi++)
#pragma unroll
                for (int ni = 0; ni < 4; ni++)
                    MMA16816(acc[mi][ni], a[mi], bl[ni]);
#pragma unroll
            for (int mi = 0; mi < 4; mi++)
                LDSM4(a[mi], tAl + swz(arow + mi * 16, ach));
#pragma unroll
            for (int mi = 0; mi < 4; mi++)
#pragma unroll
                for (int ni = 0; ni < 4; ni++)
                    MMA16816(acc[mi][ni], a[mi], bh[ni]);
        }
    }

#pragma unroll
    for (int mi = 0; mi < 4; mi++) {
        const int r0 = m0 + wm * 64 + mi * 16 + (lane >> 2);
#pragma unroll
        for (int ni = 0; ni < 4; ni++) {
            const int col = n0 + wn * 32 + ni * 8 + (lane & 3) * 2;
            float b0 = 0.f, b1 = 0.f;
            if (BIAS) { b0 = __ldg(bias + col); b1 = __ldg(bias + col + 1); }
            const float x0 = acc[mi][ni][0] * scale + b0;
            const float x1 = acc[mi][ni][1] * scale + b1;
            const float x2 = acc[mi][ni][2] * scale + b0;
            const float x3 = acc[mi][ni][3] * scale + b1;
            const long long g0 = co + (long long)r0 * N + col;
            const long long g1 = co + (long long)(r0 + 8) * N + col;
            if (OM & 1) {
                *(float2*)(Cf + g0) = make_float2(x0, x1);
                *(float2*)(Cf + g1) = make_float2(x2, x3);
            }
            if (OM & 2) {
                float h0, l0, h1, l1, h2, l2, h3, l3;
                split1(x0, h0, l0); split1(x1, h1, l1);
                split1(x2, h2, l2); split1(x3, h3, l3);
                *(uint32_t*)(Ch + g0) = pack2(h0, h1);
                *(uint32_t*)(Ch + g1) = pack2(h2, h3);
                *(uint32_t*)(Cl + g0) = pack2(l0, l1);
                *(uint32_t*)(Cl + g1) = pack2(l2, l3);
            }
            if (OM & 4) {
                const long long rg0 = (long long)r0 * 2048 + resOff + col;
                const long long rg1 = (long long)(r0 + 8) * 2048 + resOff + col;
                *(float2*)(Cres + rg0) = make_float2(x0, x1);
                *(float2*)(Cres + rg1) = make_float2(x2, x3);
            }
        }
    }
}

// ---------------------------------------------------------------------------
// NN GEMM: C = A @ B, A[M,K], B[K,N] (row-major), bf16 splits; out = bf16 split.
// ---------------------------------------------------------------------------
__global__ void __launch_bounds__(256, 2) gemm_nn(
    const bf16* __restrict__ Ah, const bf16* __restrict__ Al,
    const bf16* __restrict__ Bh, const bf16* __restrict__ Bl,
    bf16* __restrict__ Ch, bf16* __restrict__ Cl,
    int M, int N, int K,
    long long sA, long long sB, long long sC)
{
    extern __shared__ char sm[];
    const uint32_t sb = smem_u32(sm);
    const int tid = threadIdx.x, lane = tid & 31, warp = tid >> 5;
    const int wm = warp >> 2, wn = warp & 3;
    const int bz = blockIdx.z;
    Ah += bz * sA;  Al += bz * sA;
    Bh += bz * sB;  Bl += bz * sB;
    const long long co = (long long)bz * sC;
    const int m0 = blockIdx.y * 128, n0 = blockIdx.x * 128;

    auto load_stage = [&](int slot, int k0){
        const uint32_t s = sb + slot * STGB;
#pragma unroll
        for (int i = 0; i < 2; i++) {
            const int c = tid + i * 256;
            const uint32_t row = c >> 2, ch = c & 3;
            const long long g = (long long)(m0 + row) * K + k0 + ch * 8;
            CP_ASYNC16(s + swz(row, ch),          Ah + g);
            CP_ASYNC16(s + TILEB + swz(row, ch),  Al + g);
        }
#pragma unroll
        for (int i = 0; i < 2; i++) {
            const int c = tid + i * 256;
            const uint32_t row = c >> 4, ch = c & 15;
            const long long g = (long long)(k0 + row) * N + n0 + ch * 8;
            CP_ASYNC16(s + 2*TILEB + swzN(row, ch), Bh + g);
            CP_ASYNC16(s + 3*TILEB + swzN(row, ch), Bl + g);
        }
    };

    const int NS = K / 32;
    load_stage(0, 0);
    asm volatile("cp.async.commit_group;" ::: "memory");
    load_stage(1, 32);
    asm volatile("cp.async.commit_group;" ::: "memory");

    float acc[4][4][4] = {};
    int slot = 0;

    for (int s = 0; s < NS; s++) {
        asm volatile("cp.async.wait_group 1;" ::: "memory");
        __syncthreads();

        const uint32_t st  = sb + slot * STGB;
        const uint32_t tAh = st, tAl = st + TILEB, tBh = st + 2*TILEB, tBl = st + 3*TILEB;
        if (++slot == 3) slot = 0;

        uint32_t a[4][4], bh[4][2], bl[4][2];
        // ---- ks = 0 with embedded prefetch ----
        {
            const uint32_t ach  = (lane >> 4);
            const uint32_t arow = wm * 64 + (lane & 15);
            const uint32_t brr  = (lane & 7) + (((lane >> 3) & 1) << 3);
#pragma unroll
            for (int mi = 0; mi < 4; mi++)
                LDSM4(a[mi], tAh + swz(arow + mi * 16, ach));
#pragma unroll
            for (int pi = 0; pi < 2; pi++) {
                const uint32_t bcc = ((wn * 32 + pi * 16) >> 3) + (lane >> 4);
                uint32_t v[4];
                LDSM4T(v, tBh + swzN(brr, bcc));
                bh[2*pi][0] = v[0]; bh[2*pi][1] = v[1];
                bh[2*pi+1][0] = v[2]; bh[2*pi+1][1] = v[3];
            }
#pragma unroll
            for (int mi = 0; mi < 4; mi++)
#pragma unroll
                for (int ni = 0; ni < 4; ni++)
                    MMA16816(acc[mi][ni], a[mi], bh[ni]);

            if (s + 2 < NS) {
                int ns = slot + 1; if (ns >= 3) ns -= 3;
                load_stage(ns, (s + 2) * 32);
            }
            asm volatile("cp.async.commit_group;" ::: "memory");

#pragma unroll
            for (int pi = 0; pi < 2; pi++) {
                const uint32_t bcc = ((wn * 32 + pi * 16) >> 3) + (lane >> 4);
                uint32_t v[4];
                LDSM4T(v, tBl + swzN(brr, bcc));
                bl[2*pi][0] = v[0]; bl[2*pi][1] = v[1];
                bl[2*pi+1][0] = v[2]; bl[2*pi+1][1] = v[3];
            }
#pragma unroll
            for (int mi = 0; mi < 4; mi++)
#pragma unroll
                for (int ni = 0; ni < 4; ni++)
                    MMA16816(acc[mi][ni], a[mi], bl[ni]);
#pragma unroll
            for (int mi = 0; mi < 4; mi++)
                LDSM4(a[mi], tAl + swz(arow + mi * 16, ach));
#pragma unroll
            for (int mi = 0; mi < 4; mi++)
#pragma unroll
                for (int ni = 0; ni < 4; ni++)
                    MMA16816(acc[mi][ni], a[mi], bh[ni]);
        }
        // ---- ks = 1 ----
        {
            const uint32_t ach  = 2 + (lane >> 4);
            const uint32_t arow = wm * 64 + (lane & 15);
            const uint32_t brr  = 16 + (lane & 7) + (((lane >> 3) & 1) << 3);
#pragma unroll
            for (int mi = 0; mi < 4; mi++)
                LDSM4(a[mi], tAh + swz(arow + mi * 16, ach));
#pragma unroll
            for (int pi = 0; pi < 2; pi++) {
                const uint32_t bcc = ((wn * 32 + pi * 16) >> 3) + (lane >> 4);
                uint32_t v[4];
                LDSM4T(v, tBh + swzN(brr, bcc));
                bh[2*pi][0] = v[0]; bh[2*pi][1] = v[1];
                bh[2*pi+1][0] = v[2]; bh[2*pi+1][1] = v[3];
            }
#pragma unroll
            for (int mi = 0; mi < 4; mi++)
#pragma unroll
                for (int ni = 0; ni < 4; ni++)
                    MMA16816(acc[mi][ni], a[mi], bh[ni]);
#pragma unroll
            for (int pi = 0; pi < 2; pi++) {
                const uint32_t bcc = ((wn * 32 + pi * 16) >> 3) + (lane >> 4);
                uint32_t v[4];
                LDSM4T(v, tBl + swzN(brr, bcc));
                bl[2*pi][0] = v[0]; bl[2*pi][1] = v[1];
                bl[2*pi+1][0] = v[2]; bl[2*pi+1][1] = v[3];
            }
#pragma unroll
            for (int mi = 0; mi < 4; mi++)
#pragma unroll
                for (int ni = 0; ni < 4; ni++)
                    MMA16816(acc[mi][ni], a[mi], bl[ni]);
#pragma unroll
            for (int mi = 0; mi < 4; mi++)
                LDSM4(a[mi], tAl + swz(arow + mi * 16, ach));
#pragma unroll
            for (int mi = 0; mi < 4; mi++)
#pragma unroll
                for (int ni = 0; ni < 4; ni++)
                    MMA16816(acc[mi][ni], a[mi], bh[ni]);
        }
    }

#pragma unroll
    for (int mi = 0; mi < 4; mi++) {
        const int r0 = m0 + wm * 64 + mi * 16 + (lane >> 2);
#pragma unroll
        for (int ni = 0; ni < 4; ni++) {
            const int col = n0 + wn * 32 + ni * 8 + (lane & 3) * 2;
            const float x0 = acc[mi][ni][0], x1 = acc[mi][ni][1];
            const float x2 = acc[mi][ni][2], x3 = acc[mi][ni][3];
            const long long g0 = co + (long long)r0 * N + col;
            const long long g1 = co + (long long)(r0 + 8) * N + col;
            float h0, l0, h1, l1, h2, l2, h3, l3;
            split1(x0, h0, l0); split1(x1, h1, l1);
            split1(x2, h2, l2); split1(x3, h3, l3);
            *(uint32_t*)(Ch + g0) = pack2(h0, h1);
            *(uint32_t*)(Ch + g1) = pack2(h2, h3);
            *(uint32_t*)(Cl + g0) = pack2(l0, l1);
            *(uint32_t*)(Cl + g1) = pack2(l2, l3);
        }
    }
}

// ---------------------------------------------------------------------------
// 5-way fused projection GEMM. z==0 additionally writes fp32 res at col 0.
// ---------------------------------------------------------------------------
struct Proj5 {
    const bf16* Ah[5]; const bf16* Al[5];
    const bf16* Bh[5]; const bf16* Bl[5];
    const float* bias[5];
    float* Cf[5];
    float* res;
};

__global__ void __launch_bounds__(256, 2) proj5_k(Proj5 j)
{
    extern __shared__ char sm[];
    const uint32_t sb = smem_u32(sm);
    const int tid = threadIdx.x, lane = tid & 31, warp = tid >> 5;
    const int wm = warp >> 2, wn = warp & 3;
    const int z = blockIdx.z;
    const bf16* Ah = j.Ah[z]; const bf16* Al = j.Al[z];
    const bf16* Bh = j.Bh[z]; const bf16* Bl = j.Bl[z];
    const float* bias = j.bias[z];
    float* Cf = j.Cf[z];
    const int m0 = blockIdx.y * 128, n0 = blockIdx.x * 128;
    constexpr int K = 1024, N = 1024;

    auto load_stage = [&](int slot, int k0){
        const uint32_t s = sb + slot * STGB;
        const bf16* srcs[4] = {Ah, Al, Bh, Bl};
#pragma unroll
        for (int t = 0; t < 4; t++) {
            const bf16* src = srcs[t];
            const int rbase = (t < 2) ? m0 : n0;
#pragma unroll
            for (int i = 0; i < 2; i++) {
                const int c = tid + i * 256;
                const uint32_t row = c >> 2, ch = c & 3;
                const uint32_t dst = s + t * TILEB + swz(row, ch);
                const bf16* g = src + (long long)(rbase + row) * K + k0 + ch * 8;
                CP_ASYNC16(dst, g);
            }
        }
    };

    const int NS = K / 32;
    load_stage(0, 0);
    asm volatile("cp.async.commit_group;" ::: "memory");
    load_stage(1, 32);
    asm volatile("cp.async.commit_group;" ::: "memory");

    float acc[4][4][4] = {};
    int slot = 0;

    for (int s = 0; s < NS; s++) {
        asm volatile("cp.async.wait_group 1;" ::: "memory");
        __syncthreads();

        const uint32_t st  = sb + slot * STGB;
        const uint32_t tAh = st, tAl = st + TILEB, tBh = st + 2*TILEB, tBl = st + 3*TILEB;
        if (++slot == 3) slot = 0;

        uint32_t a[4][4], bh[4][2], bl[4][2];
        // ks = 0 with embedded prefetch
        {
            const uint32_t ach  = (lane >> 4);
            const uint32_t arow = wm * 64 + (lane & 15);
            const uint32_t brow = wn * 32 + (lane & 7) + ((lane >> 4) << 3);
            const uint32_t bch  = ((lane >> 3) & 1);
#pragma unroll
            for (int mi = 0; mi < 4; mi++)
                LDSM4(a[mi], tAh + swz(arow + mi * 16, ach));
#pragma unroll
            for (int pi = 0; pi < 2; pi++) {
                uint32_t v[4];
                LDSM4(v, tBh + swz(brow + pi * 16, bch));
                bh[2*pi][0] = v[0]; bh[2*pi][1] = v[1];
                bh[2*pi+1][0] = v[2]; bh[2*pi+1][1] = v[3];
            }
#pragma unroll
            for (int mi = 0; mi < 4; mi++)
#pragma unroll
                for (int ni = 0; ni < 4; ni++)
                    MMA16816(acc[mi][ni], a[mi], bh[ni]);

            if (s + 2 < NS) {
                int ns = slot + 1; if (ns >= 3) ns -= 3;
                load_stage(ns, (s + 2) * 32);
            }
            asm volatile("cp.async.commit_group;" ::: "memory");

#pragma unroll
            for (int pi = 0; pi < 2; pi++) {
                uint32_t v[4];
                LDSM4(v, tBl + swz(brow + pi * 16, bch));
                bl[2*pi][0] = v[0]; bl[2*pi][1] = v[1];
                bl[2*pi+1][0] = v[2]; bl[2*pi+1][1] = v[3];
            }
#pragma unroll
            for (int mi = 0; mi < 4; mi++)
#pragma unroll
                for (int ni = 0; ni < 4; ni++)
                    MMA16816(acc[mi][ni], a[mi], bl[ni]);
#pragma unroll
            for (int mi = 0; mi < 4; mi++)
                LDSM4(a[mi], tAl + swz(arow + mi * 16, ach));
#pragma unroll
            for (int mi = 0; mi < 4; mi++)
#pragma unroll
                for (int ni = 0; ni < 4; ni++)
                    MMA16816(acc[mi][ni], a[mi], bh[ni]);
        }
        // ks = 1
        {
            const uint32_t ach  = 2 + (lane >> 4);
            const uint32_t arow = wm * 64 + (lane & 15);
            const uint32_t brow = wn * 32 + (lane & 7) + ((lane >> 4) << 3);
            const uint32_t bch  = 2 + ((lane >> 3) & 1);
#pragma unroll
            for (int mi = 0; mi < 4; mi++)
                LDSM4(a[mi], tAh + swz(arow + mi * 16, ach));
#pragma unroll
            for (int pi = 0; pi < 2; pi++) {
                uint32_t v[4];
                LDSM4(v, tBh + swz(brow + pi * 16, bch));
                bh[2*pi][0] = v[0]; bh[2*pi][1] = v[1];
                bh[2*pi+1][0] = v[2]; bh[2*pi+1][1] = v[3];
            }
#pragma unroll
            for (int mi = 0; mi < 4; mi++)
#pragma unroll
                for (int ni = 0; ni < 4; ni++)
                    MMA16816(acc[mi][ni], a[mi], bh[ni]);
#pragma unroll
            for (int pi = 0; pi < 2; pi++) {
                uint32_t v[4];
                LDSM4(v, tBl + swz(brow + pi * 16, bch));
                bl[2*pi][0] = v[0]; bl[2*pi][1] = v[1];
                bl[2*pi+1][0] = v[2]; bl[2*pi+1][1] = v[3];
            }
#pragma unroll
            for (int mi = 0; mi < 4; mi++)
#pragma unroll
                for (int ni = 0; ni < 4; ni++)
                    MMA16816(acc[mi][ni], a[mi], bl[ni]);
#pragma unroll
            for (int mi = 0; mi < 4; mi++)
                LDSM4(a[mi], tAl + swz(arow + mi * 16, ach));
#pragma unroll
            for (int mi = 0; mi < 4; mi++)
#pragma unroll
                for (int ni = 0; ni < 4; ni++)
                    MMA16816(acc[mi][ni], a[mi], bh[ni]);
        }
    }

    const bool doRes = (z == 0);
#pragma unroll
    for (int mi = 0; mi < 4; mi++) {
        const int r0 = m0 + wm * 64 + mi * 16 + (lane >> 2);
#pragma unroll
        for (int ni = 0; ni < 4; ni++) {
            const int col = n0 + wn * 32 + ni * 8 + (lane & 3) * 2;
            const float b0 = __ldg(bias + col), b1 = __ldg(bias + col + 1);
            const float x0 = acc[mi][ni][0] + b0;
            const float x1 = acc[mi][ni][1] + b1;
            const float x2 = acc[mi][ni][2] + b0;
            const float x3 = acc[mi][ni][3] + b1;
            const long long g0 = (long long)r0 * N + col;
            const long long g1 = (long long)(r0 + 8) * N + col;
            *(float2*)(Cf + g0) = make_float2(x0, x1);
            *(float2*)(Cf + g1) = make_float2(x2, x3);
            if (doRes) {
                *(float2*)(j.res + (long long)r0 * 2048 + col)       = make_float2(x0, x1);
                *(float2*)(j.res + (long long)(r0 + 8) * 2048 + col) = make_float2(x2, x3);
            }
        }
    }
}

// ---------------------------------------------------------------------------
struct Split3 { const float* x[3]; bf16* h[3]; bf16* l[3]; };

__global__ void __launch_bounds__(256) split3_k(Split3 j)
{
    const int z = blockIdx.y;
    const float* x = j.x[z];
    bf16* h = j.h[z]; bf16* l = j.l[z];
    const long long i = ((long long)blockIdx.x * 256 + threadIdx.x) * 4;
    const float4 v = *(const float4*)(x + i);
    float h0,l0,h1,l1,h2,l2,h3,l3;
    split1(v.x,h0,l0); split1(v.y,h1,l1); split1(v.z,h2,l2); split1(v.w,h3,l3);
    uint2 hp, lp;
    hp.x = pack2(h0,h1); hp.y = pack2(h2,h3);
    lp.x = pack2(l0,l1); lp.y = pack2(l2,l3);
    *(uint2*)(h + i) = hp;
    *(uint2*)(l + i) = lp;
}

struct W8 { const float* w[8]; bf16* th[8]; bf16* tl[8]; };

__global__ void __launch_bounds__(256) tspw_k(W8 j)
{
    __shared__ float t[32][33];
    const int z = blockIdx.z;
    const float* X = j.w[z];
    bf16* Th = j.th[z]; bf16* Tl = j.tl[z];
    const int c0 = blockIdx.x * 32, r0 = blockIdx.y * 32;
    const int tx = threadIdx.x, ty = threadIdx.y;
#pragma unroll
    for (int i = 0; i < 4; i++)
        t[ty + i * 8][tx] = X[(long long)(r0 + ty + i * 8) * 1024 + c0 + tx];
    __syncthreads();
#pragma unroll
    for (int i = 0; i < 4; i++) {
        const float v = t[tx][ty + i * 8];
        float h, l; split1(v, h, l);
        const long long g = (long long)(c0 + ty + i * 8) * 1024 + r0 + tx;
        Th[g] = __float2bfloat16(h);
        Tl[g] = __float2bfloat16(l);
    }
}

// ---------------------------------------------------------------------------
struct LN3 {
    const float* x[3]; const float* g[3]; const float* b[3];
    bf16* yh[3]; bf16* yl[3];
};

__global__ void __launch_bounds__(256) ln3_k(LN3 j)
{
    const int z = blockIdx.y;
    const int lane = threadIdx.x & 31, warp = threadIdx.x >> 5;
    const long long row = (long long)blockIdx.x * 8 + warp;

    const float4* xr = (const float4*)(j.x[z] + row * 1024);
    float4 xv[8];
#pragma unroll
    for (int i = 0; i < 8; i++) xv[i] = xr[lane + i * 32];

    float s = 0.f, s2 = 0.f;
#pragma unroll
    for (int i = 0; i < 8; i++) {
        s  += xv[i].x + xv[i].y + xv[i].z + xv[i].w;
        s2 += xv[i].x*xv[i].x + xv[i].y*xv[i].y + xv[i].z*xv[i].z + xv[i].w*xv[i].w;
    }
#pragma unroll
    for (int o = 16; o > 0; o >>= 1) {
        s  += __shfl_xor_sync(0xffffffffu, s, o);
        s2 += __shfl_xor_sync(0xffffffffu, s2, o);
    }
    const float mean = s * (1.0f / 1024.0f);
    const float var  = s2 * (1.0f / 1024.0f) - mean * mean;
    const float inv  = rsqrtf(var + 1e-6f);

    const float4* gr = (const float4*)j.g[z];
    const float4* br = (const float4*)j.b[z];
    uint2* yh = (uint2*)(j.yh[z] + row * 1024);
    uint2* yl = (uint2*)(j.yl[z] + row * 1024);
#pragma unroll
    for (int i = 0; i < 8; i++) {
        const float4 gg = gr[lane + i * 32];
        const float4 bb = br[lane + i * 32];
        float4 o;
        o.x = (xv[i].x - mean) * inv * gg.x + bb.x;
        o.y = (xv[i].y - mean) * inv * gg.y + bb.y;
        o.z = (xv[i].z - mean) * inv * gg.z + bb.z;
        o.w = (xv[i].w - mean) * inv * gg.w + bb.w;
        float h0,l0,h1,l1,h2,l2,h3,l3;
        split1(o.x,h0,l0); split1(o.y,h1,l1); split1(o.z,h2,l2); split1(o.w,h3,l3);
        uint2 hp, lp;
        hp.x = pack2(h0,h1); hp.y = pack2(h2,h3);
        lp.x = pack2(l0,l1); lp.y = pack2(l2,l3);
        yh[lane + i * 32] = hp;
        yl[lane + i * 32] = lp;
    }
}

// ---------------------------------------------------------------------------
template<bool F32OUT>
__global__ void __launch_bounds__(256) softmax_k(
    float* __restrict__ S, bf16* __restrict__ Ph, bf16* __restrict__ Pl)
{
    const int lane = threadIdx.x & 31, warp = threadIdx.x >> 5;
    const long long row = (long long)blockIdx.x * 8 + warp;
    float4* r4 = (float4*)(S + row * 2048);

    float4 v[16];
#pragma unroll
    for (int i = 0; i < 16; i++) v[i] = r4[lane + i * 32];

    float mx = v[0].x;
#pragma unroll
    for (int i = 0; i < 16; i++) {
        mx = fmaxf(mx, fmaxf(fmaxf(v[i].x, v[i].y), fmaxf(v[i].z, v[i].w)));
    }
#pragma unroll
    for (int o = 16; o > 0; o >>= 1) mx = fmaxf(mx, __shfl_xor_sync(0xffffffffu, mx, o));

    float sum = 0.f;
#pragma unroll
    for (int i = 0; i < 16; i++) {
        v[i].x = __expf(v[i].x - mx); v[i].y = __expf(v[i].y - mx);
        v[i].z = __expf(v[i].z - mx); v[i].w = __expf(v[i].w - mx);
        sum += v[i].x + v[i].y + v[i].z + v[i].w;
    }
#pragma unroll
    for (int o = 16; o > 0; o >>= 1) sum += __shfl_xor_sync(0xffffffffu, sum, o);
    const float inv = 1.0f / sum;

    uint2* ph = (uint2*)(Ph + row * 2048);
    uint2* pl = (uint2*)(Pl + row * 2048);
#pragma unroll
    for (int i = 0; i < 16; i++) {
        float4 p;
        p.x = v[i].x * inv; p.y = v[i].y * inv;
        p.z = v[i].z * inv; p.w = v[i].w * inv;
        float h0,l0,h1,l1,h2,l2,h3,l3;
        split1(p.x,h0,l0); split1(p.y,h1,l1); split1(p.z,h2,l2); split1(p.w,h3,l3);
        uint2 hp, lp;
        hp.x = pack2(h0,h1); hp.y = pack2(h2,h3);
        lp.x = pack2(l0,l1); lp.y = pack2(l2,l3);
        ph[lane + i * 32] = hp;
        pl[lane + i * 32] = lp;
        if (F32OUT) r4[lane + i * 32] = p;
    }
}

// ---------------------------------------------------------------------------
extern "C" void kernel_launch(void* const* d_in, const int* in_sizes, int n_in,
                              void* d_out, int out_size)
{
    const float* q = (const float*)d_in[0];
    const float* k = (const float*)d_in[1];
    const float* v = (const float*)d_in[2];
    const float* W[8]  = {(const float*)d_in[3],  (const float*)d_in[5],
                          (const float*)d_in[7],  (const float*)d_in[9],
                          (const float*)d_in[11], (const float*)d_in[13],
                          (const float*)d_in[15], (const float*)d_in[17]};
    const float* bW[8] = {(const float*)d_in[4],  (const float*)d_in[6],
                          (const float*)d_in[8],  (const float*)d_in[10],
                          (const float*)d_in[12], (const float*)d_in[14],
                          (const float*)d_in[16], (const float*)d_in[18]};
    const float* gq1 = (const float*)d_in[19]; const float* Bq1 = (const float*)d_in[20];
    const float* gk1 = (const float*)d_in[21]; const float* Bk1 = (const float*)d_in[22];
    const float* gv1 = (const float*)d_in[23]; const float* Bv1 = (const float*)d_in[24];
    const float* gq2 = (const float*)d_in[25]; const float* Bq2 = (const float*)d_in[26];
    const float* gk2 = (const float*)d_in[27]; const float* Bk2 = (const float*)d_in[28];
    const float* gv2 = (const float*)d_in[29]; const float* Bv2 = (const float*)d_in[30];

    float* out = (float*)d_out;
    float* res = out + SZB;
    float* a2  = res + SSB;

    float* buf = nullptr;
    cudaGetSymbolAddress((void**)&buf, g_buf);
    char* P = (char*)buf;
    auto takeB = [&](long long bytes){ char* r = P; P += bytes; return r; };
    bf16* q_h  = (bf16*)takeB(SZB*2); bf16* q_l  = (bf16*)takeB(SZB*2);
    bf16* k_h  = (bf16*)takeB(SZB*2); bf16* k_l  = (bf16*)takeB(SZB*2);
    bf16* v_h  = (bf16*)takeB(SZB*2); bf16* v_l  = (bf16*)takeB(SZB*2);
    float* q1b = (float*)takeB(SZB*4);
    float* kb  = (float*)takeB(SZB*4);
    float* vb  = (float*)takeB(SZB*4);
    float* k2b = (float*)takeB(SZB*4);
    float* v2b = (float*)takeB(SZB*4);
    float* q2b = (float*)takeB(SZB*4);
    bf16* nq_h = (bf16*)takeB(SZB*2); bf16* nq_l = (bf16*)takeB(SZB*2);
    bf16* nk_h = (bf16*)takeB(SZB*2); bf16* nk_l = (bf16*)takeB(SZB*2);
    bf16* nv_h = (bf16*)takeB(SZB*2); bf16* nv_l = (bf16*)takeB(SZB*2);
    bf16* oa_h = (bf16*)takeB(SZB*2); bf16* oa_l = (bf16*)takeB(SZB*2);
    bf16* o1_h = (bf16*)takeB(SZB*2); bf16* o1_l = (bf16*)takeB(SZB*2);
    float* Sbuf= (float*)takeB(SSB*4);
    bf16* P_h  = (bf16*)takeB(SSB*2); bf16* P_l  = (bf16*)takeB(SSB*2);
    bf16* WTp  = (bf16*)takeB(8ll * 2 * WSZ * 2);
    auto WTh = [&](int i){ return WTp + (long long)i * 2 * WSZ; };
    auto WTl = [&](int i){ return WTp + (long long)i * 2 * WSZ + WSZ; };

    cudaFuncSetAttribute(gemm_bf3<1,true >, cudaFuncAttributeMaxDynamicSharedMemorySize, SMEMB);
    cudaFuncSetAttribute(gemm_bf3<1,false>, cudaFuncAttributeMaxDynamicSharedMemorySize, SMEMB);
    cudaFuncSetAttribute(gemm_bf3<2,true >, cudaFuncAttributeMaxDynamicSharedMemorySize, SMEMB);
    cudaFuncSetAttribute(gemm_bf3<5,true >, cudaFuncAttributeMaxDynamicSharedMemorySize, SMEMB);
    cudaFuncSetAttribute(gemm_nn,           cudaFuncAttributeMaxDynamicSharedMemorySize, SMEMB);
    cudaFuncSetAttribute(proj5_k,           cudaFuncAttributeMaxDynamicSharedMemorySize, SMEMB);

    const dim3 tb(32, 8);
    const dim3 gproj(8, 64, 1);
    const dim3 gproj5(8, 64, 5);
    const dim3 gS(16, 16, 4);
    const dim3 gO(8, 16, 4);
    const float it = 1.0f / 32.0f;
    const long long sLD = 2048ll*1024, sLL = 2048ll*2048;

    // prep
    Split3 s3;
    s3.x[0] = q; s3.h[0] = q_h; s3.l[0] = q_l;
    s3.x[1] = k; s3.h[1] = k_h; s3.l[1] = k_l;
    s3.x[2] = v; s3.h[2] = v_h; s3.l[2] = v_l;
    split3_k<<<dim3(SZB/4/256, 3), 256>>>(s3);
    W8 w8;
    for (int i = 0; i < 8; i++) { w8.w[i] = W[i]; w8.th[i] = WTh(i); w8.tl[i] = WTl(i); }
    tspw_k<<<dim3(32,32,8), tb>>>(w8);

    Proj5 p5;
    p5.Ah[0]=q_h; p5.Al[0]=q_l; p5.Bh[0]=WTh(0); p5.Bl[0]=WTl(0); p5.bias[0]=bW[0]; p5.Cf[0]=q1b;
    p5.Ah[1]=k_h; p5.Al[1]=k_l; p5.Bh[1]=WTh(1); p5.Bl[1]=WTl(1); p5.bias[1]=bW[1]; p5.Cf[1]=kb;
    p5.Ah[2]=v_h; p5.Al[2]=v_l; p5.Bh[2]=WTh(2); p5.Bl[2]=WTl(2); p5.bias[2]=bW[2]; p5.Cf[2]=vb;
    p5.Ah[3]=k_h; p5.Al[3]=k_l; p5.Bh[3]=WTh(5); p5.Bl[3]=WTl(5); p5.bias[3]=bW[5]; p5.Cf[3]=k2b;
    p5.Ah[4]=v_h; p5.Al[4]=v_l; p5.Bh[4]=WTh(6); p5.Bl[4]=WTl(6); p5.bias[4]=bW[6]; p5.Cf[4]=v2b;
    p5.res = res;
    proj5_k<<<gproj5, 256, SMEMB>>>(p5);

    // ---------------- layer 1 ----------------
    LN3 l1;
    l1.x[0]=q1b; l1.g[0]=gq1; l1.b[0]=Bq1; l1.yh[0]=nq_h; l1.yl[0]=nq_l;
    l1.x[1]=kb;  l1.g[1]=gk1; l1.b[1]=Bk1; l1.yh[1]=nk_h; l1.yl[1]=nk_l;
    l1.x[2]=vb;  l1.g[2]=gv1; l1.b[2]=Bv1; l1.yh[2]=nv_h; l1.yl[2]=nv_l;
    ln3_k<<<dim3(1024,3), 256>>>(l1);

    gemm_bf3<1,false><<<gS,256,SMEMB>>>(nq_h,nq_l, nk_h,nk_l, 0, Sbuf,0,0, 0,0, 2048,2048,1024, it, sLD,sLD,sLL);
    softmax_k<false><<<1024,256>>>(Sbuf, P_h, P_l);
    gemm_nn<<<gO,256,SMEMB>>>(P_h,P_l, nv_h,nv_l, oa_h,oa_l, 2048,1024,2048, sLL,sLD,sLD);
    gemm_bf3<2,true ><<<gproj,256,SMEMB>>>(oa_h,oa_l, WTh(3),WTl(3), bW[3], 0,o1_h,o1_l, 0,0, 8192,1024,1024, 1.f, 0,0,0);
    gemm_bf3<5,true ><<<gproj,256,SMEMB>>>(o1_h,o1_l, WTh(4),WTl(4), bW[4], q2b,0,0, res,1024, 8192,1024,1024, 1.f, 0,0,0);

    // ---------------- layer 2 ----------------
    LN3 l2;
    l2.x[0]=q2b; l2.g[0]=gq2; l2.b[0]=Bq2; l2.yh[0]=nq_h; l2.yl[0]=nq_l;
    l2.x[1]=k2b; l2.g[1]=gk2; l2.b[1]=Bk2; l2.yh[1]=nk_h; l2.yl[1]=nk_l;
    l2.x[2]=v2b; l2.g[2]=gv2; l2.b[2]=Bv2; l2.yh[2]=nv_h; l2.yl[2]=nv_l;
    ln3_k<<<dim3(1024,3), 256>>>(l2);

    gemm_bf3<1,false><<<gS,256,SMEMB>>>(nq_h,nq_l, nk_h,nk_l, 0, a2,0,0, 0,0, 2048,2048,1024, it, sLD,sLD,sLL);
    softmax_k<true><<<1024,256>>>(a2, P_h, P_l);
    gemm_nn<<<gO,256,SMEMB>>>(P_h,P_l, nv_h,nv_l, oa_h,oa_l, 2048,1024,2048, sLL,sLD,sLD);
    gemm_bf3<1,true ><<<gproj,256,SMEMB>>>(oa_h,oa_l, WTh(7),WTl(7), bW[7], out,0,0, 0,0, 8192,1024,1024, 1.f, 0,0,0);
}

// round 14
// speedup vs baseline: 1.4799x; 1.0030x over previous
#include <cuda_runtime.h>
#include <cuda_bf16.h>
#include <cstdint>

// ---------------------------------------------------------------------------
// B=4, L=2048, D=1024, fp32. Outputs: out(8.39M) | res(16.78M) | a2(16.78M).
// GEMMs via legacy mma.sync bf16, 2-term bf16 split (3 products).
// R14 = R13 + algebraic fusion: q2 = oa @ (Wf1*Wq2) + (bf1*Wq2 + bq2),
//       eliminating the o1 intermediate projection entirely.
// ---------------------------------------------------------------------------

#define SZB 8388608ll
#define SSB 16777216ll
#define WSZ 1048576ll

__device__ float g_buf[160000000ull];   // 640MB scratch pool

using bf16 = __nv_bfloat16;

__device__ __forceinline__ uint32_t smem_u32(const void* p){
    uint32_t a;
    asm("{ .reg .u64 t; cvta.to.shared.u64 t, %1; cvt.u32.u64 %0, t; }" : "=r"(a) : "l"(p));
    return a;
}
__device__ __forceinline__ uint32_t pack2(float x, float y){
    __nv_bfloat162 t = __floats2bfloat162_rn(x, y);
    return *(uint32_t*)&t;
}
__device__ __forceinline__ void split1(float x, float& h, float& l){
    h = __bfloat162float(__float2bfloat16(x));
    l = x - h;
}
__device__ __forceinline__ uint32_t swz(uint32_t r, uint32_t c){
    return r * 64 + (((c ^ (r >> 1)) & 3) << 4) + (c & ~3u) * 16;
}
__device__ __forceinline__ uint32_t swzN(uint32_t r, uint32_t c){
    return r * 256 + ((c ^ (r & 7)) << 4);
}

#define LDSM4(R, addr) \
    asm volatile("ldmatrix.sync.aligned.m8n8.x4.shared.b16 {%0,%1,%2,%3}, [%4];" \
        : "=r"((R)[0]), "=r"((R)[1]), "=r"((R)[2]), "=r"((R)[3]) : "r"(addr))

#define LDSM4T(R, addr) \
    asm volatile("ldmatrix.sync.aligned.m8n8.x4.trans.shared.b16 {%0,%1,%2,%3}, [%4];" \
        : "=r"((R)[0]), "=r"((R)[1]), "=r"((R)[2]), "=r"((R)[3]) : "r"(addr))

#define MMA16816(d, a, b) \
    asm volatile("mma.sync.aligned.m16n8k16.row.col.f32.bf16.bf16.f32 " \
        "{%0,%1,%2,%3}, {%4,%5,%6,%7}, {%8,%9}, {%0,%1,%2,%3};" \
        : "+f"((d)[0]), "+f"((d)[1]), "+f"((d)[2]), "+f"((d)[3]) \
        : "r"((a)[0]), "r"((a)[1]), "r"((a)[2]), "r"((a)[3]), "r"((b)[0]), "r"((b)[1]))

#define CP_ASYNC16(dst, src) \
    asm volatile("cp.async.cg.shared.global [%0], [%1], 16;" :: "r"(dst), "l"(src))

constexpr int TILEB = 128 * 64;
constexpr int STGB  = 4 * TILEB;          // 32768
constexpr int SMEMB = 3 * STGB;           // 98304

// ---------------------------------------------------------------------------
// NT GEMM: C = scale*(A @ B^T)(+bias). A[M,K], B[N,K] bf16 splits.
// OM bit0: fp32 C; bit1: bf16 split out; bit2: fp32 res write.
// ---------------------------------------------------------------------------
template<int OM, bool BIAS>
__global__ void __launch_bounds__(256, 2) gemm_bf3(
    const bf16* __restrict__ Ah, const bf16* __restrict__ Al,
    const bf16* __restrict__ Bh, const bf16* __restrict__ Bl,
    const float* __restrict__ bias,
    float* __restrict__ Cf, bf16* __restrict__ Ch, bf16* __restrict__ Cl,
    float* __restrict__ Cres, int resOff,
    int M, int N, int K, float scale,
    long long sA, long long sB, long long sC)
{
    extern __shared__ char sm[];
    const uint32_t sb = smem_u32(sm);
    const int tid = threadIdx.x, lane = tid & 31, warp = tid >> 5;
    const int wm = warp >> 2, wn = warp & 3;
    const int bz = blockIdx.z;
    Ah += bz * sA;  Al += bz * sA;
    Bh += bz * sB;  Bl += bz * sB;
    const long long co = (long long)bz * sC;
    const int m0 = blockIdx.y * 128, n0 = blockIdx.x * 128;

    auto load_stage = [&](int slot, int k0){
        const uint32_t s = sb + slot * STGB;
        const bf16* srcs[4] = {Ah, Al, Bh, Bl};
#pragma unroll
        for (int t = 0; t < 4; t++) {
            const bf16* src = srcs[t];
            const int rbase = (t < 2) ? m0 : n0;
#pragma unroll
            for (int i = 0; i < 2; i++) {
                const int c = tid + i * 256;
                const uint32_t row = c >> 2, ch = c & 3;
                const uint32_t dst = s + t * TILEB + swz(row, ch);
                const bf16* g = src + (long long)(rbase + row) * K + k0 + ch * 8;
                CP_ASYNC16(dst, g);
            }
        }
    };

    const int NS = K / 32;
    load_stage(0, 0);
    asm volatile("cp.async.commit_group;" ::: "memory");
    load_stage(1, 32);
    asm volatile("cp.async.commit_group;" ::: "memory");

    float acc[4][4][4] = {};
    int slot = 0;

    for (int s = 0; s < NS; s++) {
        asm volatile("cp.async.wait_group 1;" ::: "memory");
        __syncthreads();

        const uint32_t st  = sb + slot * STGB;
        const uint32_t tAh = st, tAl = st + TILEB, tBh = st + 2*TILEB, tBl = st + 3*TILEB;
        if (++slot == 3) slot = 0;

        uint32_t a[4][4], bh[4][2], bl[4][2];
        // ---- ks = 0: first LDSM+MMA group, then embedded prefetch ----
        {
            const uint32_t ach  = (lane >> 4);
            const uint32_t arow = wm * 64 + (lane & 15);
            const uint32_t brow = wn * 32 + (lane & 7) + ((lane >> 4) << 3);
            const uint32_t bch  = ((lane >> 3) & 1);
#pragma unroll
            for (int mi = 0; mi < 4; mi++)
                LDSM4(a[mi], tAh + swz(arow + mi * 16, ach));
#pragma unroll
            for (int pi = 0; pi < 2; pi++) {
                uint32_t v[4];
                LDSM4(v, tBh + swz(brow + pi * 16, bch));
                bh[2*pi][0] = v[0]; bh[2*pi][1] = v[1];
                bh[2*pi+1][0] = v[2]; bh[2*pi+1][1] = v[3];
            }
#pragma unroll
            for (int mi = 0; mi < 4; mi++)
#pragma unroll
                for (int ni = 0; ni < 4; ni++)
                    MMA16816(acc[mi][ni], a[mi], bh[ni]);

            if (s + 2 < NS) {
                int ns = slot + 1; if (ns >= 3) ns -= 3;
                load_stage(ns, (s + 2) * 32);
            }
            asm volatile("cp.async.commit_group;" ::: "memory");

#pragma unroll
            for (int pi = 0; pi < 2; pi++) {
                uint32_t v[4];
                LDSM4(v, tBl + swz(brow + pi * 16, bch));
                bl[2*pi][0] = v[0]; bl[2*pi][1] = v[1];
                bl[2*pi+1][0] = v[2]; bl[2*pi+1][1] = v[3];
            }
#pragma unroll
            for (int mi = 0; mi < 4; mi++)
#pragma unroll
                for (int ni = 0; ni < 4; ni++)
                    MMA16816(acc[mi][ni], a[mi], bl[ni]);
#pragma unroll
            for (int mi = 0; mi < 4; mi++)
                LDSM4(a[mi], tAl + swz(arow + mi * 16, ach));
#pragma unroll
            for (int mi = 0; mi < 4; mi++)
#pragma unroll
                for (int ni = 0; ni < 4; ni++)
                    MMA16816(acc[mi][ni], a[mi], bh[ni]);
        }
        // ---- ks = 1 ----
        {
            const uint32_t ach  = 2 + (lane >> 4);
            const uint32_t arow = wm * 64 + (lane & 15);
            const uint32_t brow = wn * 32 + (lane & 7) + ((lane >> 4) << 3);
            const uint32_t bch  = 2 + ((lane >> 3) & 1);
#pragma unroll
            for (int mi = 0; mi < 4; mi++)
                LDSM4(a[mi], tAh + swz(arow + mi * 16, ach));
#pragma unroll
            for (int pi = 0; pi < 2; pi++) {
                uint32_t v[4];
                LDSM4(v, tBh + swz(brow + pi * 16, bch));
                bh[2*pi][0] = v[0]; bh[2*pi][1] = v[1];
                bh[2*pi+1][0] = v[2]; bh[2*pi+1][1] = v[3];
            }
#pragma unroll
            for (int mi = 0; mi < 4; mi++)
#pragma unroll
                for (int ni = 0; ni < 4; ni++)
                    MMA16816(acc[mi][ni], a[mi], bh[ni]);
#pragma unroll
            for (int pi = 0; pi < 2; pi++) {
                uint32_t v[4];
                LDSM4(v, tBl + swz(brow + pi * 16, bch));
                bl[2*pi][0] = v[0]; bl[2*pi][1] = v[1];
                bl[2*pi+1][0] = v[2]; bl[2*pi+1][1] = v[3];
            }
#pragma unroll
            for (int mi = 0; mi < 4; mi++)
#pragma unroll
                for (int ni = 0; ni < 4; ni++)
                    MMA16816(acc[mi][ni], a[mi], bl[ni]);
#pragma unroll
            for (int mi = 0; mi < 4; mi++)
                LDSM4(a[mi], tAl + swz(arow + mi * 16, ach));
#pragma unroll
            for (int mi = 0; mi < 4; mi++)
#pragma unroll
                for (int ni = 0; ni < 4; ni++)
                    MMA16816(acc[mi][ni], a[mi], bh[ni]);
        }
    }

#pragma unroll
    for (int mi = 0; mi < 4; mi++) {
        const int r0 = m0 + wm * 64 + mi * 16 + (lane >> 2);
#pragma unroll
        for (int ni = 0; ni < 4; ni++) {
            const int col = n0 + wn * 32 + ni * 8 + (lane & 3) * 2;
            float b0 = 0.f, b1 = 0.f;
            if (BIAS) { b0 = __ldg(bias + col); b1 = __ldg(bias + col + 1); }
            const float x0 = acc[mi][ni][0] * scale + b0;
            const float x1 = acc[mi][ni][1] * scale + b1;
            const float x2 = acc[mi][ni][2] * scale + b0;
            const float x3 = acc[mi][ni][3] * scale + b1;
            const long long g0 = co + (long long)r0 * N + col;
            const long long g1 = co + (long long)(r0 + 8) * N + col;
            if (OM & 1) {
                *(float2*)(Cf + g0) = make_float2(x0, x1);
                *(float2*)(Cf + g1) = make_float2(x2, x3);
            }
            if (OM & 2) {
                float h0, l0, h1, l1, h2, l2, h3, l3;
                split1(x0, h0, l0); split1(x1, h1, l1);
                split1(x2, h2, l2); split1(x3, h3, l3);
                *(uint32_t*)(Ch + g0) = pack2(h0, h1);
                *(uint32_t*)(Ch + g1) = pack2(h2, h3);
                *(uint32_t*)(Cl + g0) = pack2(l0, l1);
                *(uint32_t*)(Cl + g1) = pack2(l2, l3);
            }
            if (OM & 4) {
                const long long rg0 = (long long)r0 * 2048 + resOff + col;
                const long long rg1 = (long long)(r0 + 8) * 2048 + resOff + col;
                *(float2*)(Cres + rg0) = make_float2(x0, x1);
                *(float2*)(Cres + rg1) = make_float2(x2, x3);
            }
        }
    }
}

// ---------------------------------------------------------------------------
// NN GEMM: C = A @ B, A[M,K], B[K,N] (row-major), bf16 splits; out = bf16 split.
// ---------------------------------------------------------------------------
__global__ void __launch_bounds__(256, 2) gemm_nn(
    const bf16* __restrict__ Ah, const bf16* __restrict__ Al,
    const bf16* __restrict__ Bh, const bf16* __restrict__ Bl,
    bf16* __restrict__ Ch, bf16* __restrict__ Cl,
    int M, int N, int K,
    long long sA, long long sB, long long sC)
{
    extern __shared__ char sm[];
    const uint32_t sb = smem_u32(sm);
    const int tid = threadIdx.x, lane = tid & 31, warp = tid >> 5;
    const int wm = warp >> 2, wn = warp & 3;
    const int bz = blockIdx.z;
    Ah += bz * sA;  Al += bz * sA;
    Bh += bz * sB;  Bl += bz * sB;
    const long long co = (long long)bz * sC;
    const int m0 = blockIdx.y * 128, n0 = blockIdx.x * 128;

    auto load_stage = [&](int slot, int k0){
        const uint32_t s = sb + slot * STGB;
#pragma unroll
        for (int i = 0; i < 2; i++) {
            const int c = tid + i * 256;
            const uint32_t row = c >> 2, ch = c & 3;
            const long long g = (long long)(m0 + row) * K + k0 + ch * 8;
            CP_ASYNC16(s + swz(row, ch),          Ah + g);
            CP_ASYNC16(s + TILEB + swz(row, ch),  Al + g);
        }
#pragma unroll
        for (int i = 0; i < 2; i++) {
            const int c = tid + i * 256;
            const uint32_t row = c >> 4, ch = c & 15;
            const long long g = (long long)(k0 + row) * N + n0 + ch * 8;
            CP_ASYNC16(s + 2*TILEB + swzN(row, ch), Bh + g);
            CP_ASYNC16(s + 3*TILEB + swzN(row, ch), Bl + g);
        }
    };

    const int NS = K / 32;
    load_stage(0, 0);
    asm volatile("cp.async.commit_group;" ::: "memory");
    load_stage(1, 32);
    asm volatile("cp.async.commit_group;" ::: "memory");

    float acc[4][4][4] = {};
    int slot = 0;

    for (int s = 0; s < NS; s++) {
        asm volatile("cp.async.wait_group 1;" ::: "memory");
        __syncthreads();

        const uint32_t st  = sb + slot * STGB;
        const uint32_t tAh = st, tAl = st + TILEB, tBh = st + 2*TILEB, tBl = st + 3*TILEB;
        if (++slot == 3) slot = 0;

        uint32_t a[4][4], bh[4][2], bl[4][2];
        // ---- ks = 0 with embedded prefetch ----
        {
            const uint32_t ach  = (lane >> 4);
            const uint32_t arow = wm * 64 + (lane & 15);
            const uint32_t brr  = (lane & 7) + (((lane >> 3) & 1) << 3);
#pragma unroll
            for (int mi = 0; mi < 4; mi++)
                LDSM4(a[mi], tAh + swz(arow + mi * 16, ach));
#pragma unroll
            for (int pi = 0; pi < 2; pi++) {
                const uint32_t bcc = ((wn * 32 + pi * 16) >> 3) + (lane >> 4);
                uint32_t v[4];
                LDSM4T(v, tBh + swzN(brr, bcc));
                bh[2*pi][0] = v[0]; bh[2*pi][1] = v[1];
                bh[2*pi+1][0] = v[2]; bh[2*pi+1][1] = v[3];
            }
#pragma unroll
            for (int mi = 0; mi < 4; mi++)
#pragma unroll
                for (int ni = 0; ni < 4; ni++)
                    MMA16816(acc[mi][ni], a[mi], bh[ni]);

            if (s + 2 < NS) {
                int ns = slot + 1; if (ns >= 3) ns -= 3;
                load_stage(ns, (s + 2) * 32);
            }
            asm volatile("cp.async.commit_group;" ::: "memory");

#pragma unroll
            for (int pi = 0; pi < 2; pi++) {
                const uint32_t bcc = ((wn * 32 + pi * 16) >> 3) + (lane >> 4);
                uint32_t v[4];
                LDSM4T(v, tBl + swzN(brr, bcc));
                bl[2*pi][0] = v[0]; bl[2*pi][1] = v[1];
                bl[2*pi+1][0] = v[2]; bl[2*pi+1][1] = v[3];
            }
#pragma unroll
            for (int mi = 0; mi < 4; mi++)
#pragma unroll
                for (int ni = 0; ni < 4; ni++)
                    MMA16816(acc[mi][ni], a[mi], bl[ni]);
#pragma unroll
            for (int mi = 0; mi < 4; mi++)
                LDSM4(a[mi], tAl + swz(arow + mi * 16, ach));
#pragma unroll
            for (int mi = 0; mi < 4; mi++)
#pragma unroll
                for (int ni = 0; ni < 4; ni++)
                    MMA16816(acc[mi][ni], a[mi], bh[ni]);
        }
        // ---- ks = 1 ----
        {
            const uint32_t ach  = 2 + (lane >> 4);
            const uint32_t arow = wm * 64 + (lane & 15);
            const uint32_t brr  = 16 + (lane & 7) + (((lane >> 3) & 1) << 3);
#pragma unroll
            for (int mi = 0; mi < 4; mi++)
                LDSM4(a[mi], tAh + swz(arow + mi * 16, ach));
#pragma unroll
            for (int pi = 0; pi < 2; pi++) {
                const uint32_t bcc = ((wn * 32 + pi * 16) >> 3) + (lane >> 4);
                uint32_t v[4];
                LDSM4T(v, tBh + swzN(brr, bcc));
                bh[2*pi][0] = v[0]; bh[2*pi][1] = v[1];
                bh[2*pi+1][0] = v[2]; bh[2*pi+1][1] = v[3];
            }
#pragma unroll
            for (int mi = 0; mi < 4; mi++)
#pragma unroll
                for (int ni = 0; ni < 4; ni++)
                    MMA16816(acc[mi][ni], a[mi], bh[ni]);
#pragma unroll
            for (int pi = 0; pi < 2; pi++) {
                const uint32_t bcc = ((wn * 32 + pi * 16) >> 3) + (lane >> 4);
                uint32_t v[4];
                LDSM4T(v, tBl + swzN(brr, bcc));
                bl[2*pi][0] = v[0]; bl[2*pi][1] = v[1];
                bl[2*pi+1][0] = v[2]; bl[2*pi+1][1] = v[3];
            }
#pragma unroll
            for (int mi = 0; mi < 4; mi++)
#pragma unroll
                for (int ni = 0; ni < 4; ni++)
                    MMA16816(acc[mi][ni], a[mi], bl[ni]);
#pragma unroll
            for (int mi = 0; mi < 4; mi++)
                LDSM4(a[mi], tAl + swz(arow + mi * 16, ach));
#pragma unroll
            for (int mi = 0; mi < 4; mi++)
#pragma unroll
                for (int ni = 0; ni < 4; ni++)
                    MMA16816(acc[mi][ni], a[mi], bh[ni]);
        }
    }

#pragma unroll
    for (int mi = 0; mi < 4; mi++) {
        const int r0 = m0 + wm * 64 + mi * 16 + (lane >> 2);
#pragma unroll
        for (int ni = 0; ni < 4; ni++) {
            const int col = n0 + wn * 32 + ni * 8 + (lane & 3) * 2;
            const float x0 = acc[mi][ni][0], x1 = acc[mi][ni][1];
            const float x2 = acc[mi][ni][2], x3 = acc[mi][ni][3];
            const long long g0 = co + (long long)r0 * N + col;
            const long long g1 = co + (long long)(r0 + 8) * N + col;
            float h0, l0, h1, l1, h2, l2, h3, l3;
            split1(x0, h0, l0); split1(x1, h1, l1);
            split1(x2, h2, l2); split1(x3, h3, l3);
            *(uint32_t*)(Ch + g0) = pack2(h0, h1);
            *(uint32_t*)(Ch + g1) = pack2(h2, h3);
            *(uint32_t*)(Cl + g0) = pack2(l0, l1);
            *(uint32_t*)(Cl + g1) = pack2(l2, l3);
        }
    }
}

// ---------------------------------------------------------------------------
// 5-way fused projection GEMM. z==0 additionally writes fp32 res at col 0.
// ---------------------------------------------------------------------------
struct Proj5 {
    const bf16* Ah[5]; const bf16* Al[5];
    const bf16* Bh[5]; const bf16* Bl[5];
    const float* bias[5];
    float* Cf[5];
    float* res;
};

__global__ void __launch_bounds__(256, 2) proj5_k(Proj5 j)
{
    extern __shared__ char sm[];
    const uint32_t sb = smem_u32(sm);
    const int tid = threadIdx.x, lane = tid & 31, warp = tid >> 5;
    const int wm = warp >> 2, wn = warp & 3;
    const int z = blockIdx.z;
    const bf16* Ah = j.Ah[z]; const bf16* Al = j.Al[z];
    const bf16* Bh = j.Bh[z]; const bf16* Bl = j.Bl[z];
    const float* bias = j.bias[z];
    float* Cf = j.Cf[z];
    const int m0 = blockIdx.y * 128, n0 = blockIdx.x * 128;
    constexpr int K = 1024, N = 1024;

    auto load_stage = [&](int slot, int k0){
        const uint32_t s = sb + slot * STGB;
        const bf16* srcs[4] = {Ah, Al, Bh, Bl};
#pragma unroll
        for (int t = 0; t < 4; t++) {
            const bf16* src = srcs[t];
            const int rbase = (t < 2) ? m0 : n0;
#pragma unroll
            for (int i = 0; i < 2; i++) {
                const int c = tid + i * 256;
                const uint32_t row = c >> 2, ch = c & 3;
                const uint32_t dst = s + t * TILEB + swz(row, ch);
                const bf16* g = src + (long long)(rbase + row) * K + k0 + ch * 8;
                CP_ASYNC16(dst, g);
            }
        }
    };

    const int NS = K / 32;
    load_stage(0, 0);
    asm volatile("cp.async.commit_group;" ::: "memory");
    load_stage(1, 32);
    asm volatile("cp.async.commit_group;" ::: "memory");

    float acc[4][4][4] = {};
    int slot = 0;

    for (int s = 0; s < NS; s++) {
        asm volatile("cp.async.wait_group 1;" ::: "memory");
        __syncthreads();

        const uint32_t st  = sb + slot * STGB;
        const uint32_t tAh = st, tAl = st + TILEB, tBh = st + 2*TILEB, tBl = st + 3*TILEB;
        if (++slot == 3) slot = 0;

        uint32_t a[4][4], bh[4][2], bl[4][2];
        // ks = 0 with embedded prefetch
        {
            const uint32_t ach  = (lane >> 4);
            const uint32_t arow = wm * 64 + (lane & 15);
            const uint32_t brow = wn * 32 + (lane & 7) + ((lane >> 4) << 3);
            const uint32_t bch  = ((lane >> 3) & 1);
#pragma unroll
            for (int mi = 0; mi < 4; mi++)
                LDSM4(a[mi], tAh + swz(arow + mi * 16, ach));
#pragma unroll
            for (int pi = 0; pi < 2; pi++) {
                uint32_t v[4];
                LDSM4(v, tBh + swz(brow + pi * 16, bch));
                bh[2*pi][0] = v[0]; bh[2*pi][1] = v[1];
                bh[2*pi+1][0] = v[2]; bh[2*pi+1][1] = v[3];
            }
#pragma unroll
            for (int mi = 0; mi < 4; mi++)
#pragma unroll
                for (int ni = 0; ni < 4; ni++)
                    MMA16816(acc[mi][ni], a[mi], bh[ni]);

            if (s + 2 < NS) {
                int ns = slot + 1; if (ns >= 3) ns -= 3;
                load_stage(ns, (s + 2) * 32);
            }
            asm volatile("cp.async.commit_group;" ::: "memory");

#pragma unroll
            for (int pi = 0; pi < 2; pi++) {
                uint32_t v[4];
                LDSM4(v, tBl + swz(brow + pi * 16, bch));
                bl[2*pi][0] = v[0]; bl[2*pi][1] = v[1];
                bl[2*pi+1][0] = v[2]; bl[2*pi+1][1] = v[3];
            }
#pragma unroll
            for (int mi = 0; mi < 4; mi++)
#pragma unroll
                for (int ni = 0; ni < 4; ni++)
                    MMA16816(acc[mi][ni], a[mi], bl[ni]);
#pragma unroll
            for (int mi = 0; mi < 4; mi++)
                LDSM4(a[mi], tAl + swz(arow + mi * 16, ach));
#pragma unroll
            for (int mi = 0; mi < 4; mi++)
#pragma unroll
                for (int ni = 0; ni < 4; ni++)
                    MMA16816(acc[mi][ni], a[mi], bh[ni]);
        }
        // ks = 1
        {
            const uint32_t ach  = 2 + (lane >> 4);
            const uint32_t arow = wm * 64 + (lane & 15);
            const uint32_t brow = wn * 32 + (lane & 7) + ((lane >> 4) << 3);
            const uint32_t bch  = 2 + ((lane >> 3) & 1);
#pragma unroll
            for (int mi = 0; mi < 4; mi++)
                LDSM4(a[mi], tAh + swz(arow + mi * 16, ach));
#pragma unroll
            for (int pi = 0; pi < 2; pi++) {
                uint32_t v[4];
                LDSM4(v, tBh + swz(brow + pi * 16, bch));
                bh[2*pi][0] = v[0]; bh[2*pi][1] = v[1];
                bh[2*pi+1][0] = v[2]; bh[2*pi+1][1] = v[3];
            }
#pragma unroll
            for (int mi = 0; mi < 4; mi++)
#pragma unroll
                for (int ni = 0; ni < 4; ni++)
                    MMA16816(acc[mi][ni], a[mi], bh[ni]);
#pragma unroll
            for (int pi = 0; pi < 2; pi++) {
                uint32_t v[4];
                LDSM4(v, tBl + swz(brow + pi * 16, bch));
                bl[2*pi][0] = v[0]; bl[2*pi][1] = v[1];
                bl[2*pi+1][0] = v[2]; bl[2*pi+1][1] = v[3];
            }
#pragma unroll
            for (int mi = 0; mi < 4; mi++)
#pragma unroll
                for (int ni = 0; ni < 4; ni++)
                    MMA16816(acc[mi][ni], a[mi], bl[ni]);
#pragma unroll
            for (int mi = 0; mi < 4; mi++)
                LDSM4(a[mi], tAl + swz(arow + mi * 16, ach));
#pragma unroll
            for (int mi = 0; mi < 4; mi++)
#pragma unroll
                for (int ni = 0; ni < 4; ni++)
                    MMA16816(acc[mi][ni], a[mi], bh[ni]);
        }
    }

    const bool doRes = (z == 0);
#pragma unroll
    for (int mi = 0; mi < 4; mi++) {
        const int r0 = m0 + wm * 64 + mi * 16 + (lane >> 2);
#pragma unroll
        for (int ni = 0; ni < 4; ni++) {
            const int col = n0 + wn * 32 + ni * 8 + (lane & 3) * 2;
            const float b0 = __ldg(bias + col), b1 = __ldg(bias + col + 1);
            const float x0 = acc[mi][ni][0] + b0;
            const float x1 = acc[mi][ni][1] + b1;
            const float x2 = acc[mi][ni][2] + b0;
            const float x3 = acc[mi][ni][3] + b1;
            const long long g0 = (long long)r0 * N + col;
            const long long g1 = (long long)(r0 + 8) * N + col;
            *(float2*)(Cf + g0) = make_float2(x0, x1);
            *(float2*)(Cf + g1) = make_float2(x2, x3);
            if (doRes) {
                *(float2*)(j.res + (long long)r0 * 2048 + col)       = make_float2(x0, x1);
                *(float2*)(j.res + (long long)(r0 + 8) * 2048 + col) = make_float2(x2, x3);
            }
        }
    }
}

// ---------------------------------------------------------------------------
struct Split3 { const float* x[3]; bf16* h[3]; bf16* l[3]; };

__global__ void __launch_bounds__(256) split3_k(Split3 j)
{
    const int z = blockIdx.y;
    const float* x = j.x[z];
    bf16* h = j.h[z]; bf16* l = j.l[z];
    const long long i = ((long long)blockIdx.x * 256 + threadIdx.x) * 4;
    const float4 v = *(const float4*)(x + i);
    float h0,l0,h1,l1,h2,l2,h3,l3;
    split1(v.x,h0,l0); split1(v.y,h1,l1); split1(v.z,h2,l2); split1(v.w,h3,l3);
    uint2 hp, lp;
    hp.x = pack2(h0,h1); hp.y = pack2(h2,h3);
    lp.x = pack2(l0,l1); lp.y = pack2(l2,l3);
    *(uint2*)(h + i) = hp;
    *(uint2*)(l + i) = lp;
}

// single-tensor fp32 -> bf16 hi/lo split (for Wf1 in original orientation)
__global__ void __launch_bounds__(256) split1_k(
    const float* __restrict__ x, bf16* __restrict__ h, bf16* __restrict__ l)
{
    const long long i = ((long long)blockIdx.x * 256 + threadIdx.x) * 4;
    const float4 v = *(const float4*)(x + i);
    float h0,l0,h1,l1,h2,l2,h3,l3;
    split1(v.x,h0,l0); split1(v.y,h1,l1); split1(v.z,h2,l2); split1(v.w,h3,l3);
    uint2 hp, lp;
    hp.x = pack2(h0,h1); hp.y = pack2(h2,h3);
    lp.x = pack2(l0,l1); lp.y = pack2(l2,l3);
    *(uint2*)(h + i) = hp;
    *(uint2*)(l + i) = lp;
}

// fused bias: bc[n] = bq2[n] + sum_k bf1[k] * Wq2[k][n]
__global__ void __launch_bounds__(256) biasf_k(
    const float* __restrict__ Wq2, const float* __restrict__ bf1,
    const float* __restrict__ bq2, float* __restrict__ bc)
{
    const int n = blockIdx.x * 256 + threadIdx.x;
    float s = bq2[n];
#pragma unroll 4
    for (int kk = 0; kk < 1024; kk++)
        s += bf1[kk] * Wq2[(long long)kk * 1024 + n];
    bc[n] = s;
}

struct W8 { const float* w[8]; bf16* th[8]; bf16* tl[8]; };

__global__ void __launch_bounds__(256) tspw_k(W8 j)
{
    __shared__ float t[32][33];
    const int z = blockIdx.z;
    const float* X = j.w[z];
    bf16* Th = j.th[z]; bf16* Tl = j.tl[z];
    const int c0 = blockIdx.x * 32, r0 = blockIdx.y * 32;
    const int tx = threadIdx.x, ty = threadIdx.y;
#pragma unroll
    for (int i = 0; i < 4; i++)
        t[ty + i * 8][tx] = X[(long long)(r0 + ty + i * 8) * 1024 + c0 + tx];
    __syncthreads();
#pragma unroll
    for (int i = 0; i < 4; i++) {
        const float v = t[tx][ty + i * 8];
        float h, l; split1(v, h, l);
        const long long g = (long long)(c0 + ty + i * 8) * 1024 + r0 + tx;
        Th[g] = __float2bfloat16(h);
        Tl[g] = __float2bfloat16(l);
    }
}

// ---------------------------------------------------------------------------
struct LN3 {
    const float* x[3]; const float* g[3]; const float* b[3];
    bf16* yh[3]; bf16* yl[3];
};

__global__ void __launch_bounds__(256) ln3_k(LN3 j)
{
    const int z = blockIdx.y;
    const int lane = threadIdx.x & 31, warp = threadIdx.x >> 5;
    const long long row = (long long)blockIdx.x * 8 + warp;

    const float4* xr = (const float4*)(j.x[z] + row * 1024);
    float4 xv[8];
#pragma unroll
    for (int i = 0; i < 8; i++) xv[i] = xr[lane + i * 32];

    float s = 0.f, s2 = 0.f;
#pragma unroll
    for (int i = 0; i < 8; i++) {
        s  += xv[i].x + xv[i].y + xv[i].z + xv[i].w;
        s2 += xv[i].x*xv[i].x + xv[i].y*xv[i].y + xv[i].z*xv[i].z + xv[i].w*xv[i].w;
    }
#pragma unroll
    for (int o = 16; o > 0; o >>= 1) {
        s  += __shfl_xor_sync(0xffffffffu, s, o);
        s2 += __shfl_xor_sync(0xffffffffu, s2, o);
    }
    const float mean = s * (1.0f / 1024.0f);
    const float var  = s2 * (1.0f / 1024.0f) - mean * mean;
    const float inv  = rsqrtf(var + 1e-6f);

    const float4* gr = (const float4*)j.g[z];
    const float4* br = (const float4*)j.b[z];
    uint2* yh = (uint2*)(j.yh[z] + row * 1024);
    uint2* yl = (uint2*)(j.yl[z] + row * 1024);
#pragma unroll
    for (int i = 0; i < 8; i++) {
        const float4 gg = gr[lane + i * 32];
        const float4 bb = br[lane + i * 32];
        float4 o;
        o.x = (xv[i].x - mean) * inv * gg.x + bb.x;
        o.y = (xv[i].y - mean) * inv * gg.y + bb.y;
        o.z = (xv[i].z - mean) * inv * gg.z + bb.z;
        o.w = (xv[i].w - mean) * inv * gg.w + bb.w;
        float h0,l0,h1,l1,h2,l2,h3,l3;
        split1(o.x,h0,l0); split1(o.y,h1,l1); split1(o.z,h2,l2); split1(o.w,h3,l3);
        uint2 hp, lp;
        hp.x = pack2(h0,h1); hp.y = pack2(h2,h3);
        lp.x = pack2(l0,l1); lp.y = pack2(l2,l3);
        yh[lane + i * 32] = hp;
        yl[lane + i * 32] = lp;
    }
}

// ---------------------------------------------------------------------------
template<bool F32OUT>
__global__ void __launch_bounds__(256) softmax_k(
    float* __restrict__ S, bf16* __restrict__ Ph, bf16* __restrict__ Pl)
{
    const int lane = threadIdx.x & 31, warp = threadIdx.x >> 5;
    const long long row = (long long)blockIdx.x * 8 + warp;
    float4* r4 = (float4*)(S + row * 2048);

    float4 v[16];
#pragma unroll
    for (int i = 0; i < 16; i++) v[i] = r4[lane + i * 32];

    float mx = v[0].x;
#pragma unroll
    for (int i = 0; i < 16; i++) {
        mx = fmaxf(mx, fmaxf(fmaxf(v[i].x, v[i].y), fmaxf(v[i].z, v[i].w)));
    }
#pragma unroll
    for (int o = 16; o > 0; o >>= 1) mx = fmaxf(mx, __shfl_xor_sync(0xffffffffu, mx, o));

    float sum = 0.f;
#pragma unroll
    for (int i = 0; i < 16; i++) {
        v[i].x = __expf(v[i].x - mx); v[i].y = __expf(v[i].y - mx);
        v[i].z = __expf(v[i].z - mx); v[i].w = __expf(v[i].w - mx);
        sum += v[i].x + v[i].y + v[i].z + v[i].w;
    }
#pragma unroll
    for (int o = 16; o > 0; o >>= 1) sum += __shfl_xor_sync(0xffffffffu, sum, o);
    const float inv = 1.0f / sum;

    uint2* ph = (uint2*)(Ph + row * 2048);
    uint2* pl = (uint2*)(Pl + row * 2048);
#pragma unroll
    for (int i = 0; i < 16; i++) {
        float4 p;
        p.x = v[i].x * inv; p.y = v[i].y * inv;
        p.z = v[i].z * inv; p.w = v[i].w * inv;
        float h0,l0,h1,l1,h2,l2,h3,l3;
        split1(p.x,h0,l0); split1(p.y,h1,l1); split1(p.z,h2,l2); split1(p.w,h3,l3);
        uint2 hp, lp;
        hp.x = pack2(h0,h1); hp.y = pack2(h2,h3);
        lp.x = pack2(l0,l1); lp.y = pack2(l2,l3);
        ph[lane + i * 32] = hp;
        pl[lane + i * 32] = lp;
        if (F32OUT) r4[lane + i * 32] = p;
    }
}

// ---------------------------------------------------------------------------
extern "C" void kernel_launch(void* const* d_in, const int* in_sizes, int n_in,
                              void* d_out, int out_size)
{
    const float* q = (const float*)d_in[0];
    const float* k = (const float*)d_in[1];
    const float* v = (const float*)d_in[2];
    const float* W[8]  = {(const float*)d_in[3],  (const float*)d_in[5],
                          (const float*)d_in[7],  (const float*)d_in[9],
                          (const float*)d_in[11], (const float*)d_in[13],
                          (const float*)d_in[15], (const float*)d_in[17]};
    const float* bW[8] = {(const float*)d_in[4],  (const float*)d_in[6],
                          (const float*)d_in[8],  (const float*)d_in[10],
                          (const float*)d_in[12], (const float*)d_in[14],
                          (const float*)d_in[16], (const float*)d_in[18]};
    const float* gq1 = (const float*)d_in[19]; const float* Bq1 = (const float*)d_in[20];
    const float* gk1 = (const float*)d_in[21]; const float* Bk1 = (const float*)d_in[22];
    const float* gv1 = (const float*)d_in[23]; const float* Bv1 = (const float*)d_in[24];
    const float* gq2 = (const float*)d_in[25]; const float* Bq2 = (const float*)d_in[26];
    const float* gk2 = (const float*)d_in[27]; const float* Bk2 = (const float*)d_in[28];
    const float* gv2 = (const float*)d_in[29]; const float* Bv2 = (const float*)d_in[30];

    float* out = (float*)d_out;
    float* res = out + SZB;
    float* a2  = res + SSB;

    float* buf = nullptr;
    cudaGetSymbolAddress((void**)&buf, g_buf);
    char* P = (char*)buf;
    auto takeB = [&](long long bytes){ char* r = P; P += bytes; return r; };
    bf16* q_h  = (bf16*)takeB(SZB*2); bf16* q_l  = (bf16*)takeB(SZB*2);
    bf16* k_h  = (bf16*)takeB(SZB*2); bf16* k_l  = (bf16*)takeB(SZB*2);
    bf16* v_h  = (bf16*)takeB(SZB*2); bf16* v_l  = (bf16*)takeB(SZB*2);
    float* q1b = (float*)takeB(SZB*4);
    float* kb  = (float*)takeB(SZB*4);
    float* vb  = (float*)takeB(SZB*4);
    float* k2b = (float*)takeB(SZB*4);
    float* v2b = (float*)takeB(SZB*4);
    float* q2b = (float*)takeB(SZB*4);
    bf16* nq_h = (bf16*)takeB(SZB*2); bf16* nq_l = (bf16*)takeB(SZB*2);
    bf16* nk_h = (bf16*)takeB(SZB*2); bf16* nk_l = (bf16*)takeB(SZB*2);
    bf16* nv_h = (bf16*)takeB(SZB*2); bf16* nv_l = (bf16*)takeB(SZB*2);
    bf16* oa_h = (bf16*)takeB(SZB*2); bf16* oa_l = (bf16*)takeB(SZB*2);
    float* Sbuf= (float*)takeB(SSB*4);
    bf16* P_h  = (bf16*)takeB(SSB*2); bf16* P_l  = (bf16*)takeB(SSB*2);
    bf16* WTp  = (bf16*)takeB(8ll * 2 * WSZ * 2);
    bf16* f1_h = (bf16*)takeB(WSZ*2); bf16* f1_l = (bf16*)takeB(WSZ*2);
    bf16* Wc_h = (bf16*)takeB(WSZ*2); bf16* Wc_l = (bf16*)takeB(WSZ*2);
    float* bc  = (float*)takeB(1024*4);
    auto WTh = [&](int i){ return WTp + (long long)i * 2 * WSZ; };
    auto WTl = [&](int i){ return WTp + (long long)i * 2 * WSZ + WSZ; };

    cudaFuncSetAttribute(gemm_bf3<1,true >, cudaFuncAttributeMaxDynamicSharedMemorySize, SMEMB);
    cudaFuncSetAttribute(gemm_bf3<1,false>, cudaFuncAttributeMaxDynamicSharedMemorySize, SMEMB);
    cudaFuncSetAttribute(gemm_bf3<2,false>, cudaFuncAttributeMaxDynamicSharedMemorySize, SMEMB);
    cudaFuncSetAttribute(gemm_bf3<5,true >, cudaFuncAttributeMaxDynamicSharedMemorySize, SMEMB);
    cudaFuncSetAttribute(gemm_nn,           cudaFuncAttributeMaxDynamicSharedMemorySize, SMEMB);
    cudaFuncSetAttribute(proj5_k,           cudaFuncAttributeMaxDynamicSharedMemorySize, SMEMB);

    const dim3 tb(32, 8);
    const dim3 gproj(8, 64, 1);
    const dim3 gproj5(8, 64, 5);
    const dim3 gS(16, 16, 4);
    const dim3 gO(8, 16, 4);
    const float it = 1.0f / 32.0f;
    const long long sLD = 2048ll*1024, sLL = 2048ll*2048;

    // ---------------- prep ----------------
    Split3 s3;
    s3.x[0] = q; s3.h[0] = q_h; s3.l[0] = q_l;
    s3.x[1] = k; s3.h[1] = k_h; s3.l[1] = k_l;
    s3.x[2] = v; s3.h[2] = v_h; s3.l[2] = v_l;
    split3_k<<<dim3(SZB/4/256, 3), 256>>>(s3);
    split1_k<<<WSZ/4/256, 256>>>(W[3], f1_h, f1_l);   // Wf1, original orientation
    W8 w8;
    for (int i = 0; i < 8; i++) { w8.w[i] = W[i]; w8.th[i] = WTh(i); w8.tl[i] = WTl(i); }
    tspw_k<<<dim3(32,32,8), tb>>>(w8);
    biasf_k<<<4, 256>>>(W[4], bW[3], bW[4], bc);      // bc = Wq2^T bf1 + bq2
    // WcT[n][j] = sum_k' Wq2^T[n][k'] * Wf1[j][k']   (bf16 split out)
    gemm_bf3<2,false><<<dim3(8,8,1),256,SMEMB>>>(WTh(4),WTl(4), f1_h,f1_l, 0,
        0, Wc_h, Wc_l, 0,0, 1024,1024,1024, 1.f, 0,0,0);

    Proj5 p5;
    p5.Ah[0]=q_h; p5.Al[0]=q_l; p5.Bh[0]=WTh(0); p5.Bl[0]=WTl(0); p5.bias[0]=bW[0]; p5.Cf[0]=q1b;
    p5.Ah[1]=k_h; p5.Al[1]=k_l; p5.Bh[1]=WTh(1); p5.Bl[1]=WTl(1); p5.bias[1]=bW[1]; p5.Cf[1]=kb;
    p5.Ah[2]=v_h; p5.Al[2]=v_l; p5.Bh[2]=WTh(2); p5.Bl[2]=WTl(2); p5.bias[2]=bW[2]; p5.Cf[2]=vb;
    p5.Ah[3]=k_h; p5.Al[3]=k_l; p5.Bh[3]=WTh(5); p5.Bl[3]=WTl(5); p5.bias[3]=bW[5]; p5.Cf[3]=k2b;
    p5.Ah[4]=v_h; p5.Al[4]=v_l; p5.Bh[4]=WTh(6); p5.Bl[4]=WTl(6); p5.bias[4]=bW[6]; p5.Cf[4]=v2b;
    p5.res = res;
    proj5_k<<<gproj5, 256, SMEMB>>>(p5);

    // ---------------- layer 1 ----------------
    LN3 l1;
    l1.x[0]=q1b; l1.g[0]=gq1; l1.b[0]=Bq1; l1.yh[0]=nq_h; l1.yl[0]=nq_l;
    l1.x[1]=kb;  l1.g[1]=gk1; l1.b[1]=Bk1; l1.yh[1]=nk_h; l1.yl[1]=nk_l;
    l1.x[2]=vb;  l1.g[2]=gv1; l1.b[2]=Bv1; l1.yh[2]=nv_h; l1.yl[2]=nv_l;
    ln3_k<<<dim3(1024,3), 256>>>(l1);

    gemm_bf3<1,false><<<gS,256,SMEMB>>>(nq_h,nq_l, nk_h,nk_l, 0, Sbuf,0,0, 0,0, 2048,2048,1024, it, sLD,sLD,sLL);
    softmax_k<false><<<1024,256>>>(Sbuf, P_h, P_l);
    gemm_nn<<<gO,256,SMEMB>>>(P_h,P_l, nv_h,nv_l, oa_h,oa_l, 2048,1024,2048, sLL,sLD,sLD);
    // fused: q2 = oa @ Wc + bc  (replaces oa->o1->q2)
    gemm_bf3<5,true ><<<gproj,256,SMEMB>>>(oa_h,oa_l, Wc_h,Wc_l, bc, q2b,0,0, res,1024, 8192,1024,1024, 1.f, 0,0,0);

    // ---------------- layer 2 ----------------
    LN3 l2;
    l2.x[0]=q2b; l2.g[0]=gq2; l2.b[0]=Bq2; l2.yh[0]=nq_h; l2.yl[0]=nq_l;
    l2.x[1]=k2b; l2.g[1]=gk2; l2.b[1]=Bk2; l2.yh[1]=nk_h; l2.yl[1]=nk_l;
    l2.x[2]=v2b; l2.g[2]=gv2; l2.b[2]=Bv2; l2.yh[2]=nv_h; l2.yl[2]=nv_l;
    ln3_k<<<dim3(1024,3), 256>>>(l2);

    gemm_bf3<1,false><<<gS,256,SMEMB>>>(nq_h,nq_l, nk_h,nk_l, 0, a2,0,0, 0,0, 2048,2048,1024, it, sLD,sLD,sLL);
    softmax_k<true><<<1024,256>>>(a2, P_h, P_l);
    gemm_nn<<<gO,256,SMEMB>>>(P_h,P_l, nv_h,nv_l, oa_h,oa_l, 2048,1024,2048, sLL,sLD,sLD);
    gemm_bf3<1,true ><<<gproj,256,SMEMB>>>(oa_h,oa_l, WTh(7),WTl(7), bW[7], out,0,0, 0,0, 8192,1024,1024, 1.f, 0,0,0);
}

// round 15
// speedup vs baseline: 1.5379x; 1.0392x over previous
#include <cuda_runtime.h>
#include <cuda_bf16.h>
#include <cstdint>

// ---------------------------------------------------------------------------
// B=4, L=2048, D=1024, fp32. Outputs: out(8.39M) | res(16.78M) | a2(16.78M).
// GEMMs via legacy mma.sync bf16, 2-term bf16 split (3 products).
// R15 = R14 with the fused-bias GEMV rewritten as split-K two-phase
//       (R14's biasf_k ran on 4 SMs and cost 147us).
// ---------------------------------------------------------------------------

#define SZB 8388608ll
#define SSB 16777216ll
#define WSZ 1048576ll

__device__ float g_buf[160000000ull];   // 640MB scratch pool

using bf16 = __nv_bfloat16;

__device__ __forceinline__ uint32_t smem_u32(const void* p){
    uint32_t a;
    asm("{ .reg .u64 t; cvta.to.shared.u64 t, %1; cvt.u32.u64 %0, t; }" : "=r"(a) : "l"(p));
    return a;
}
__device__ __forceinline__ uint32_t pack2(float x, float y){
    __nv_bfloat162 t = __floats2bfloat162_rn(x, y);
    return *(uint32_t*)&t;
}
__device__ __forceinline__ void split1(float x, float& h, float& l){
    h = __bfloat162float(__float2bfloat16(x));
    l = x - h;
}
__device__ __forceinline__ uint32_t swz(uint32_t r, uint32_t c){
    return r * 64 + (((c ^ (r >> 1)) & 3) << 4) + (c & ~3u) * 16;
}
__device__ __forceinline__ uint32_t swzN(uint32_t r, uint32_t c){
    return r * 256 + ((c ^ (r & 7)) << 4);
}

#define LDSM4(R, addr) \
    asm volatile("ldmatrix.sync.aligned.m8n8.x4.shared.b16 {%0,%1,%2,%3}, [%4];" \
        : "=r"((R)[0]), "=r"((R)[1]), "=r"((R)[2]), "=r"((R)[3]) : "r"(addr))

#define LDSM4T(R, addr) \
    asm volatile("ldmatrix.sync.aligned.m8n8.x4.trans.shared.b16 {%0,%1,%2,%3}, [%4];" \
        : "=r"((R)[0]), "=r"((R)[1]), "=r"((R)[2]), "=r"((R)[3]) : "r"(addr))

#define MMA16816(d, a, b) \
    asm volatile("mma.sync.aligned.m16n8k16.row.col.f32.bf16.bf16.f32 " \
        "{%0,%1,%2,%3}, {%4,%5,%6,%7}, {%8,%9}, {%0,%1,%2,%3};" \
        : "+f"((d)[0]), "+f"((d)[1]), "+f"((d)[2]), "+f"((d)[3]) \
        : "r"((a)[0]), "r"((a)[1]), "r"((a)[2]), "r"((a)[3]), "r"((b)[0]), "r"((b)[1]))

#define CP_ASYNC16(dst, src) \
    asm volatile("cp.async.cg.shared.global [%0], [%1], 16;" :: "r"(dst), "l"(src))

constexpr int TILEB = 128 * 64;
constexpr int STGB  = 4 * TILEB;          // 32768
constexpr int SMEMB = 3 * STGB;           // 98304

// ---------------------------------------------------------------------------
// NT GEMM: C = scale*(A @ B^T)(+bias). A[M,K], B[N,K] bf16 splits.
// OM bit0: fp32 C; bit1: bf16 split out; bit2: fp32 res write.
// ---------------------------------------------------------------------------
template<int OM, bool BIAS>
__global__ void __launch_bounds__(256, 2) gemm_bf3(
    const bf16* __restrict__ Ah, const bf16* __restrict__ Al,
    const bf16* __restrict__ Bh, const bf16* __restrict__ Bl,
    const float* __restrict__ bias,
    float* __restrict__ Cf, bf16* __restrict__ Ch, bf16* __restrict__ Cl,
    float* __restrict__ Cres, int resOff,
    int M, int N, int K, float scale,
    long long sA, long long sB, long long sC)
{
    extern __shared__ char sm[];
    const uint32_t sb = smem_u32(sm);
    const int tid = threadIdx.x, lane = tid & 31, warp = tid >> 5;
    const int wm = warp >> 2, wn = warp & 3;
    const int bz = blockIdx.z;
    Ah += bz * sA;  Al += bz * sA;
    Bh += bz * sB;  Bl += bz * sB;
    const long long co = (long long)bz * sC;
    const int m0 = blockIdx.y * 128, n0 = blockIdx.x * 128;

    auto load_stage = [&](int slot, int k0){
        const uint32_t s = sb + slot * STGB;
        const bf16* srcs[4] = {Ah, Al, Bh, Bl};
#pragma unroll
        for (int t = 0; t < 4; t++) {
            const bf16* src = srcs[t];
            const int rbase = (t < 2) ? m0 : n0;
#pragma unroll
            for (int i = 0; i < 2; i++) {
                const int c = tid + i * 256;
                const uint32_t row = c >> 2, ch = c & 3;
                const uint32_t dst = s + t * TILEB + swz(row, ch);
                const bf16* g = src + (long long)(rbase + row) * K + k0 + ch * 8;
                CP_ASYNC16(dst, g);
            }
        }
    };

    const int NS = K / 32;
    load_stage(0, 0);
    asm volatile("cp.async.commit_group;" ::: "memory");
    load_stage(1, 32);
    asm volatile("cp.async.commit_group;" ::: "memory");

    float acc[4][4][4] = {};
    int slot = 0;

    for (int s = 0; s < NS; s++) {
        asm volatile("cp.async.wait_group 1;" ::: "memory");
        __syncthreads();

        const uint32_t st  = sb + slot * STGB;
        const uint32_t tAh = st, tAl = st + TILEB, tBh = st + 2*TILEB, tBl = st + 3*TILEB;
        if (++slot == 3) slot = 0;

        uint32_t a[4][4], bh[4][2], bl[4][2];
        // ---- ks = 0: first LDSM+MMA group, then embedded prefetch ----
        {
            const uint32_t ach  = (lane >> 4);
            const uint32_t arow = wm * 64 + (lane & 15);
            const uint32_t brow = wn * 32 + (lane & 7) + ((lane >> 4) << 3);
            const uint32_t bch  = ((lane >> 3) & 1);
#pragma unroll
            for (int mi = 0; mi < 4; mi++)
                LDSM4(a[mi], tAh + swz(arow + mi * 16, ach));
#pragma unroll
            for (int pi = 0; pi < 2; pi++) {
                uint32_t v[4];
                LDSM4(v, tBh + swz(brow + pi * 16, bch));
                bh[2*pi][0] = v[0]; bh[2*pi][1] = v[1];
                bh[2*pi+1][0] = v[2]; bh[2*pi+1][1] = v[3];
            }
#pragma unroll
            for (int mi = 0; mi < 4; mi++)
#pragma unroll
                for (int ni = 0; ni < 4; ni++)
                    MMA16816(acc[mi][ni], a[mi], bh[ni]);

            if (s + 2 < NS) {
                int ns = slot + 1; if (ns >= 3) ns -= 3;
                load_stage(ns, (s + 2) * 32);
            }
            asm volatile("cp.async.commit_group;" ::: "memory");

#pragma unroll
            for (int pi = 0; pi < 2; pi++) {
                uint32_t v[4];
                LDSM4(v, tBl + swz(brow + pi * 16, bch));
                bl[2*pi][0] = v[0]; bl[2*pi][1] = v[1];
                bl[2*pi+1][0] = v[2]; bl[2*pi+1][1] = v[3];
            }
#pragma unroll
            for (int mi = 0; mi < 4; mi++)
#pragma unroll
                for (int ni = 0; ni < 4; ni++)
                    MMA16816(acc[mi][ni], a[mi], bl[ni]);
#pragma unroll
            for (int mi = 0; mi < 4; mi++)
                LDSM4(a[mi], tAl + swz(arow + mi * 16, ach));
#pragma unroll
            for (int mi = 0; mi < 4; mi++)
#pragma unroll
                for (int ni = 0; ni < 4; ni++)
                    MMA16816(acc[mi][ni], a[mi], bh[ni]);
        }
        // ---- ks = 1 ----
        {
            const uint32_t ach  = 2 + (lane >> 4);
            const uint32_t arow = wm * 64 + (lane & 15);
            const uint32_t brow = wn * 32 + (lane & 7) + ((lane >> 4) << 3);
            const uint32_t bch  = 2 + ((lane >> 3) & 1);
#pragma unroll
            for (int mi = 0; mi < 4; mi++)
                LDSM4(a[mi], tAh + swz(arow + mi * 16, ach));
#pragma unroll
            for (int pi = 0; pi < 2; pi++) {
                uint32_t v[4];
                LDSM4(v, tBh + swz(brow + pi * 16, bch));
                bh[2*pi][0] = v[0]; bh[2*pi][1] = v[1];
                bh[2*pi+1][0] = v[2]; bh[2*pi+1][1] = v[3];
            }
#pragma unroll
            for (int mi = 0; mi < 4; mi++)
#pragma unroll
                for (int ni = 0; ni < 4; ni++)
                    MMA16816(acc[mi][ni], a[mi], bh[ni]);
#pragma unroll
            for (int pi = 0; pi < 2; pi++) {
                uint32_t v[4];
                LDSM4(v, tBl + swz(brow + pi * 16, bch));
                bl[2*pi][0] = v[0]; bl[2*pi][1] = v[1];
                bl[2*pi+1][0] = v[2]; bl[2*pi+1][1] = v[3];
            }
#pragma unroll
            for (int mi = 0; mi < 4; mi++)
#pragma unroll
                for (int ni = 0; ni < 4; ni++)
                    MMA16816(acc[mi][ni], a[mi], bl[ni]);
#pragma unroll
            for (int mi = 0; mi < 4; mi++)
                LDSM4(a[mi], tAl + swz(arow + mi * 16, ach));
#pragma unroll
            for (int mi = 0; mi < 4; mi++)
#pragma unroll
                for (int ni = 0; ni < 4; ni++)
                    MMA16816(acc[mi][ni], a[mi], bh[ni]);
        }
    }

#pragma unroll
    for (int mi = 0; mi < 4; mi++) {
        const int r0 = m0 + wm * 64 + mi * 16 + (lane >> 2);
#pragma unroll
        for (int ni = 0; ni < 4; ni++) {
            const int col = n0 + wn * 32 + ni * 8 + (lane & 3) * 2;
            float b0 = 0.f, b1 = 0.f;
            if (BIAS) { b0 = __ldg(bias + col); b1 = __ldg(bias + col + 1); }
            const float x0 = acc[mi][ni][0] * scale + b0;
            const float x1 = acc[mi][ni][1] * scale + b1;
            const float x2 = acc[mi][ni][2] * scale + b0;
            const float x3 = acc[mi][ni][3] * scale + b1;
            const long long g0 = co + (long long)r0 * N + col;
            const long long g1 = co + (long long)(r0 + 8) * N + col;
            if (OM & 1) {
                *(float2*)(Cf + g0) = make_float2(x0, x1);
                *(float2*)(Cf + g1) = make_float2(x2, x3);
            }
            if (OM & 2) {
                float h0, l0, h1, l1, h2, l2, h3, l3;
                split1(x0, h0, l0); split1(x1, h1, l1);
                split1(x2, h2, l2); split1(x3, h3, l3);
                *(uint32_t*)(Ch + g0) = pack2(h0, h1);
                *(uint32_t*)(Ch + g1) = pack2(h2, h3);
                *(uint32_t*)(Cl + g0) = pack2(l0, l1);
                *(uint32_t*)(Cl + g1) = pack2(l2, l3);
            }
            if (OM & 4) {
                const long long rg0 = (long long)r0 * 2048 + resOff + col;
                const long long rg1 = (long long)(r0 + 8) * 2048 + resOff + col;
                *(float2*)(Cres + rg0) = make_float2(x0, x1);
                *(float2*)(Cres + rg1) = make_float2(x2, x3);
            }
        }
    }
}

// ---------------------------------------------------------------------------
// NN GEMM: C = A @ B, A[M,K], B[K,N] (row-major), bf16 splits; out = bf16 split.
// ---------------------------------------------------------------------------
__global__ void __launch_bounds__(256, 2) gemm_nn(
    const bf16* __restrict__ Ah, const bf16* __restrict__ Al,
    const bf16* __restrict__ Bh, const bf16* __restrict__ Bl,
    bf16* __restrict__ Ch, bf16* __restrict__ Cl,
    int M, int N, int K,
    long long sA, long long sB, long long sC)
{
    extern __shared__ char sm[];
    const uint32_t sb = smem_u32(sm);
    const int tid = threadIdx.x, lane = tid & 31, warp = tid >> 5;
    const int wm = warp >> 2, wn = warp & 3;
    const int bz = blockIdx.z;
    Ah += bz * sA;  Al += bz * sA;
    Bh += bz * sB;  Bl += bz * sB;
    const long long co = (long long)bz * sC;
    const int m0 = blockIdx.y * 128, n0 = blockIdx.x * 128;

    auto load_stage = [&](int slot, int k0){
        const uint32_t s = sb + slot * STGB;
#pragma unroll
        for (int i = 0; i < 2; i++) {
            const int c = tid + i * 256;
            const uint32_t row = c >> 2, ch = c & 3;
            const long long g = (long long)(m0 + row) * K + k0 + ch * 8;
            CP_ASYNC16(s + swz(row, ch),          Ah + g);
            CP_ASYNC16(s + TILEB + swz(row, ch),  Al + g);
        }
#pragma unroll
        for (int i = 0; i < 2; i++) {
            const int c = tid + i * 256;
            const uint32_t row = c >> 4, ch = c & 15;
            const long long g = (long long)(k0 + row) * N + n0 + ch * 8;
            CP_ASYNC16(s + 2*TILEB + swzN(row, ch), Bh + g);
            CP_ASYNC16(s + 3*TILEB + swzN(row, ch), Bl + g);
        }
    };

    const int NS = K / 32;
    load_stage(0, 0);
    asm volatile("cp.async.commit_group;" ::: "memory");
    load_stage(1, 32);
    asm volatile("cp.async.commit_group;" ::: "memory");

    float acc[4][4][4] = {};
    int slot = 0;

    for (int s = 0; s < NS; s++) {
        asm volatile("cp.async.wait_group 1;" ::: "memory");
        __syncthreads();

        const uint32_t st  = sb + slot * STGB;
        const uint32_t tAh = st, tAl = st + TILEB, tBh = st + 2*TILEB, tBl = st + 3*TILEB;
        if (++slot == 3) slot = 0;

        uint32_t a[4][4], bh[4][2], bl[4][2];
        // ---- ks = 0 with embedded prefetch ----
        {
            const uint32_t ach  = (lane >> 4);
            const uint32_t arow = wm * 64 + (lane & 15);
            const uint32_t brr  = (lane & 7) + (((lane >> 3) & 1) << 3);
#pragma unroll
            for (int mi = 0; mi < 4; mi++)
                LDSM4(a[mi], tAh + swz(arow + mi * 16, ach));
#pragma unroll
            for (int pi = 0; pi < 2; pi++) {
                const uint32_t bcc = ((wn * 32 + pi * 16) >> 3) + (lane >> 4);
                uint32_t v[4];
                LDSM4T(v, tBh + swzN(brr, bcc));
                bh[2*pi][0] = v[0]; bh[2*pi][1] = v[1];
                bh[2*pi+1][0] = v[2]; bh[2*pi+1][1] = v[3];
            }
#pragma unroll
            for (int mi = 0; mi < 4; mi++)
#pragma unroll
                for (int ni = 0; ni < 4; ni++)
                    MMA16816(acc[mi][ni], a[mi], bh[ni]);

            if (s + 2 < NS) {
                int ns = slot + 1; if (ns >= 3) ns -= 3;
                load_stage(ns, (s + 2) * 32);
            }
            asm volatile("cp.async.commit_group;" ::: "memory");

#pragma unroll
            for (int pi = 0; pi < 2; pi++) {
                const uint32_t bcc = ((wn * 32 + pi * 16) >> 3) + (lane >> 4);
                uint32_t v[4];
                LDSM4T(v, tBl + swzN(brr, bcc));
                bl[2*pi][0] = v[0]; bl[2*pi][1] = v[1];
                bl[2*pi+1][0] = v[2]; bl[2*pi+1][1] = v[3];
            }
#pragma unroll
            for (int mi = 0; mi < 4; mi++)
#pragma unroll
                for (int ni = 0; ni < 4; ni++)
                    MMA16816(acc[mi][ni], a[mi], bl[ni]);
#pragma unroll
            for (int mi = 0; mi < 4; mi++)
                LDSM4(a[mi], tAl + swz(arow + mi * 16, ach));
#pragma unroll
            for (int mi = 0; mi < 4; mi++)
#pragma unroll
                for (int ni = 0; ni < 4; ni++)
                    MMA16816(acc[mi][ni], a[mi], bh[ni]);
        }
        // ---- ks = 1 ----
        {
            const uint32_t ach  = 2 + (lane >> 4);
            const uint32_t arow = wm * 64 + (lane & 15);
            const uint32_t brr  = 16 + (lane & 7) + (((lane >> 3) & 1) << 3);
#pragma unroll
            for (int mi = 0; mi < 4; mi++)
                LDSM4(a[mi], tAh + swz(arow + mi * 16, ach));
#pragma unroll
            for (int pi = 0; pi < 2; pi++) {
                const uint32_t bcc = ((wn * 32 + pi * 16) >> 3) + (lane >> 4);
                uint32_t v[4];
                LDSM4T(v, tBh + swzN(brr, bcc));
                bh[2*pi][0] = v[0]; bh[2*pi][1] = v[1];
                bh[2*pi+1][0] = v[2]; bh[2*pi+1][1] = v[3];
            }
#pragma unroll
            for (int mi = 0; mi < 4; mi++)
#pragma unroll
                for (int ni = 0; ni < 4; ni++)
                    MMA16816(acc[mi][ni], a[mi], bh[ni]);
#pragma unroll
            for (int pi = 0; pi < 2; pi++) {
                const uint32_t bcc = ((wn * 32 + pi * 16) >> 3) + (lane >> 4);
                uint32_t v[4];
                LDSM4T(v, tBl + swzN(brr, bcc));
                bl[2*pi][0] = v[0]; bl[2*pi][1] = v[1];
                bl[2*pi+1][0] = v[2]; bl[2*pi+1][1] = v[3];
            }
#pragma unroll
            for (int mi = 0; mi < 4; mi++)
#pragma unroll
                for (int ni = 0; ni < 4; ni++)
                    MMA16816(acc[mi][ni], a[mi], bl[ni]);
#pragma unroll
            for (int mi = 0; mi < 4; mi++)
                LDSM4(a[mi], tAl + swz(arow + mi * 16, ach));
#pragma unroll
            for (int mi = 0; mi < 4; mi++)
#pragma unroll
                for (int ni = 0; ni < 4; ni++)
                    MMA16816(acc[mi][ni], a[mi], bh[ni]);
        }
    }

#pragma unroll
    for (int mi = 0; mi < 4; mi++) {
        const int r0 = m0 + wm * 64 + mi * 16 + (lane >> 2);
#pragma unroll
        for (int ni = 0; ni < 4; ni++) {
            const int col = n0 + wn * 32 + ni * 8 + (lane & 3) * 2;
            const float x0 = acc[mi][ni][0], x1 = acc[mi][ni][1];
            const float x2 = acc[mi][ni][2], x3 = acc[mi][ni][3];
            const long long g0 = co + (long long)r0 * N + col;
            const long long g1 = co + (long long)(r0 + 8) * N + col;
            float h0, l0, h1, l1, h2, l2, h3, l3;
            split1(x0, h0, l0); split1(x1, h1, l1);
            split1(x2, h2, l2); split1(x3, h3, l3);
            *(uint32_t*)(Ch + g0) = pack2(h0, h1);
            *(uint32_t*)(Ch + g1) = pack2(h2, h3);
            *(uint32_t*)(Cl + g0) = pack2(l0, l1);
            *(uint32_t*)(Cl + g1) = pack2(l2, l3);
        }
    }
}

// ---------------------------------------------------------------------------
// 5-way fused projection GEMM. z==0 additionally writes fp32 res at col 0.
// ---------------------------------------------------------------------------
struct Proj5 {
    const bf16* Ah[5]; const bf16* Al[5];
    const bf16* Bh[5]; const bf16* Bl[5];
    const float* bias[5];
    float* Cf[5];
    float* res;
};

__global__ void __launch_bounds__(256, 2) proj5_k(Proj5 j)
{
    extern __shared__ char sm[];
    const uint32_t sb = smem_u32(sm);
    const int tid = threadIdx.x, lane = tid & 31, warp = tid >> 5;
    const int wm = warp >> 2, wn = warp & 3;
    const int z = blockIdx.z;
    const bf16* Ah = j.Ah[z]; const bf16* Al = j.Al[z];
    const bf16* Bh = j.Bh[z]; const bf16* Bl = j.Bl[z];
    const float* bias = j.bias[z];
    float* Cf = j.Cf[z];
    const int m0 = blockIdx.y * 128, n0 = blockIdx.x * 128;
    constexpr int K = 1024, N = 1024;

    auto load_stage = [&](int slot, int k0){
        const uint32_t s = sb + slot * STGB;
        const bf16* srcs[4] = {Ah, Al, Bh, Bl};
#pragma unroll
        for (int t = 0; t < 4; t++) {
            const bf16* src = srcs[t];
            const int rbase = (t < 2) ? m0 : n0;
#pragma unroll
            for (int i = 0; i < 2; i++) {
                const int c = tid + i * 256;
                const uint32_t row = c >> 2, ch = c & 3;
                const uint32_t dst = s + t * TILEB + swz(row, ch);
                const bf16* g = src + (long long)(rbase + row) * K + k0 + ch * 8;
                CP_ASYNC16(dst, g);
            }
        }
    };

    const int NS = K / 32;
    load_stage(0, 0);
    asm volatile("cp.async.commit_group;" ::: "memory");
    load_stage(1, 32);
    asm volatile("cp.async.commit_group;" ::: "memory");

    float acc[4][4][4] = {};
    int slot = 0;

    for (int s = 0; s < NS; s++) {
        asm volatile("cp.async.wait_group 1;" ::: "memory");
        __syncthreads();

        const uint32_t st  = sb + slot * STGB;
        const uint32_t tAh = st, tAl = st + TILEB, tBh = st + 2*TILEB, tBl = st + 3*TILEB;
        if (++slot == 3) slot = 0;

        uint32_t a[4][4], bh[4][2], bl[4][2];
        // ks = 0 with embedded prefetch
        {
            const uint32_t ach  = (lane >> 4);
            const uint32_t arow = wm * 64 + (lane & 15);
            const uint32_t brow = wn * 32 + (lane & 7) + ((lane >> 4) << 3);
            const uint32_t bch  = ((lane >> 3) & 1);
#pragma unroll
            for (int mi = 0; mi < 4; mi++)
                LDSM4(a[mi], tAh + swz(arow + mi * 16, ach));
#pragma unroll
            for (int pi = 0; pi < 2; pi++) {
                uint32_t v[4];
                LDSM4(v, tBh + swz(brow + pi * 16, bch));
                bh[2*pi][0] = v[0]; bh[2*pi][1] = v[1];
                bh[2*pi+1][0] = v[2]; bh[2*pi+1][1] = v[3];
            }
#pragma unroll
            for (int mi = 0; mi < 4; mi++)
#pragma unroll
                for (int ni = 0; ni < 4; ni++)
                    MMA16816(acc[mi][ni], a[mi], bh[ni]);

            if (s + 2 < NS) {
                int ns = slot + 1; if (ns >= 3) ns -= 3;
                load_stage(ns, (s + 2) * 32);
            }
            asm volatile("cp.async.commit_group;" ::: "memory");

#pragma unroll
            for (int pi = 0; pi < 2; pi++) {
                uint32_t v[4];
                LDSM4(v, tBl + swz(brow + pi * 16, bch));
                bl[2*pi][0] = v[0]; bl[2*pi][1] = v[1];
                bl[2*pi+1][0] = v[2]; bl[2*pi+1][1] = v[3];
            }
#pragma unroll
            for (int mi = 0; mi < 4; mi++)
#pragma unroll
                for (int ni = 0; ni < 4; ni++)
                    MMA16816(acc[mi][ni], a[mi], bl[ni]);
#pragma unroll
            for (int mi = 0; mi < 4; mi++)
                LDSM4(a[mi], tAl + swz(arow + mi * 16, ach));
#pragma unroll
            for (int mi = 0; mi < 4; mi++)
#pragma unroll
                for (int ni = 0; ni < 4; ni++)
                    MMA16816(acc[mi][ni], a[mi], bh[ni]);
        }
        // ks = 1
        {
            const uint32_t ach  = 2 + (lane >> 4);
            const uint32_t arow = wm * 64 + (lane & 15);
            const uint32_t brow = wn * 32 + (lane & 7) + ((lane >> 4) << 3);
            const uint32_t bch  = 2 + ((lane >> 3) & 1);
#pragma unroll
            for (int mi = 0; mi < 4; mi++)
                LDSM4(a[mi], tAh + swz(arow + mi * 16, ach));
#pragma unroll
            for (int pi = 0; pi < 2; pi++) {
                uint32_t v[4];
                LDSM4(v, tBh + swz(brow + pi * 16, bch));
                bh[2*pi][0] = v[0]; bh[2*pi][1] = v[1];
                bh[2*pi+1][0] = v[2]; bh[2*pi+1][1] = v[3];
            }
#pragma unroll
            for (int mi = 0; mi < 4; mi++)
#pragma unroll
                for (int ni = 0; ni < 4; ni++)
                    MMA16816(acc[mi][ni], a[mi], bh[ni]);
#pragma unroll
            for (int pi = 0; pi < 2; pi++) {
                uint32_t v[4];
                LDSM4(v, tBl + swz(brow + pi * 16, bch));
                bl[2*pi][0] = v[0]; bl[2*pi][1] = v[1];
                bl[2*pi+1][0] = v[2]; bl[2*pi+1][1] = v[3];
            }
#pragma unroll
            for (int mi = 0; mi < 4; mi++)
#pragma unroll
                for (int ni = 0; ni < 4; ni++)
                    MMA16816(acc[mi][ni], a[mi], bl[ni]);
#pragma unroll
            for (int mi = 0; mi < 4; mi++)
                LDSM4(a[mi], tAl + swz(arow + mi * 16, ach));
#pragma unroll
            for (int mi = 0; mi < 4; mi++)
#pragma unroll
                for (int ni = 0; ni < 4; ni++)
                    MMA16816(acc[mi][ni], a[mi], bh[ni]);
        }
    }

    const bool doRes = (z == 0);
#pragma unroll
    for (int mi = 0; mi < 4; mi++) {
        const int r0 = m0 + wm * 64 + mi * 16 + (lane >> 2);
#pragma unroll
        for (int ni = 0; ni < 4; ni++) {
            const int col = n0 + wn * 32 + ni * 8 + (lane & 3) * 2;
            const float b0 = __ldg(bias + col), b1 = __ldg(bias + col + 1);
            const float x0 = acc[mi][ni][0] + b0;
            const float x1 = acc[mi][ni][1] + b1;
            const float x2 = acc[mi][ni][2] + b0;
            const float x3 = acc[mi][ni][3] + b1;
            const long long g0 = (long long)r0 * N + col;
            const long long g1 = (long long)(r0 + 8) * N + col;
            *(float2*)(Cf + g0) = make_float2(x0, x1);
            *(float2*)(Cf + g1) = make_float2(x2, x3);
            if (doRes) {
                *(float2*)(j.res + (long long)r0 * 2048 + col)       = make_float2(x0, x1);
                *(float2*)(j.res + (long long)(r0 + 8) * 2048 + col) = make_float2(x2, x3);
            }
        }
    }
}

// ---------------------------------------------------------------------------
struct Split3 { const float* x[3]; bf16* h[3]; bf16* l[3]; };

__global__ void __launch_bounds__(256) split3_k(Split3 j)
{
    const int z = blockIdx.y;
    const float* x = j.x[z];
    bf16* h = j.h[z]; bf16* l = j.l[z];
    const long long i = ((long long)blockIdx.x * 256 + threadIdx.x) * 4;
    const float4 v = *(const float4*)(x + i);
    float h0,l0,h1,l1,h2,l2,h3,l3;
    split1(v.x,h0,l0); split1(v.y,h1,l1); split1(v.z,h2,l2); split1(v.w,h3,l3);
    uint2 hp, lp;
    hp.x = pack2(h0,h1); hp.y = pack2(h2,h3);
    lp.x = pack2(l0,l1); lp.y = pack2(l2,l3);
    *(uint2*)(h + i) = hp;
    *(uint2*)(l + i) = lp;
}

// single-tensor fp32 -> bf16 hi/lo split
__global__ void __launch_bounds__(256) split1_k(
    const float* __restrict__ x, bf16* __restrict__ h, bf16* __restrict__ l)
{
    const long long i = ((long long)blockIdx.x * 256 + threadIdx.x) * 4;
    const float4 v = *(const float4*)(x + i);
    float h0,l0,h1,l1,h2,l2,h3,l3;
    split1(v.x,h0,l0); split1(v.y,h1,l1); split1(v.z,h2,l2); split1(v.w,h3,l3);
    uint2 hp, lp;
    hp.x = pack2(h0,h1); hp.y = pack2(h2,h3);
    lp.x = pack2(l0,l1); lp.y = pack2(l2,l3);
    *(uint2*)(h + i) = hp;
    *(uint2*)(l + i) = lp;
}

// split-K fused bias, phase 1: partial[kb][n] = sum_{k in chunk kb} bf1[k]*Wq2[k][n]
__global__ void __launch_bounds__(256) biasf1_k(
    const float* __restrict__ Wq2, const float* __restrict__ bf1,
    float* __restrict__ partial)
{
    const int n  = blockIdx.x * 256 + threadIdx.x;
    const int kb = blockIdx.y;
    const int k0 = kb * 32;
    float s = 0.f;
#pragma unroll
    for (int kk = 0; kk < 32; kk++)
        s += bf1[k0 + kk] * Wq2[(long long)(k0 + kk) * 1024 + n];
    partial[kb * 1024 + n] = s;
}

// phase 2: bc[n] = bq2[n] + sum_kb partial[kb][n]  (fixed order, deterministic)
__global__ void __launch_bounds__(256) biasf2_k(
    const float* __restrict__ partial, const float* __restrict__ bq2,
    float* __restrict__ bc)
{
    const int n = blockIdx.x * 256 + threadIdx.x;
    float s = bq2[n];
#pragma unroll
    for (int kb = 0; kb < 32; kb++)
        s += partial[kb * 1024 + n];
    bc[n] = s;
}

struct W8 { const float* w[8]; bf16* th[8]; bf16* tl[8]; };

__global__ void __launch_bounds__(256) tspw_k(W8 j)
{
    __shared__ float t[32][33];
    const int z = blockIdx.z;
    const float* X = j.w[z];
    bf16* Th = j.th[z]; bf16* Tl = j.tl[z];
    const int c0 = blockIdx.x * 32, r0 = blockIdx.y * 32;
    const int tx = threadIdx.x, ty = threadIdx.y;
#pragma unroll
    for (int i = 0; i < 4; i++)
        t[ty + i * 8][tx] = X[(long long)(r0 + ty + i * 8) * 1024 + c0 + tx];
    __syncthreads();
#pragma unroll
    for (int i = 0; i < 4; i++) {
        const float v = t[tx][ty + i * 8];
        float h, l; split1(v, h, l);
        const long long g = (long long)(c0 + ty + i * 8) * 1024 + r0 + tx;
        Th[g] = __float2bfloat16(h);
        Tl[g] = __float2bfloat16(l);
    }
}

// ---------------------------------------------------------------------------
struct LN3 {
    const float* x[3]; const float* g[3]; const float* b[3];
    bf16* yh[3]; bf16* yl[3];
};

__global__ void __launch_bounds__(256) ln3_k(LN3 j)
{
    const int z = blockIdx.y;
    const int lane = threadIdx.x & 31, warp = threadIdx.x >> 5;
    const long long row = (long long)blockIdx.x * 8 + warp;

    const float4* xr = (const float4*)(j.x[z] + row * 1024);
    float4 xv[8];
#pragma unroll
    for (int i = 0; i < 8; i++) xv[i] = xr[lane + i * 32];

    float s = 0.f, s2 = 0.f;
#pragma unroll
    for (int i = 0; i < 8; i++) {
        s  += xv[i].x + xv[i].y + xv[i].z + xv[i].w;
        s2 += xv[i].x*xv[i].x + xv[i].y*xv[i].y + xv[i].z*xv[i].z + xv[i].w*xv[i].w;
    }
#pragma unroll
    for (int o = 16; o > 0; o >>= 1) {
        s  += __shfl_xor_sync(0xffffffffu, s, o);
        s2 += __shfl_xor_sync(0xffffffffu, s2, o);
    }
    const float mean = s * (1.0f / 1024.0f);
    const float var  = s2 * (1.0f / 1024.0f) - mean * mean;
    const float inv  = rsqrtf(var + 1e-6f);

    const float4* gr = (const float4*)j.g[z];
    const float4* br = (const float4*)j.b[z];
    uint2* yh = (uint2*)(j.yh[z] + row * 1024);
    uint2* yl = (uint2*)(j.yl[z] + row * 1024);
#pragma unroll
    for (int i = 0; i < 8; i++) {
        const float4 gg = gr[lane + i * 32];
        const float4 bb = br[lane + i * 32];
        float4 o;
        o.x = (xv[i].x - mean) * inv * gg.x + bb.x;
        o.y = (xv[i].y - mean) * inv * gg.y + bb.y;
        o.z = (xv[i].z - mean) * inv * gg.z + bb.z;
        o.w = (xv[i].w - mean) * inv * gg.w + bb.w;
        float h0,l0,h1,l1,h2,l2,h3,l3;
        split1(o.x,h0,l0); split1(o.y,h1,l1); split1(o.z,h2,l2); split1(o.w,h3,l3);
        uint2 hp, lp;
        hp.x = pack2(h0,h1); hp.y = pack2(h2,h3);
        lp.x = pack2(l0,l1); lp.y = pack2(l2,l3);
        yh[lane + i * 32] = hp;
        yl[lane + i * 32] = lp;
    }
}

// ---------------------------------------------------------------------------
template<bool F32OUT>
__global__ void __launch_bounds__(256) softmax_k(
    float* __restrict__ S, bf16* __restrict__ Ph, bf16* __restrict__ Pl)
{
    const int lane = threadIdx.x & 31, warp = threadIdx.x >> 5;
    const long long row = (long long)blockIdx.x * 8 + warp;
    float4* r4 = (float4*)(S + row * 2048);

    float4 v[16];
#pragma unroll
    for (int i = 0; i < 16; i++) v[i] = r4[lane + i * 32];

    float mx = v[0].x;
#pragma unroll
    for (int i = 0; i < 16; i++) {
        mx = fmaxf(mx, fmaxf(fmaxf(v[i].x, v[i].y), fmaxf(v[i].z, v[i].w)));
    }
#pragma unroll
    for (int o = 16; o > 0; o >>= 1) mx = fmaxf(mx, __shfl_xor_sync(0xffffffffu, mx, o));

    float sum = 0.f;
#pragma unroll
    for (int i = 0; i < 16; i++) {
        v[i].x = __expf(v[i].x - mx); v[i].y = __expf(v[i].y - mx);
        v[i].z = __expf(v[i].z - mx); v[i].w = __expf(v[i].w - mx);
        sum += v[i].x + v[i].y + v[i].z + v[i].w;
    }
#pragma unroll
    for (int o = 16; o > 0; o >>= 1) sum += __shfl_xor_sync(0xffffffffu, sum, o);
    const float inv = 1.0f / sum;

    uint2* ph = (uint2*)(Ph + row * 2048);
    uint2* pl = (uint2*)(Pl + row * 2048);
#pragma unroll
    for (int i = 0; i < 16; i++) {
        float4 p;
        p.x = v[i].x * inv; p.y = v[i].y * inv;
        p.z = v[i].z * inv; p.w = v[i].w * inv;
        float h0,l0,h1,l1,h2,l2,h3,l3;
        split1(p.x,h0,l0); split1(p.y,h1,l1); split1(p.z,h2,l2); split1(p.w,h3,l3);
        uint2 hp, lp;
        hp.x = pack2(h0,h1); hp.y = pack2(h2,h3);
        lp.x = pack2(l0,l1); lp.y = pack2(l2,l3);
        ph[lane + i * 32] = hp;
        pl[lane + i * 32] = lp;
        if (F32OUT) r4[lane + i * 32] = p;
    }
}

// ---------------------------------------------------------------------------
extern "C" void kernel_launch(void* const* d_in, const int* in_sizes, int n_in,
                              void* d_out, int out_size)
{
    const float* q = (const float*)d_in[0];
    const float* k = (const float*)d_in[1];
    const float* v = (const float*)d_in[2];
    const float* W[8]  = {(const float*)d_in[3],  (const float*)d_in[5],
                          (const float*)d_in[7],  (const float*)d_in[9],
                          (const float*)d_in[11], (const float*)d_in[13],
                          (const float*)d_in[15], (const float*)d_in[17]};
    const float* bW[8] = {(const float*)d_in[4],  (const float*)d_in[6],
                          (const float*)d_in[8],  (const float*)d_in[10],
                          (const float*)d_in[12], (const float*)d_in[14],
                          (const float*)d_in[16], (const float*)d_in[18]};
    const float* gq1 = (const float*)d_in[19]; const float* Bq1 = (const float*)d_in[20];
    const float* gk1 = (const float*)d_in[21]; const float* Bk1 = (const float*)d_in[22];
    const float* gv1 = (const float*)d_in[23]; const float* Bv1 = (const float*)d_in[24];
    const float* gq2 = (const float*)d_in[25]; const float* Bq2 = (const float*)d_in[26];
    const float* gk2 = (const float*)d_in[27]; const float* Bk2 = (const float*)d_in[28];
    const float* gv2 = (const float*)d_in[29]; const float* Bv2 = (const float*)d_in[30];

    float* out = (float*)d_out;
    float* res = out + SZB;
    float* a2  = res + SSB;

    float* buf = nullptr;
    cudaGetSymbolAddress((void**)&buf, g_buf);
    char* P = (char*)buf;
    auto takeB = [&](long long bytes){ char* r = P; P += bytes; return r; };
    bf16* q_h  = (bf16*)takeB(SZB*2); bf16* q_l  = (bf16*)takeB(SZB*2);
    bf16* k_h  = (bf16*)takeB(SZB*2); bf16* k_l  = (bf16*)takeB(SZB*2);
    bf16* v_h  = (bf16*)takeB(SZB*2); bf16* v_l  = (bf16*)takeB(SZB*2);
    float* q1b = (float*)takeB(SZB*4);
    float* kb  = (float*)takeB(SZB*4);
    float* vb  = (float*)takeB(SZB*4);
    float* k2b = (float*)takeB(SZB*4);
    float* v2b = (float*)takeB(SZB*4);
    float* q2b = (float*)takeB(SZB*4);
    bf16* nq_h = (bf16*)takeB(SZB*2); bf16* nq_l = (bf16*)takeB(SZB*2);
    bf16* nk_h = (bf16*)takeB(SZB*2); bf16* nk_l = (bf16*)takeB(SZB*2);
    bf16* nv_h = (bf16*)takeB(SZB*2); bf16* nv_l = (bf16*)takeB(SZB*2);
    bf16* oa_h = (bf16*)takeB(SZB*2); bf16* oa_l = (bf16*)takeB(SZB*2);
    float* Sbuf= (float*)takeB(SSB*4);
    bf16* P_h  = (bf16*)takeB(SSB*2); bf16* P_l  = (bf16*)takeB(SSB*2);
    bf16* WTp  = (bf16*)takeB(8ll * 2 * WSZ * 2);
    bf16* f1_h = (bf16*)takeB(WSZ*2); bf16* f1_l = (bf16*)takeB(WSZ*2);
    bf16* Wc_h = (bf16*)takeB(WSZ*2); bf16* Wc_l = (bf16*)takeB(WSZ*2);
    float* bc  = (float*)takeB(1024*4);
    float* bpart = (float*)takeB(32*1024*4);
    auto WTh = [&](int i){ return WTp + (long long)i * 2 * WSZ; };
    auto WTl = [&](int i){ return WTp + (long long)i * 2 * WSZ + WSZ; };

    cudaFuncSetAttribute(gemm_bf3<1,true >, cudaFuncAttributeMaxDynamicSharedMemorySize, SMEMB);
    cudaFuncSetAttribute(gemm_bf3<1,false>, cudaFuncAttributeMaxDynamicSharedMemorySize, SMEMB);
    cudaFuncSetAttribute(gemm_bf3<2,false>, cudaFuncAttributeMaxDynamicSharedMemorySize, SMEMB);
    cudaFuncSetAttribute(gemm_bf3<5,true >, cudaFuncAttributeMaxDynamicSharedMemorySize, SMEMB);
    cudaFuncSetAttribute(gemm_nn,           cudaFuncAttributeMaxDynamicSharedMemorySize, SMEMB);
    cudaFuncSetAttribute(proj5_k,           cudaFuncAttributeMaxDynamicSharedMemorySize, SMEMB);

    const dim3 tb(32, 8);
    const dim3 gproj(8, 64, 1);
    const dim3 gproj5(8, 64, 5);
    const dim3 gS(16, 16, 4);
    const dim3 gO(8, 16, 4);
    const float it = 1.0f / 32.0f;
    const long long sLD = 2048ll*1024, sLL = 2048ll*2048;

    // ---------------- prep ----------------
    Split3 s3;
    s3.x[0] = q; s3.h[0] = q_h; s3.l[0] = q_l;
    s3.x[1] = k; s3.h[1] = k_h; s3.l[1] = k_l;
    s3.x[2] = v; s3.h[2] = v_h; s3.l[2] = v_l;
    split3_k<<<dim3(SZB/4/256, 3), 256>>>(s3);
    split1_k<<<WSZ/4/256, 256>>>(W[3], f1_h, f1_l);   // Wf1, original orientation
    W8 w8;
    for (int i = 0; i < 8; i++) { w8.w[i] = W[i]; w8.th[i] = WTh(i); w8.tl[i] = WTl(i); }
    tspw_k<<<dim3(32,32,8), tb>>>(w8);
    biasf1_k<<<dim3(4,32), 256>>>(W[4], bW[3], bpart);
    biasf2_k<<<4, 256>>>(bpart, bW[4], bc);           // bc = Wq2^T bf1 + bq2
    // WcT[n][j] = sum_k' Wq2^T[n][k'] * Wf1[j][k']   (bf16 split out)
    gemm_bf3<2,false><<<dim3(8,8,1),256,SMEMB>>>(WTh(4),WTl(4), f1_h,f1_l, 0,
        0, Wc_h, Wc_l, 0,0, 1024,1024,1024, 1.f, 0,0,0);

    Proj5 p5;
    p5.Ah[0]=q_h; p5.Al[0]=q_l; p5.Bh[0]=WTh(0); p5.Bl[0]=WTl(0); p5.bias[0]=bW[0]; p5.Cf[0]=q1b;
    p5.Ah[1]=k_h; p5.Al[1]=k_l; p5.Bh[1]=WTh(1); p5.Bl[1]=WTl(1); p5.bias[1]=bW[1]; p5.Cf[1]=kb;
    p5.Ah[2]=v_h; p5.Al[2]=v_l; p5.Bh[2]=WTh(2); p5.Bl[2]=WTl(2); p5.bias[2]=bW[2]; p5.Cf[2]=vb;
    p5.Ah[3]=k_h; p5.Al[3]=k_l; p5.Bh[3]=WTh(5); p5.Bl[3]=WTl(5); p5.bias[3]=bW[5]; p5.Cf[3]=k2b;
    p5.Ah[4]=v_h; p5.Al[4]=v_l; p5.Bh[4]=WTh(6); p5.Bl[4]=WTl(6); p5.bias[4]=bW[6]; p5.Cf[4]=v2b;
    p5.res = res;
    proj5_k<<<gproj5, 256, SMEMB>>>(p5);

    // ---------------- layer 1 ----------------
    LN3 l1;
    l1.x[0]=q1b; l1.g[0]=gq1; l1.b[0]=Bq1; l1.yh[0]=nq_h; l1.yl[0]=nq_l;
    l1.x[1]=kb;  l1.g[1]=gk1; l1.b[1]=Bk1; l1.yh[1]=nk_h; l1.yl[1]=nk_l;
    l1.x[2]=vb;  l1.g[2]=gv1; l1.b[2]=Bv1; l1.yh[2]=nv_h; l1.yl[2]=nv_l;
    ln3_k<<<dim3(1024,3), 256>>>(l1);

    gemm_bf3<1,false><<<gS,256,SMEMB>>>(nq_h,nq_l, nk_h,nk_l, 0, Sbuf,0,0, 0,0, 2048,2048,1024, it, sLD,sLD,sLL);
    softmax_k<false><<<1024,256>>>(Sbuf, P_h, P_l);
    gemm_nn<<<gO,256,SMEMB>>>(P_h,P_l, nv_h,nv_l, oa_h,oa_l, 2048,1024,2048, sLL,sLD,sLD);
    // fused: q2 = oa @ Wc + bc  (replaces oa->o1->q2)
    gemm_bf3<5,true ><<<gproj,256,SMEMB>>>(oa_h,oa_l, Wc_h,Wc_l, bc, q2b,0,0, res,1024, 8192,1024,1024, 1.f, 0,0,0);

    // ---------------- layer 2 ----------------
    LN3 l2;
    l2.x[0]=q2b; l2.g[0]=gq2; l2.b[0]=Bq2; l2.yh[0]=nq_h; l2.yl[0]=nq_l;
    l2.x[1]=k2b; l2.g[1]=gk2; l2.b[1]=Bk2; l2.yh[1]=nk_h; l2.yl[1]=nk_l;
    l2.x[2]=v2b; l2.g[2]=gv2; l2.b[2]=Bv2; l2.yh[2]=nv_h; l2.yl[2]=nv_l;
    ln3_k<<<dim3(1024,3), 256>>>(l2);

    gemm_bf3<1,false><<<gS,256,SMEMB>>>(nq_h,nq_l, nk_h,nk_l, 0, a2,0,0, 0,0, 2048,2048,1024, it, sLD,sLD,sLL);
    softmax_k<true><<<1024,256>>>(a2, P_h, P_l);
    gemm_nn<<<gO,256,SMEMB>>>(P_h,P_l, nv_h,nv_l, oa_h,oa_l, 2048,1024,2048, sLL,sLD,sLD);
    gemm_bf3<1,true ><<<gproj,256,SMEMB>>>(oa_h,oa_l, WTh(7),WTl(7), bW[7], out,0,0, 0,0, 8192,1024,1024, 1.f, 0,0,0);
}